// round 1
// baseline (speedup 1.0000x reference)
#include <cuda_runtime.h>
#include <cuda_bf16.h>
#include <math.h>

#define Nn   8192
#define Bb   8
#define Ll   1024
#define Hh   8
#define Cc   32
#define Dd   256
#define DFF  2048
#define Emax 262144
#define ETOTmax (Emax + Nn)

// ------------------------- scratch (static device globals) -------------------------
__device__ float    g_h   [Nn * Dd];
__device__ float    g_x   [Nn * Dd];
__device__ float    g_y   [Nn * Dd];
__device__ float    g_as  [Nn * Hh];
__device__ float    g_ad  [Nn * Hh];
__device__ unsigned g_menc[Nn * Hh];
__device__ float    g_ssum[Nn * Hh];
__device__ float    g_e   [ETOTmax * Hh];
__device__ float    g_qkv [Nn * 3 * Dd];
__device__ float    g_S   [(size_t)Bb * Hh * Ll * Ll];   // 268 MB
__device__ float    g_ff  [Nn * DFF];

// ------------------------- small helpers -------------------------
__device__ __forceinline__ unsigned fenc(float f) {
    unsigned u = __float_as_uint(f);
    return (u & 0x80000000u) ? ~u : (u | 0x80000000u);
}
__device__ __forceinline__ float fdec(unsigned e) {
    unsigned u = (e & 0x80000000u) ? (e & 0x7fffffffu) : ~e;
    return __uint_as_float(u);
}
__device__ __forceinline__ float warpSum(float v) {
    #pragma unroll
    for (int o = 16; o > 0; o >>= 1) v += __shfl_xor_sync(0xffffffffu, v, o);
    return v;
}
__device__ __forceinline__ float warpMax(float v) {
    #pragma unroll
    for (int o = 16; o > 0; o >>= 1) v = fmaxf(v, __shfl_xor_sync(0xffffffffu, v, o));
    return v;
}

__global__ void fillz(float* p, int n) {
    int i = blockIdx.x * 256 + threadIdx.x;
    if (i < n) p[i] = 0.0f;
}

// ------------------------- generic GEMM: C = A[M,K] * W[N,K]^T (+bias)(+relu) -------------------------
__global__ void gemm_wt(const float* __restrict__ A, const float* __restrict__ W,
                        const float* __restrict__ bias, float* __restrict__ C,
                        int M, int N, int K, int relu)
{
    __shared__ float As[16][68];
    __shared__ float Bs[16][68];
    int t  = threadIdx.x;          // 256 threads
    int tx = t & 15, ty = t >> 4;
    const float* Ab = A + (size_t)blockIdx.y * 64 * K;
    const float* Wb = W + (size_t)blockIdx.x * 64 * K;
    float acc[4][4] = {};
    for (int k0 = 0; k0 < K; k0 += 16) {
        #pragma unroll
        for (int r = 0; r < 4; r++) {
            int idx = t + r * 256;
            int row = idx >> 4, kk = idx & 15;
            As[kk][row] = Ab[(size_t)row * K + k0 + kk];
            Bs[kk][row] = Wb[(size_t)row * K + k0 + kk];
        }
        __syncthreads();
        #pragma unroll
        for (int kk = 0; kk < 16; kk++) {
            float4 a4 = *(const float4*)&As[kk][ty * 4];
            float4 b4 = *(const float4*)&Bs[kk][tx * 4];
            float av[4] = {a4.x, a4.y, a4.z, a4.w};
            float bv[4] = {b4.x, b4.y, b4.z, b4.w};
            #pragma unroll
            for (int i = 0; i < 4; i++)
                #pragma unroll
                for (int j = 0; j < 4; j++)
                    acc[i][j] += av[i] * bv[j];
        }
        __syncthreads();
    }
    int row0 = blockIdx.y * 64 + ty * 4;
    int col0 = blockIdx.x * 64 + tx * 4;
    #pragma unroll
    for (int i = 0; i < 4; i++) {
        #pragma unroll
        for (int j = 0; j < 4; j++) {
            float v = acc[i][j];
            if (bias) v += bias[col0 + j];
            if (relu) v = fmaxf(v, 0.0f);
            C[(size_t)(row0 + i) * N + col0 + j] = v;
        }
    }
}

// ------------------------- GAT: attention logits prep -------------------------
__global__ void att_prep(const float* __restrict__ hbuf,
                         const float* __restrict__ atts, const float* __restrict__ attd)
{
    int t = blockIdx.x * 256 + threadIdx.x;
    if (t >= Nn * Hh) return;
    int n = t >> 3, hd = t & 7;
    const float* hp = hbuf + (size_t)n * Dd + hd * Cc;
    const float* pa = atts + hd * Cc;
    const float* pb = attd + hd * Cc;
    float s1 = 0.0f, s2 = 0.0f;
    #pragma unroll
    for (int c = 0; c < Cc; c++) {
        float hv = hp[c];
        s1 += hv * pa[c];
        s2 += hv * pb[c];
    }
    g_as[t] = s1;
    g_ad[t] = s2;
}

// ------------------------- GAT: edge passes -------------------------
__global__ void edge_pass1(const int* __restrict__ ei, int E, int Etot)
{
    int t = blockIdx.x * 256 + threadIdx.x;
    if (t >= Etot * Hh) return;
    int e = t >> 3, hd = t & 7;
    int s, d;
    if (e < E) { s = ei[e]; d = ei[E + e]; } else { s = d = e - E; }
    float v = g_as[s * Hh + hd] + g_ad[d * Hh + hd];
    v = v > 0.0f ? v : 0.2f * v;
    g_e[t] = v;
    atomicMax(&g_menc[d * Hh + hd], fenc(v));
}

__global__ void edge_pass2(const int* __restrict__ ei, int E, int Etot)
{
    int t = blockIdx.x * 256 + threadIdx.x;
    if (t >= Etot * Hh) return;
    int e = t >> 3, hd = t & 7;
    int d;
    if (e < E) { d = ei[E + e]; } else { d = e - E; }
    float m = fdec(g_menc[d * Hh + hd]);
    float p = __expf(g_e[t] - m);
    g_e[t] = p;
    atomicAdd(&g_ssum[d * Hh + hd], p);
}

__global__ void edge_pass3(const int* __restrict__ ei, int E, int Etot,
                           const float* __restrict__ hbuf, float* __restrict__ obuf)
{
    int gt = blockIdx.x * 256 + threadIdx.x;
    int e = gt >> 5, lane = gt & 31;
    if (e >= Etot) return;
    int s, d;
    if (e < E) { s = ei[e]; d = ei[E + e]; } else { s = d = e - E; }
    #pragma unroll
    for (int k = 0; k < Hh; k++) {
        float alpha = g_e[e * Hh + k] / g_ssum[d * Hh + k];
        float hv = hbuf[(size_t)s * Dd + k * Cc + lane];
        atomicAdd(&obuf[(size_t)d * Dd + k * Cc + lane], hv * alpha);
    }
}

__global__ void bias_relu(float* __restrict__ buf, const float* __restrict__ bias)
{
    int t = blockIdx.x * 256 + threadIdx.x;
    if (t >= Nn * Dd) return;
    float v = buf[t] + bias[t & (Dd - 1)];
    buf[t] = fmaxf(v, 0.0f);
}

// ------------------------- attention: S = Q K^T (per b,h) -------------------------
__global__ void attn_scores(const float* __restrict__ qkv, float* __restrict__ S)
{
    __shared__ float Qs[32][68];
    __shared__ float Ks[32][68];
    int z = blockIdx.z;                 // b*8 + h
    int b = z >> 3, h = z & 7;
    int q0 = blockIdx.y * 64, k0 = blockIdx.x * 64;
    int t = threadIdx.x;
    int tx = t & 15, ty = t >> 4;
    const float* Qb = qkv + (size_t)b * Ll * 768 + h * 32;
    const float* Kb = Qb + 256;
    #pragma unroll
    for (int r = 0; r < 8; r++) {
        int idx = t + r * 256;
        int row = idx >> 5, kk = idx & 31;
        Qs[kk][row] = Qb[(size_t)(q0 + row) * 768 + kk];
        Ks[kk][row] = Kb[(size_t)(k0 + row) * 768 + kk];
    }
    __syncthreads();
    float acc[4][4] = {};
    #pragma unroll
    for (int kk = 0; kk < 32; kk++) {
        float4 a4 = *(const float4*)&Qs[kk][ty * 4];
        float4 b4 = *(const float4*)&Ks[kk][tx * 4];
        float av[4] = {a4.x, a4.y, a4.z, a4.w};
        float bv[4] = {b4.x, b4.y, b4.z, b4.w};
        #pragma unroll
        for (int i = 0; i < 4; i++)
            #pragma unroll
            for (int j = 0; j < 4; j++)
                acc[i][j] += av[i] * bv[j];
    }
    float* Sp = S + (size_t)z * Ll * Ll;
    #pragma unroll
    for (int i = 0; i < 4; i++)
        #pragma unroll
        for (int j = 0; j < 4; j++)
            Sp[(size_t)(q0 + ty * 4 + i) * Ll + k0 + tx * 4 + j] = acc[i][j];
}

// ------------------------- softmax over rows of S (width 1024), scale folded -------------------------
__global__ void softmax_rows(float* __restrict__ S, float scale)
{
    __shared__ float red[8];
    size_t base = (size_t)blockIdx.x * Ll;
    int t = threadIdx.x;
    float v[4];
    float mx = -1e30f;
    #pragma unroll
    for (int j = 0; j < 4; j++) {
        v[j] = S[base + t + j * 256] * scale;
        mx = fmaxf(mx, v[j]);
    }
    mx = warpMax(mx);
    if ((t & 31) == 0) red[t >> 5] = mx;
    __syncthreads();
    float m2 = red[0];
    #pragma unroll
    for (int i = 1; i < 8; i++) m2 = fmaxf(m2, red[i]);
    __syncthreads();
    float sum = 0.0f;
    #pragma unroll
    for (int j = 0; j < 4; j++) {
        v[j] = __expf(v[j] - m2);
        sum += v[j];
    }
    sum = warpSum(sum);
    if ((t & 31) == 0) red[t >> 5] = sum;
    __syncthreads();
    float tot = 0.0f;
    #pragma unroll
    for (int i = 0; i < 8; i++) tot += red[i];
    float inv = 1.0f / tot;
    #pragma unroll
    for (int j = 0; j < 4; j++) S[base + t + j * 256] = v[j] * inv;
}

// ------------------------- attention: O = P V (per b,h) -------------------------
__global__ void attn_av(const float* __restrict__ S, const float* __restrict__ qkv,
                        float* __restrict__ O)
{
    __shared__ float Ps[32][68];
    __shared__ float Vs[32][36];
    int z = blockIdx.y;
    int b = z >> 3, h = z & 7;
    int q0 = blockIdx.x * 64;
    int t = threadIdx.x;
    int tx = t & 15, ty = t >> 4;
    const float* Sp = S + (size_t)z * Ll * Ll;
    const float* Vb = qkv + (size_t)b * Ll * 768 + 512 + h * 32;
    float acc[4][2] = {};
    for (int kc = 0; kc < 32; kc++) {
        #pragma unroll
        for (int r = 0; r < 8; r++) {
            int idx = t + r * 256;
            int row = idx >> 5, kk = idx & 31;
            Ps[kk][row] = Sp[(size_t)(q0 + row) * Ll + kc * 32 + kk];
        }
        #pragma unroll
        for (int r = 0; r < 4; r++) {
            int idx = t + r * 256;
            int key = idx >> 5, dd = idx & 31;
            Vs[key][dd] = Vb[(size_t)(kc * 32 + key) * 768 + dd];
        }
        __syncthreads();
        #pragma unroll
        for (int kk = 0; kk < 32; kk++) {
            float4 a4 = *(const float4*)&Ps[kk][ty * 4];
            float2 b2 = *(const float2*)&Vs[kk][tx * 2];
            float av[4] = {a4.x, a4.y, a4.z, a4.w};
            #pragma unroll
            for (int i = 0; i < 4; i++) {
                acc[i][0] += av[i] * b2.x;
                acc[i][1] += av[i] * b2.y;
            }
        }
        __syncthreads();
    }
    #pragma unroll
    for (int i = 0; i < 4; i++) {
        #pragma unroll
        for (int j = 0; j < 2; j++) {
            O[(size_t)(b * Ll + q0 + ty * 4 + i) * Dd + h * 32 + tx * 2 + j] = acc[i][j];
        }
    }
}

// ------------------------- residual + layernorm (row width 256), warp per row -------------------------
__global__ void ln_res(const float* __restrict__ xin, const float* __restrict__ add,
                       float* __restrict__ xout, const float* __restrict__ w,
                       const float* __restrict__ b)
{
    int row = blockIdx.x * 8 + (threadIdx.x >> 5);
    int lane = threadIdx.x & 31;
    const float* xr = xin + (size_t)row * Dd;
    const float* ar = add + (size_t)row * Dd;
    float v[8];
    float s = 0.0f;
    #pragma unroll
    for (int j = 0; j < 8; j++) {
        int d = lane + j * 32;
        v[j] = xr[d] + ar[d];
        s += v[j];
    }
    s = warpSum(s);
    float mean = s * (1.0f / 256.0f);
    float var = 0.0f;
    #pragma unroll
    for (int j = 0; j < 8; j++) {
        float dv = v[j] - mean;
        var += dv * dv;
    }
    var = warpSum(var) * (1.0f / 256.0f);
    float inv = rsqrtf(var + 1e-5f);
    float* orow = xout + (size_t)row * Dd;
    #pragma unroll
    for (int j = 0; j < 8; j++) {
        int d = lane + j * 32;
        orow[d] = (v[j] - mean) * inv * w[d] + b[d];
    }
}

// ------------------------- prediction head: out = x @ pred_w^T + pred_b -------------------------
__global__ void pred_kernel(const float* __restrict__ xin, const float* __restrict__ pw,
                            const float* __restrict__ pb, float* __restrict__ out)
{
    int gw = (blockIdx.x * 256 + threadIdx.x) >> 5;
    int lane = threadIdx.x & 31;
    if (gw >= Nn) return;
    const float* xr = xin + (size_t)gw * Dd;
    float a0 = 0.0f, a1 = 0.0f, a2 = 0.0f;
    #pragma unroll
    for (int j = 0; j < 8; j++) {
        int d = lane + j * 32;
        float xv = xr[d];
        a0 += xv * pw[d];
        a1 += xv * pw[Dd + d];
        a2 += xv * pw[2 * Dd + d];
    }
    a0 = warpSum(a0);
    a1 = warpSum(a1);
    a2 = warpSum(a2);
    if (lane == 0) {
        out[gw * 3 + 0] = a0 + pb[0];
        out[gw * 3 + 1] = a1 + pb[1];
        out[gw * 3 + 2] = a2 + pb[2];
    }
}

// ------------------------- host orchestration -------------------------
extern "C" void kernel_launch(void* const* d_in, const int* in_sizes, int n_in,
                              void* d_out, int out_size)
{
    const float* x      = (const float*)d_in[0];
    const int*   ei     = (const int*)d_in[1];
    const float* W0     = (const float*)d_in[3];
    const float* W12    = (const float*)d_in[4];
    const float* att_s  = (const float*)d_in[5];
    const float* att_d  = (const float*)d_in[6];
    const float* gbias  = (const float*)d_in[7];
    const float* qkv_w  = (const float*)d_in[8];
    const float* qkv_b  = (const float*)d_in[9];
    const float* out_w  = (const float*)d_in[10];
    const float* out_b  = (const float*)d_in[11];
    const float* ln1w   = (const float*)d_in[12];
    const float* ln1b   = (const float*)d_in[13];
    const float* ln2w   = (const float*)d_in[14];
    const float* ln2b   = (const float*)d_in[15];
    const float* ff1w   = (const float*)d_in[16];
    const float* ff1b   = (const float*)d_in[17];
    const float* ff2w   = (const float*)d_in[18];
    const float* ff2b   = (const float*)d_in[19];
    const float* predw  = (const float*)d_in[20];
    const float* predb  = (const float*)d_in[21];
    float* out = (float*)d_out;

    int E = in_sizes[1] / 2;
    int Etot = E + Nn;

    float *ph, *px, *py, *pssum, *pqkv, *pS, *pff;
    unsigned* pm;
    cudaGetSymbolAddress((void**)&ph,    g_h);
    cudaGetSymbolAddress((void**)&px,    g_x);
    cudaGetSymbolAddress((void**)&py,    g_y);
    cudaGetSymbolAddress((void**)&pm,    g_menc);
    cudaGetSymbolAddress((void**)&pssum, g_ssum);
    cudaGetSymbolAddress((void**)&pqkv,  g_qkv);
    cudaGetSymbolAddress((void**)&pS,    g_S);
    cudaGetSymbolAddress((void**)&pff,   g_ff);

    // ---------------- GAT layers ----------------
    const float* cur = x;
    int curK = 64;
    float* aggr_targets[3] = {px, py, px};
    for (int l = 0; l < 3; l++) {
        const float* W = (l == 0) ? W0 : (W12 + (size_t)(l - 1) * Dd * Dd);
        float* aggr = aggr_targets[l];
        gemm_wt<<<dim3(Dd / 64, Nn / 64), 256>>>(cur, W, nullptr, ph, Nn, Dd, curK, 0);
        att_prep<<<(Nn * Hh + 255) / 256, 256>>>(ph, att_s + l * Dd, att_d + l * Dd);
        fillz<<<(Nn * Hh + 255) / 256, 256>>>((float*)pm, Nn * Hh);
        fillz<<<(Nn * Hh + 255) / 256, 256>>>(pssum, Nn * Hh);
        fillz<<<(Nn * Dd + 255) / 256, 256>>>(aggr, Nn * Dd);
        edge_pass1<<<(Etot * Hh + 255) / 256, 256>>>(ei, E, Etot);
        edge_pass2<<<(Etot * Hh + 255) / 256, 256>>>(ei, E, Etot);
        edge_pass3<<<(Etot * 32 + 255) / 256, 256>>>(ei, E, Etot, ph, aggr);
        bias_relu<<<(Nn * Dd + 255) / 256, 256>>>(aggr, gbias + l * Dd);
        cur = aggr;
        curK = Dd;
    }
    // features now in g_x

    // ---------------- transformer layers ----------------
    const float scale = 0.17677669529663687f;  // 1/sqrt(32)
    for (int i = 0; i < 2; i++) {
        gemm_wt<<<dim3(768 / 64, Nn / 64), 256>>>(px, qkv_w + (size_t)i * 768 * Dd,
                                                  qkv_b + i * 768, pqkv, Nn, 768, Dd, 0);
        attn_scores<<<dim3(Ll / 64, Ll / 64, Bb * Hh), 256>>>(pqkv, pS);
        softmax_rows<<<Bb * Hh * Ll, 256>>>(pS, scale);
        attn_av<<<dim3(Ll / 64, Bb * Hh), 256>>>(pS, pqkv, py);
        gemm_wt<<<dim3(Dd / 64, Nn / 64), 256>>>(py, out_w + (size_t)i * Dd * Dd,
                                                 out_b + i * Dd, ph, Nn, Dd, Dd, 0);
        ln_res<<<Nn / 8, 256>>>(px, ph, px, ln1w + i * Dd, ln1b + i * Dd);
        gemm_wt<<<dim3(DFF / 64, Nn / 64), 256>>>(px, ff1w + (size_t)i * DFF * Dd,
                                                  ff1b + i * DFF, pff, Nn, DFF, Dd, 1);
        gemm_wt<<<dim3(Dd / 64, Nn / 64), 256>>>(pff, ff2w + (size_t)i * Dd * DFF,
                                                 ff2b + i * Dd, ph, Nn, Dd, DFF, 0);
        ln_res<<<Nn / 8, 256>>>(px, ph, px, ln2w + i * Dd, ln2b + i * Dd);
    }

    // ---------------- prediction head ----------------
    pred_kernel<<<(Nn * 32 + 255) / 256, 256>>>(px, predw, predb, out);
}

// round 3
// speedup vs baseline: 1.7706x; 1.7706x over previous
#include <cuda_runtime.h>
#include <cuda_bf16.h>
#include <math.h>
#include <stdint.h>

using bf16 = __nv_bfloat16;

#define Nn   8192
#define Bb   8
#define Ll   1024
#define Hh   8
#define Cc   32
#define Dd   256
#define DFF  2048
#define Emax 262144
#define ETOTmax (Emax + Nn)
#define SSZ  (8ULL * 8 * 1024 * 1024)

// ------------------------- scratch (static device globals) -------------------------
__device__ float    g_h   [Nn * Dd];
__device__ float    g_x   [Nn * Dd];
__device__ float    g_y   [Nn * Dd];
__device__ float    g_as  [Nn * Hh];
__device__ float    g_ad  [Nn * Hh];
__device__ unsigned g_menc[Nn * Hh];
__device__ float    g_ssum[Nn * Hh];
__device__ float    g_e   [ETOTmax * Hh];
__device__ float    g_qkv [Nn * 3 * Dd];
__device__ float    g_S   [SSZ];              // fp32 scores, 268 MB
__device__ float    g_ff  [Nn * DFF];

__device__ bf16 g_ah[Nn * DFF];               // A hi (max 8192x2048)
__device__ bf16 g_al[Nn * DFF];               // A lo
__device__ bf16 g_wh[DFF * Dd];               // W hi (max 2048x256)
__device__ bf16 g_wl[DFF * Dd];
__device__ bf16 g_qh[Nn * 3 * Dd];            // qkv hi
__device__ bf16 g_ql[Nn * 3 * Dd];
__device__ bf16 g_sh[SSZ];                    // softmax probs hi
__device__ bf16 g_sl[SSZ];                    // softmax probs lo
__device__ bf16 g_vth[64 * 32 * 1024];        // V transposed hi: [z][d][k]
__device__ bf16 g_vtl[64 * 32 * 1024];

// ------------------------- helpers -------------------------
__device__ __forceinline__ uint32_t smem_u32(const void* p) {
    uint32_t a;
    asm("{ .reg .u64 t; cvta.to.shared.u64 t, %1; cvt.u32.u64 %0, t; }" : "=r"(a) : "l"(p));
    return a;
}
__device__ __forceinline__ void cp16(uint32_t s, const void* g) {
    asm volatile("cp.async.cg.shared.global [%0], [%1], 16;" :: "r"(s), "l"(g));
}
__device__ __forceinline__ void cp_commit() {
    asm volatile("cp.async.commit_group;" ::: "memory");
}
__device__ __forceinline__ void cp_wait0() {
    asm volatile("cp.async.wait_group 0;" ::: "memory");
}
__device__ __forceinline__ void cp_wait1() {
    asm volatile("cp.async.wait_group 1;" ::: "memory");
}
__device__ __forceinline__ void ldm4(uint32_t* r, uint32_t addr) {
    asm volatile("ldmatrix.sync.aligned.m8n8.x4.shared.b16 {%0,%1,%2,%3}, [%4];"
        : "=r"(r[0]), "=r"(r[1]), "=r"(r[2]), "=r"(r[3]) : "r"(addr));
}
__device__ __forceinline__ void mma16816(float* d, const uint32_t* a, const uint32_t* b) {
    asm volatile(
        "mma.sync.aligned.m16n8k16.row.col.f32.bf16.bf16.f32 "
        "{%0,%1,%2,%3}, {%4,%5,%6,%7}, {%8,%9}, {%0,%1,%2,%3};"
        : "+f"(d[0]), "+f"(d[1]), "+f"(d[2]), "+f"(d[3])
        : "r"(a[0]), "r"(a[1]), "r"(a[2]), "r"(a[3]), "r"(b[0]), "r"(b[1]));
}
__device__ __forceinline__ float warpSum(float v) {
    #pragma unroll
    for (int o = 16; o > 0; o >>= 1) v += __shfl_xor_sync(0xffffffffu, v, o);
    return v;
}
__device__ __forceinline__ float warpMax(float v) {
    #pragma unroll
    for (int o = 16; o > 0; o >>= 1) v = fmaxf(v, __shfl_xor_sync(0xffffffffu, v, o));
    return v;
}
__device__ __forceinline__ unsigned fenc(float f) {
    unsigned u = __float_as_uint(f);
    return (u & 0x80000000u) ? ~u : (u | 0x80000000u);
}
__device__ __forceinline__ float fdec(unsigned e) {
    unsigned u = (e & 0x80000000u) ? (e & 0x7fffffffu) : ~e;
    return __uint_as_float(u);
}

// ------------------------- fp32 -> bf16 hi/lo conversion -------------------------
__global__ void cvt_hilo(const float* __restrict__ in, bf16* __restrict__ hi,
                         bf16* __restrict__ lo, int n4)
{
    int i = blockIdx.x * 256 + threadIdx.x;
    if (i >= n4) return;
    float4 x = ((const float4*)in)[i];
    float xs[4] = {x.x, x.y, x.z, x.w};
    bf16 h[4], l[4];
    #pragma unroll
    for (int j = 0; j < 4; j++) {
        h[j] = __float2bfloat16(xs[j]);
        l[j] = __float2bfloat16(xs[j] - __bfloat162float(h[j]));
    }
    ((__nv_bfloat162*)hi)[2 * i]     = __nv_bfloat162(h[0], h[1]);
    ((__nv_bfloat162*)hi)[2 * i + 1] = __nv_bfloat162(h[2], h[3]);
    ((__nv_bfloat162*)lo)[2 * i]     = __nv_bfloat162(l[0], l[1]);
    ((__nv_bfloat162*)lo)[2 * i + 1] = __nv_bfloat162(l[2], l[3]);
}

// fused V transpose + hi/lo:  vt[z][d][k] = qkv[b*1024+k][512 + h*32 + d]
__global__ void cvt_vt(const float* __restrict__ qkv, bf16* __restrict__ vth,
                       bf16* __restrict__ vtl)
{
    int i = blockIdx.x * 256 + threadIdx.x;           // 64*32*1024 = 2M
    int k = i & 1023, d = (i >> 10) & 31, z = i >> 15;
    int b = z >> 3, h = z & 7;
    float v = qkv[(size_t)(b * 1024 + k) * 768 + 512 + h * 32 + d];
    bf16 hh = __float2bfloat16(v);
    vth[i] = hh;
    vtl[i] = __float2bfloat16(v - __bfloat162float(hh));
}

// ------------------------- HMMA split-bf16 GEMM -------------------------
// MODE 0: C[M,N] = A[M,K] @ W[N,K]^T (+bias)(+relu). grid (N/NT, M/128)
// MODE 1: S[z] = Q·K^T per (b,h), A/B strided in qkv. grid (8, 8, 64), K=32
// MODE 2: O[z] = P·V^T, B = pre-transposed V [32,1024]. grid (1, 8, 64)
template<int MODE, int NT, int WARPS_M, int WARPS_N>
__global__ void __launch_bounds__(256, 1)
hgemm(const bf16* __restrict__ aH, const bf16* __restrict__ aL, int lda,
      const bf16* __restrict__ bH, const bf16* __restrict__ bL, int ldb,
      const float* __restrict__ bias, float* __restrict__ C, int ldc,
      int K, int relu)
{
    constexpr int WM  = 128 / WARPS_M;   // warp tile M
    constexpr int WN  = NT / WARPS_N;    // warp tile N
    constexpr int MT  = WM / 16;
    constexpr int NT8 = WN / 8;
    constexpr int SST = 40;              // smem row stride (bf16 elems) = 80B
    constexpr int ATILE = 128 * SST;     // elems
    constexpr int BTILE = NT * SST;
    constexpr int STAGE = 2 * ATILE + 2 * BTILE;

    extern __shared__ bf16 sm[];

    int tid = threadIdx.x;
    int wid = tid >> 5, lane = tid & 31;
    int wm = wid % WARPS_M, wn = wid / WARPS_M;
    int m0 = blockIdx.y * 128;
    int n0 = (MODE == 2) ? 0 : blockIdx.x * NT;

    if (MODE == 1) {
        int z = blockIdx.z, b = z >> 3, h = z & 7;
        size_t qb = (size_t)b * Ll * 768 + h * 32;
        aH += qb; aL += qb; bH += qb + 256; bL += qb + 256;
        C += (size_t)z * Ll * Ll;
    } else if (MODE == 2) {
        int z = blockIdx.z, b = z >> 3, h = z & 7;
        aH += (size_t)z * Ll * Ll;
        aL += (size_t)z * Ll * Ll;
        bH += (size_t)z * 32 * 1024;
        bL += (size_t)z * 32 * 1024;
        C += (size_t)b * Ll * Dd + h * 32;
    }

    float acc[MT][NT8][4] = {};
    int P = K >> 5;

    auto load_panel = [&](int p, int s) {
        bf16* Ah = sm + s * STAGE;
        bf16* Al = Ah + ATILE;
        bf16* Bh = Al + ATILE;
        bf16* Bl = Bh + BTILE;
        int k0 = p * 32;
        #pragma unroll 2
        for (int idx = tid; idx < 128 * 4; idx += 256) {
            int r = idx >> 2, c = idx & 3;
            size_t g = (size_t)(m0 + r) * lda + k0 + c * 8;
            cp16(smem_u32(Ah + r * SST + c * 8), aH + g);
            cp16(smem_u32(Al + r * SST + c * 8), aL + g);
        }
        #pragma unroll 2
        for (int idx = tid; idx < NT * 4; idx += 256) {
            int r = idx >> 2, c = idx & 3;
            size_t g = (size_t)(n0 + r) * ldb + k0 + c * 8;
            cp16(smem_u32(Bh + r * SST + c * 8), bH + g);
            cp16(smem_u32(Bl + r * SST + c * 8), bL + g);
        }
        cp_commit();
    };

    // per-lane ldmatrix source coordinates
    int t8 = lane >> 3;
    int rA = (t8 & 1) * 8 + (lane & 7), cA = (t8 >> 1) * 8;
    int rB = (t8 >> 1) * 8 + (lane & 7), cB = (t8 & 1) * 8;

    auto compute = [&](int s) {
        bf16* Ah = sm + s * STAGE;
        bf16* Al = Ah + ATILE;
        bf16* Bh = Al + ATILE;
        bf16* Bl = Bh + BTILE;
        #pragma unroll
        for (int kk = 0; kk < 2; kk++) {
            int k16 = kk * 16;
            uint32_t ah[MT][4], al[MT][4], bh[NT8][2], bl[NT8][2];
            #pragma unroll
            for (int mt = 0; mt < MT; mt++) {
                int row = wm * WM + mt * 16 + rA;
                int col = k16 + cA;
                ldm4(ah[mt], smem_u32(Ah + row * SST + col));
                ldm4(al[mt], smem_u32(Al + row * SST + col));
            }
            #pragma unroll
            for (int nt2 = 0; nt2 < NT8 / 2; nt2++) {
                int row = wn * WN + nt2 * 16 + rB;
                int col = k16 + cB;
                uint32_t r4[4];
                ldm4(r4, smem_u32(Bh + row * SST + col));
                bh[2 * nt2][0] = r4[0]; bh[2 * nt2][1] = r4[1];
                bh[2 * nt2 + 1][0] = r4[2]; bh[2 * nt2 + 1][1] = r4[3];
                ldm4(r4, smem_u32(Bl + row * SST + col));
                bl[2 * nt2][0] = r4[0]; bl[2 * nt2][1] = r4[1];
                bl[2 * nt2 + 1][0] = r4[2]; bl[2 * nt2 + 1][1] = r4[3];
            }
            #pragma unroll
            for (int mt = 0; mt < MT; mt++) {
                #pragma unroll
                for (int nt = 0; nt < NT8; nt++) {
                    mma16816(acc[mt][nt], ah[mt], bh[nt]);
                    mma16816(acc[mt][nt], ah[mt], bl[nt]);
                    mma16816(acc[mt][nt], al[mt], bh[nt]);
                }
            }
        }
    };

    load_panel(0, 0);
    for (int p = 0; p < P; p++) {
        if (p + 1 < P) {
            load_panel(p + 1, (p + 1) & 1);
            cp_wait1();
        } else {
            cp_wait0();
        }
        __syncthreads();
        compute(p & 1);
        __syncthreads();
    }

    // epilogue
    int grp = lane >> 2, q4 = lane & 3;
    #pragma unroll
    for (int mt = 0; mt < MT; mt++) {
        #pragma unroll
        for (int nt = 0; nt < NT8; nt++) {
            int row = m0 + wm * WM + mt * 16 + grp;
            int col = n0 + wn * WN + nt * 8 + q4 * 2;
            float* a4 = acc[mt][nt];
            float b0 = 0.0f, b1 = 0.0f;
            if (bias) { b0 = bias[col]; b1 = bias[col + 1]; }
            float v0 = a4[0] + b0, v1 = a4[1] + b1;
            float v2 = a4[2] + b0, v3 = a4[3] + b1;
            if (relu) {
                v0 = fmaxf(v0, 0.0f); v1 = fmaxf(v1, 0.0f);
                v2 = fmaxf(v2, 0.0f); v3 = fmaxf(v3, 0.0f);
            }
            *(float2*)&C[(size_t)row * ldc + col]       = make_float2(v0, v1);
            *(float2*)&C[(size_t)(row + 8) * ldc + col] = make_float2(v2, v3);
        }
    }
}

// ------------------------- GAT pieces -------------------------
__global__ void fillz(float* p, int n) {
    int i = blockIdx.x * 256 + threadIdx.x;
    if (i < n) p[i] = 0.0f;
}

__global__ void att_prep(const float* __restrict__ hbuf,
                         const float* __restrict__ atts, const float* __restrict__ attd)
{
    int t = blockIdx.x * 256 + threadIdx.x;
    if (t >= Nn * Hh) return;
    int n = t >> 3, hd = t & 7;
    const float* hp = hbuf + (size_t)n * Dd + hd * Cc;
    const float* pa = atts + hd * Cc;
    const float* pb = attd + hd * Cc;
    float s1 = 0.0f, s2 = 0.0f;
    #pragma unroll
    for (int c = 0; c < Cc; c++) {
        float hv = hp[c];
        s1 += hv * pa[c];
        s2 += hv * pb[c];
    }
    g_as[t] = s1;
    g_ad[t] = s2;
}

__global__ void edge_pass1(const int* __restrict__ ei, int E, int Etot)
{
    int t = blockIdx.x * 256 + threadIdx.x;
    if (t >= Etot * Hh) return;
    int e = t >> 3, hd = t & 7;
    int s, d;
    if (e < E) { s = ei[e]; d = ei[E + e]; } else { s = d = e - E; }
    float v = g_as[s * Hh + hd] + g_ad[d * Hh + hd];
    v = v > 0.0f ? v : 0.2f * v;
    g_e[t] = v;
    atomicMax(&g_menc[d * Hh + hd], fenc(v));
}

__global__ void edge_pass2(const int* __restrict__ ei, int E, int Etot)
{
    int t = blockIdx.x * 256 + threadIdx.x;
    if (t >= Etot * Hh) return;
    int e = t >> 3, hd = t & 7;
    int d;
    if (e < E) { d = ei[E + e]; } else { d = e - E; }
    float m = fdec(g_menc[d * Hh + hd]);
    float p = __expf(g_e[t] - m);
    g_e[t] = p;
    atomicAdd(&g_ssum[d * Hh + hd], p);
}

__global__ void edge_pass3(const int* __restrict__ ei, int E, int Etot,
                           const float* __restrict__ hbuf, float* __restrict__ obuf)
{
    int gt = blockIdx.x * 256 + threadIdx.x;
    int e = gt >> 5, lane = gt & 31;
    if (e >= Etot) return;
    int s, d;
    if (e < E) { s = ei[e]; d = ei[E + e]; } else { s = d = e - E; }
    #pragma unroll
    for (int k = 0; k < Hh; k++) {
        float alpha = g_e[e * Hh + k] / g_ssum[d * Hh + k];
        float hv = hbuf[(size_t)s * Dd + k * Cc + lane];
        atomicAdd(&obuf[(size_t)d * Dd + k * Cc + lane], hv * alpha);
    }
}

__global__ void bias_relu(float* __restrict__ buf, const float* __restrict__ bias)
{
    int t = blockIdx.x * 256 + threadIdx.x;
    if (t >= Nn * Dd) return;
    float v = buf[t] + bias[t & (Dd - 1)];
    buf[t] = fmaxf(v, 0.0f);
}

// ------------------------- softmax (writes bf16 hi/lo) -------------------------
__global__ void softmax_rows(const float* __restrict__ S, bf16* __restrict__ sh,
                             bf16* __restrict__ sl, float scale)
{
    __shared__ float red[8];
    size_t base = (size_t)blockIdx.x * Ll;
    int t = threadIdx.x;
    float v[4];
    float mx = -1e30f;
    #pragma unroll
    for (int j = 0; j < 4; j++) {
        v[j] = S[base + t + j * 256] * scale;
        mx = fmaxf(mx, v[j]);
    }
    mx = warpMax(mx);
    if ((t & 31) == 0) red[t >> 5] = mx;
    __syncthreads();
    float m2 = red[0];
    #pragma unroll
    for (int i = 1; i < 8; i++) m2 = fmaxf(m2, red[i]);
    __syncthreads();
    float sum = 0.0f;
    #pragma unroll
    for (int j = 0; j < 4; j++) {
        v[j] = __expf(v[j] - m2);
        sum += v[j];
    }
    sum = warpSum(sum);
    if ((t & 31) == 0) red[t >> 5] = sum;
    __syncthreads();
    float tot = 0.0f;
    #pragma unroll
    for (int i = 0; i < 8; i++) tot += red[i];
    float inv = 1.0f / tot;
    #pragma unroll
    for (int j = 0; j < 4; j++) {
        float pv = v[j] * inv;
        bf16 h = __float2bfloat16(pv);
        sh[base + t + j * 256] = h;
        sl[base + t + j * 256] = __float2bfloat16(pv - __bfloat162float(h));
    }
}

// ------------------------- residual + layernorm -------------------------
__global__ void ln_res(const float* __restrict__ xin, const float* __restrict__ add,
                       float* __restrict__ xout, const float* __restrict__ w,
                       const float* __restrict__ b)
{
    int row = blockIdx.x * 8 + (threadIdx.x >> 5);
    int lane = threadIdx.x & 31;
    const float* xr = xin + (size_t)row * Dd;
    const float* ar = add + (size_t)row * Dd;
    float v[8];
    float s = 0.0f;
    #pragma unroll
    for (int j = 0; j < 8; j++) {
        int d = lane + j * 32;
        v[j] = xr[d] + ar[d];
        s += v[j];
    }
    s = warpSum(s);
    float mean = s * (1.0f / 256.0f);
    float var = 0.0f;
    #pragma unroll
    for (int j = 0; j < 8; j++) {
        float dv = v[j] - mean;
        var += dv * dv;
    }
    var = warpSum(var) * (1.0f / 256.0f);
    float inv = rsqrtf(var + 1e-5f);
    float* orow = xout + (size_t)row * Dd;
    #pragma unroll
    for (int j = 0; j < 8; j++) {
        int d = lane + j * 32;
        orow[d] = (v[j] - mean) * inv * w[d] + b[d];
    }
}

// ------------------------- prediction head -------------------------
__global__ void pred_kernel(const float* __restrict__ xin, const float* __restrict__ pw,
                            const float* __restrict__ pb, float* __restrict__ out)
{
    int gw = (blockIdx.x * 256 + threadIdx.x) >> 5;
    int lane = threadIdx.x & 31;
    if (gw >= Nn) return;
    const float* xr = xin + (size_t)gw * Dd;
    float a0 = 0.0f, a1 = 0.0f, a2 = 0.0f;
    #pragma unroll
    for (int j = 0; j < 8; j++) {
        int d = lane + j * 32;
        float xv = xr[d];
        a0 += xv * pw[d];
        a1 += xv * pw[Dd + d];
        a2 += xv * pw[2 * Dd + d];
    }
    a0 = warpSum(a0);
    a1 = warpSum(a1);
    a2 = warpSum(a2);
    if (lane == 0) {
        out[gw * 3 + 0] = a0 + pb[0];
        out[gw * 3 + 1] = a1 + pb[1];
        out[gw * 3 + 2] = a2 + pb[2];
    }
}

// ------------------------- host orchestration -------------------------
#define SMEM0 (2 * (2 * 128 * 40 + 2 * 128 * 40) * 2)   // 81920 B
#define SMEM2 (2 * (2 * 128 * 40 + 2 * 32 * 40) * 2)    // 51200 B

extern "C" void kernel_launch(void* const* d_in, const int* in_sizes, int n_in,
                              void* d_out, int out_size)
{
    const float* x      = (const float*)d_in[0];
    const int*   ei     = (const int*)d_in[1];
    const float* W0     = (const float*)d_in[3];
    const float* W12    = (const float*)d_in[4];
    const float* att_s  = (const float*)d_in[5];
    const float* att_d  = (const float*)d_in[6];
    const float* gbias  = (const float*)d_in[7];
    const float* qkv_w  = (const float*)d_in[8];
    const float* qkv_b  = (const float*)d_in[9];
    const float* out_w  = (const float*)d_in[10];
    const float* out_b  = (const float*)d_in[11];
    const float* ln1w   = (const float*)d_in[12];
    const float* ln1b   = (const float*)d_in[13];
    const float* ln2w   = (const float*)d_in[14];
    const float* ln2b   = (const float*)d_in[15];
    const float* ff1w   = (const float*)d_in[16];
    const float* ff1b   = (const float*)d_in[17];
    const float* ff2w   = (const float*)d_in[18];
    const float* ff2b   = (const float*)d_in[19];
    const float* predw  = (const float*)d_in[20];
    const float* predb  = (const float*)d_in[21];
    float* out = (float*)d_out;

    int E = in_sizes[1] / 2;
    int Etot = E + Nn;

    cudaFuncSetAttribute((const void*)hgemm<0, 128, 2, 4>, cudaFuncAttributeMaxDynamicSharedMemorySize, SMEM0);
    cudaFuncSetAttribute((const void*)hgemm<1, 128, 2, 4>, cudaFuncAttributeMaxDynamicSharedMemorySize, SMEM0);
    cudaFuncSetAttribute((const void*)hgemm<2, 32, 8, 1>,  cudaFuncAttributeMaxDynamicSharedMemorySize, SMEM2);

    float *ph, *px, *py, *pssum, *pqkv, *pS, *pff;
    unsigned* pm;
    bf16 *pah, *pal, *pwh, *pwl, *pqh, *pql, *psh, *psl, *pvth, *pvtl;
    cudaGetSymbolAddress((void**)&ph,    g_h);
    cudaGetSymbolAddress((void**)&px,    g_x);
    cudaGetSymbolAddress((void**)&py,    g_y);
    cudaGetSymbolAddress((void**)&pm,    g_menc);
    cudaGetSymbolAddress((void**)&pssum, g_ssum);
    cudaGetSymbolAddress((void**)&pqkv,  g_qkv);
    cudaGetSymbolAddress((void**)&pS,    g_S);
    cudaGetSymbolAddress((void**)&pff,   g_ff);
    cudaGetSymbolAddress((void**)&pah,   g_ah);
    cudaGetSymbolAddress((void**)&pal,   g_al);
    cudaGetSymbolAddress((void**)&pwh,   g_wh);
    cudaGetSymbolAddress((void**)&pwl,   g_wl);
    cudaGetSymbolAddress((void**)&pqh,   g_qh);
    cudaGetSymbolAddress((void**)&pql,   g_ql);
    cudaGetSymbolAddress((void**)&psh,   g_sh);
    cudaGetSymbolAddress((void**)&psl,   g_sl);
    cudaGetSymbolAddress((void**)&pvth,  g_vth);
    cudaGetSymbolAddress((void**)&pvtl,  g_vtl);

    // ---------------- GAT layers ----------------
    const float* cur = x;
    int curK = 64;
    float* aggr_targets[3] = {px, py, px};
    for (int l = 0; l < 3; l++) {
        const float* W = (l == 0) ? W0 : (W12 + (size_t)(l - 1) * Dd * Dd);
        float* aggr = aggr_targets[l];
        cvt_hilo<<<(Nn * curK / 4 + 255) / 256, 256>>>(cur, pah, pal, Nn * curK / 4);
        cvt_hilo<<<(Dd * curK / 4 + 255) / 256, 256>>>(W, pwh, pwl, Dd * curK / 4);
        hgemm<0, 128, 2, 4><<<dim3(Dd / 128, Nn / 128), 256, SMEM0>>>(
            pah, pal, curK, pwh, pwl, curK, nullptr, ph, Dd, curK, 0);
        att_prep<<<(Nn * Hh + 255) / 256, 256>>>(ph, att_s + l * Dd, att_d + l * Dd);
        fillz<<<(Nn * Hh + 255) / 256, 256>>>((float*)pm, Nn * Hh);
        fillz<<<(Nn * Hh + 255) / 256, 256>>>(pssum, Nn * Hh);
        fillz<<<(Nn * Dd + 255) / 256, 256>>>(aggr, Nn * Dd);
        edge_pass1<<<(Etot * Hh + 255) / 256, 256>>>(ei, E, Etot);
        edge_pass2<<<(Etot * Hh + 255) / 256, 256>>>(ei, E, Etot);
        edge_pass3<<<(Etot * 32 + 255) / 256, 256>>>(ei, E, Etot, ph, aggr);
        bias_relu<<<(Nn * Dd + 255) / 256, 256>>>(aggr, gbias + l * Dd);
        cur = aggr;
        curK = Dd;
    }
    // features now in g_x

    // ---------------- transformer layers ----------------
    const float scale = 0.17677669529663687f;  // 1/sqrt(32)
    for (int i = 0; i < 2; i++) {
        // QKV projection
        cvt_hilo<<<(Nn * Dd / 4 + 255) / 256, 256>>>(px, pah, pal, Nn * Dd / 4);
        cvt_hilo<<<(768 * Dd / 4 + 255) / 256, 256>>>(qkv_w + (size_t)i * 768 * Dd, pwh, pwl, 768 * Dd / 4);
        hgemm<0, 128, 2, 4><<<dim3(768 / 128, Nn / 128), 256, SMEM0>>>(
            pah, pal, Dd, pwh, pwl, Dd, qkv_b + i * 768, pqkv, 768, Dd, 0);
        // attention
        cvt_hilo<<<(Nn * 768 / 4 + 255) / 256, 256>>>(pqkv, pqh, pql, Nn * 768 / 4);
        cvt_vt<<<(64 * 32 * 1024) / 256, 256>>>(pqkv, pvth, pvtl);
        hgemm<1, 128, 2, 4><<<dim3(8, 8, 64), 256, SMEM0>>>(
            pqh, pql, 768, pqh, pql, 768, nullptr, pS, Ll, 32, 0);
        softmax_rows<<<Bb * Hh * Ll, 256>>>(pS, psh, psl, scale);
        hgemm<2, 32, 8, 1><<<dim3(1, 8, 64), 256, SMEM2>>>(
            psh, psl, Ll, pvth, pvtl, 1024, nullptr, py, Dd, Ll, 0);
        // out projection
        cvt_hilo<<<(Nn * Dd / 4 + 255) / 256, 256>>>(py, pah, pal, Nn * Dd / 4);
        cvt_hilo<<<(Dd * Dd / 4 + 255) / 256, 256>>>(out_w + (size_t)i * Dd * Dd, pwh, pwl, Dd * Dd / 4);
        hgemm<0, 128, 2, 4><<<dim3(Dd / 128, Nn / 128), 256, SMEM0>>>(
            pah, pal, Dd, pwh, pwl, Dd, out_b + i * Dd, ph, Dd, Dd, 0);
        ln_res<<<Nn / 8, 256>>>(px, ph, px, ln1w + i * Dd, ln1b + i * Dd);
        // FFN
        cvt_hilo<<<(Nn * Dd / 4 + 255) / 256, 256>>>(px, pah, pal, Nn * Dd / 4);
        cvt_hilo<<<(DFF * Dd / 4 + 255) / 256, 256>>>(ff1w + (size_t)i * DFF * Dd, pwh, pwl, DFF * Dd / 4);
        hgemm<0, 128, 2, 4><<<dim3(DFF / 128, Nn / 128), 256, SMEM0>>>(
            pah, pal, Dd, pwh, pwl, Dd, ff1b + i * DFF, pff, DFF, Dd, 1);
        cvt_hilo<<<(Nn * DFF / 4 + 255) / 256, 256>>>(pff, pah, pal, Nn * DFF / 4);
        cvt_hilo<<<(Dd * DFF / 4 + 255) / 256, 256>>>(ff2w + (size_t)i * Dd * DFF, pwh, pwl, Dd * DFF / 4);
        hgemm<0, 128, 2, 4><<<dim3(Dd / 128, Nn / 128), 256, SMEM0>>>(
            pah, pal, DFF, pwh, pwl, DFF, ff2b + i * Dd, ph, Dd, DFF, 0);
        ln_res<<<Nn / 8, 256>>>(px, ph, px, ln2w + i * Dd, ln2b + i * Dd);
    }

    // ---------------- prediction head ----------------
    pred_kernel<<<(Nn * 32 + 255) / 256, 256>>>(px, predw, predb, out);
}

// round 4
// speedup vs baseline: 2.2521x; 1.2720x over previous
#include <cuda_runtime.h>
#include <cuda_bf16.h>
#include <math.h>
#include <stdint.h>

using bf16 = __nv_bfloat16;

#define Nn   8192
#define Bb   8
#define Ll   1024
#define Hh   8
#define Cc   32
#define Dd   256
#define DFF  2048
#define Emax 262144
#define ETOTmax (Emax + Nn)

// ------------------------- scratch (static device globals) -------------------------
__device__ float    g_h   [Nn * Dd];
__device__ float    g_x   [Nn * Dd];
__device__ float    g_y   [Nn * Dd];
__device__ float    g_as  [Nn * Hh];
__device__ float    g_ad  [Nn * Hh];
__device__ unsigned g_menc[Nn * Hh];
__device__ float    g_ssum[Nn * Hh];
__device__ float    g_e   [ETOTmax * Hh];

__device__ bf16 g_ah[Nn * DFF];               // A hi (max 8192x2048)
__device__ bf16 g_al[Nn * DFF];               // A lo
__device__ bf16 g_xh[Nn * Dd];                // residual stream hi
__device__ bf16 g_xl[Nn * Dd];
__device__ bf16 g_wh[DFF * Dd];               // W hi (max 2048x256)
__device__ bf16 g_wl[DFF * Dd];
__device__ bf16 g_qh[Nn * 3 * Dd];            // qkv hi
__device__ bf16 g_ql[Nn * 3 * Dd];
__device__ bf16 g_vth[64 * 32 * 1024];        // V transposed hi: [z][d][k]
__device__ bf16 g_vtl[64 * 32 * 1024];

// ------------------------- helpers -------------------------
__device__ __forceinline__ uint32_t smem_u32(const void* p) {
    uint32_t a;
    asm("{ .reg .u64 t; cvta.to.shared.u64 t, %1; cvt.u32.u64 %0, t; }" : "=r"(a) : "l"(p));
    return a;
}
__device__ __forceinline__ void cp16(uint32_t s, const void* g) {
    asm volatile("cp.async.cg.shared.global [%0], [%1], 16;" :: "r"(s), "l"(g));
}
__device__ __forceinline__ void cp_commit() {
    asm volatile("cp.async.commit_group;" ::: "memory");
}
__device__ __forceinline__ void cp_wait0() {
    asm volatile("cp.async.wait_group 0;" ::: "memory");
}
__device__ __forceinline__ void cp_wait1() {
    asm volatile("cp.async.wait_group 1;" ::: "memory");
}
__device__ __forceinline__ void ldm4(uint32_t* r, uint32_t addr) {
    asm volatile("ldmatrix.sync.aligned.m8n8.x4.shared.b16 {%0,%1,%2,%3}, [%4];"
        : "=r"(r[0]), "=r"(r[1]), "=r"(r[2]), "=r"(r[3]) : "r"(addr));
}
__device__ __forceinline__ void mma16816(float* d, const uint32_t* a, const uint32_t* b) {
    asm volatile(
        "mma.sync.aligned.m16n8k16.row.col.f32.bf16.bf16.f32 "
        "{%0,%1,%2,%3}, {%4,%5,%6,%7}, {%8,%9}, {%0,%1,%2,%3};"
        : "+f"(d[0]), "+f"(d[1]), "+f"(d[2]), "+f"(d[3])
        : "r"(a[0]), "r"(a[1]), "r"(a[2]), "r"(a[3]), "r"(b[0]), "r"(b[1]));
}
__device__ __forceinline__ float warpSum(float v) {
    #pragma unroll
    for (int o = 16; o > 0; o >>= 1) v += __shfl_xor_sync(0xffffffffu, v, o);
    return v;
}
__device__ __forceinline__ unsigned fenc(float f) {
    unsigned u = __float_as_uint(f);
    return (u & 0x80000000u) ? ~u : (u | 0x80000000u);
}
__device__ __forceinline__ float fdec(unsigned e) {
    unsigned u = (e & 0x80000000u) ? (e & 0x7fffffffu) : ~e;
    return __uint_as_float(u);
}
// pack two fp32 into bf16x2 hi reg, residual into lo reg
__device__ __forceinline__ uint32_t pk2(float a, float b, uint32_t& lo) {
    bf16 ha = __float2bfloat16(a), hb = __float2bfloat16(b);
    bf16 la = __float2bfloat16(a - __bfloat162float(ha));
    bf16 lb = __float2bfloat16(b - __bfloat162float(hb));
    lo = ((uint32_t)__bfloat16_as_ushort(lb) << 16) | __bfloat16_as_ushort(la);
    return ((uint32_t)__bfloat16_as_ushort(hb) << 16) | __bfloat16_as_ushort(ha);
}

// ------------------------- fp32 -> bf16 hi/lo conversion -------------------------
__global__ void cvt_hilo(const float* __restrict__ in, bf16* __restrict__ hi,
                         bf16* __restrict__ lo, int n4)
{
    int i = blockIdx.x * 256 + threadIdx.x;
    if (i >= n4) return;
    float4 x = ((const float4*)in)[i];
    float xs[4] = {x.x, x.y, x.z, x.w};
    bf16 h[4], l[4];
    #pragma unroll
    for (int j = 0; j < 4; j++) {
        h[j] = __float2bfloat16(xs[j]);
        l[j] = __float2bfloat16(xs[j] - __bfloat162float(h[j]));
    }
    ((__nv_bfloat162*)hi)[2 * i]     = __nv_bfloat162(h[0], h[1]);
    ((__nv_bfloat162*)hi)[2 * i + 1] = __nv_bfloat162(h[2], h[3]);
    ((__nv_bfloat162*)lo)[2 * i]     = __nv_bfloat162(l[0], l[1]);
    ((__nv_bfloat162*)lo)[2 * i + 1] = __nv_bfloat162(l[2], l[3]);
}

// V^T gather (hi/lo already split):  vt[z][d][k] = qkv_hl[b*1024+k][512 + h*32 + d]
__global__ void cvt_vt(const bf16* __restrict__ qh, const bf16* __restrict__ ql,
                       bf16* __restrict__ vth, bf16* __restrict__ vtl)
{
    int i = blockIdx.x * 256 + threadIdx.x;           // 64*32*1024 = 2M
    int k = i & 1023, d = (i >> 10) & 31, z = i >> 15;
    int b = z >> 3, h = z & 7;
    size_t src = (size_t)(b * 1024 + k) * 768 + 512 + h * 32 + d;
    vth[i] = qh[src];
    vtl[i] = ql[src];
}

// ------------------------- HMMA split-bf16 GEMM -------------------------
// C[M,N] = A[M,K] @ W[N,K]^T (+bias)(+relu). grid (N/128, M/128), 256 thr.
// OUT=0: fp32 C.  OUT=1: bf16 hi/lo (Ch, Cl).
template<int OUT>
__global__ void __launch_bounds__(256, 1)
hgemm(const bf16* __restrict__ aH, const bf16* __restrict__ aL, int lda,
      const bf16* __restrict__ bH, const bf16* __restrict__ bL, int ldb,
      const float* __restrict__ bias, float* __restrict__ C,
      bf16* __restrict__ Ch, bf16* __restrict__ Cl, int ldc,
      int K, int relu)
{
    constexpr int WM = 64, WN = 32, MT = 4, NT8 = 4;
    constexpr int SST = 40;
    constexpr int ATILE = 128 * SST;
    constexpr int BTILE = 128 * SST;
    constexpr int STAGE = 2 * ATILE + 2 * BTILE;

    extern __shared__ bf16 sm[];

    int tid = threadIdx.x;
    int wid = tid >> 5, lane = tid & 31;
    int wm = wid % 2, wn = wid / 2;
    int m0 = blockIdx.y * 128;
    int n0 = blockIdx.x * 128;

    float acc[MT][NT8][4] = {};
    int P = K >> 5;

    auto load_panel = [&](int p, int s) {
        bf16* Ah = sm + s * STAGE;
        bf16* Al = Ah + ATILE;
        bf16* Bh = Al + ATILE;
        bf16* Bl = Bh + BTILE;
        int k0 = p * 32;
        #pragma unroll 2
        for (int idx = tid; idx < 512; idx += 256) {
            int r = idx >> 2, c = idx & 3;
            size_t g = (size_t)(m0 + r) * lda + k0 + c * 8;
            cp16(smem_u32(Ah + r * SST + c * 8), aH + g);
            cp16(smem_u32(Al + r * SST + c * 8), aL + g);
        }
        #pragma unroll 2
        for (int idx = tid; idx < 512; idx += 256) {
            int r = idx >> 2, c = idx & 3;
            size_t g = (size_t)(n0 + r) * ldb + k0 + c * 8;
            cp16(smem_u32(Bh + r * SST + c * 8), bH + g);
            cp16(smem_u32(Bl + r * SST + c * 8), bL + g);
        }
        cp_commit();
    };

    int t8 = lane >> 3;
    int rA = (t8 & 1) * 8 + (lane & 7), cA = (t8 >> 1) * 8;
    int rB = (t8 >> 1) * 8 + (lane & 7), cB = (t8 & 1) * 8;

    auto compute = [&](int s) {
        bf16* Ah = sm + s * STAGE;
        bf16* Al = Ah + ATILE;
        bf16* Bh = Al + ATILE;
        bf16* Bl = Bh + BTILE;
        #pragma unroll
        for (int kk = 0; kk < 2; kk++) {
            int k16 = kk * 16;
            uint32_t ah[MT][4], al[MT][4], bh[NT8][2], bl[NT8][2];
            #pragma unroll
            for (int mt = 0; mt < MT; mt++) {
                int row = wm * WM + mt * 16 + rA;
                ldm4(ah[mt], smem_u32(Ah + row * SST + k16 + cA));
                ldm4(al[mt], smem_u32(Al + row * SST + k16 + cA));
            }
            #pragma unroll
            for (int nt2 = 0; nt2 < NT8 / 2; nt2++) {
                int row = wn * WN + nt2 * 16 + rB;
                uint32_t r4[4];
                ldm4(r4, smem_u32(Bh + row * SST + k16 + cB));
                bh[2 * nt2][0] = r4[0]; bh[2 * nt2][1] = r4[1];
                bh[2 * nt2 + 1][0] = r4[2]; bh[2 * nt2 + 1][1] = r4[3];
                ldm4(r4, smem_u32(Bl + row * SST + k16 + cB));
                bl[2 * nt2][0] = r4[0]; bl[2 * nt2][1] = r4[1];
                bl[2 * nt2 + 1][0] = r4[2]; bl[2 * nt2 + 1][1] = r4[3];
            }
            #pragma unroll
            for (int mt = 0; mt < MT; mt++) {
                #pragma unroll
                for (int nt = 0; nt < NT8; nt++) {
                    mma16816(acc[mt][nt], ah[mt], bh[nt]);
                    mma16816(acc[mt][nt], ah[mt], bl[nt]);
                    mma16816(acc[mt][nt], al[mt], bh[nt]);
                }
            }
        }
    };

    load_panel(0, 0);
    for (int p = 0; p < P; p++) {
        if (p + 1 < P) {
            load_panel(p + 1, (p + 1) & 1);
            cp_wait1();
        } else {
            cp_wait0();
        }
        __syncthreads();
        compute(p & 1);
        __syncthreads();
    }

    int grp = lane >> 2, q4 = lane & 3;
    #pragma unroll
    for (int mt = 0; mt < MT; mt++) {
        #pragma unroll
        for (int nt = 0; nt < NT8; nt++) {
            int row = m0 + wm * WM + mt * 16 + grp;
            int col = n0 + wn * WN + nt * 8 + q4 * 2;
            float* a4 = acc[mt][nt];
            float b0 = 0.0f, b1 = 0.0f;
            if (bias) { b0 = bias[col]; b1 = bias[col + 1]; }
            float v0 = a4[0] + b0, v1 = a4[1] + b1;
            float v2 = a4[2] + b0, v3 = a4[3] + b1;
            if (relu) {
                v0 = fmaxf(v0, 0.0f); v1 = fmaxf(v1, 0.0f);
                v2 = fmaxf(v2, 0.0f); v3 = fmaxf(v3, 0.0f);
            }
            if (OUT == 0) {
                *(float2*)&C[(size_t)row * ldc + col]       = make_float2(v0, v1);
                *(float2*)&C[(size_t)(row + 8) * ldc + col] = make_float2(v2, v3);
            } else {
                uint32_t lo0, lo1;
                uint32_t h0 = pk2(v0, v1, lo0);
                uint32_t h1 = pk2(v2, v3, lo1);
                *(uint32_t*)&Ch[(size_t)row * ldc + col]       = h0;
                *(uint32_t*)&Cl[(size_t)row * ldc + col]       = lo0;
                *(uint32_t*)&Ch[(size_t)(row + 8) * ldc + col] = h1;
                *(uint32_t*)&Cl[(size_t)(row + 8) * ldc + col] = lo1;
            }
        }
    }
}

// ------------------------- fused flash attention -------------------------
// grid (8 qtiles, 64 zh), 256 threads (8 warps x 16 q rows).
// Q,K from qkv hi/lo [8192][768]; V^T hi/lo [z][32][1024]; out bf16 hi/lo [8192][256].
__global__ void __launch_bounds__(256, 1)
flash_attn(const bf16* __restrict__ qkh, const bf16* __restrict__ qkl,
           const bf16* __restrict__ vth, const bf16* __restrict__ vtl,
           bf16* __restrict__ Oh, bf16* __restrict__ Ol, float scale)
{
    constexpr int QST = 40, VST = 136;
    constexpr int KBUF = 2 * 128 * QST + 2 * 32 * VST;  // elems
    extern __shared__ bf16 fsm[];
    bf16* sQh = fsm;
    bf16* sQl = sQh + 128 * QST;
    bf16* sK  = sQl + 128 * QST;

    int tid = threadIdx.x, wid = tid >> 5, lane = tid & 31;
    int z = blockIdx.y, b = z >> 3, h = z & 7;
    int q0 = blockIdx.x * 128;

    const bf16* Qh = qkh + (size_t)b * 1024 * 768 + h * 32;
    const bf16* Ql = qkl + (size_t)b * 1024 * 768 + h * 32;
    const bf16* Kh = Qh + 256;
    const bf16* Kl = Ql + 256;
    const bf16* Vh = vth + (size_t)z * 32 * 1024;
    const bf16* Vl = vtl + (size_t)z * 32 * 1024;

    // load Q once (grouped with chunk 0 commit)
    for (int idx = tid; idx < 512; idx += 256) {
        int r = idx >> 2, c = idx & 3;
        cp16(smem_u32(sQh + r * QST + c * 8), Qh + (size_t)(q0 + r) * 768 + c * 8);
        cp16(smem_u32(sQl + r * QST + c * 8), Ql + (size_t)(q0 + r) * 768 + c * 8);
    }
    auto load_chunk = [&](int p, int s) {
        bf16* kh = sK + s * KBUF;
        bf16* kl = kh + 128 * QST;
        bf16* vh = kl + 128 * QST;
        bf16* vl = vh + 32 * VST;
        int k0 = p * 128;
        #pragma unroll 2
        for (int idx = tid; idx < 512; idx += 256) {
            int r = idx >> 2, c = idx & 3;
            cp16(smem_u32(kh + r * QST + c * 8), Kh + (size_t)(k0 + r) * 768 + c * 8);
            cp16(smem_u32(kl + r * QST + c * 8), Kl + (size_t)(k0 + r) * 768 + c * 8);
        }
        #pragma unroll 2
        for (int idx = tid; idx < 512; idx += 256) {
            int r = idx >> 4, c = idx & 15;
            cp16(smem_u32(vh + r * VST + c * 8), Vh + (size_t)r * 1024 + k0 + c * 8);
            cp16(smem_u32(vl + r * VST + c * 8), Vl + (size_t)r * 1024 + k0 + c * 8);
        }
        cp_commit();
    };

    int t8 = lane >> 3;
    int rA = (t8 & 1) * 8 + (lane & 7), cA = (t8 >> 1) * 8;
    int rB = (t8 >> 1) * 8 + (lane & 7), cB = (t8 & 1) * 8;
    int grp = lane >> 2, q4 = lane & 3;

    float oacc[4][4] = {};
    float m0 = -1e30f, m1 = -1e30f, l0 = 0.0f, l1 = 0.0f;
    uint32_t qfh[2][4], qfl[2][4];

    load_chunk(0, 0);
    for (int p = 0; p < 8; p++) {
        if (p < 7) { load_chunk(p + 1, (p + 1) & 1); cp_wait1(); }
        else cp_wait0();
        __syncthreads();
        if (p == 0) {
            #pragma unroll
            for (int kk = 0; kk < 2; kk++) {
                ldm4(qfh[kk], smem_u32(sQh + (wid * 16 + rA) * QST + kk * 16 + cA));
                ldm4(qfl[kk], smem_u32(sQl + (wid * 16 + rA) * QST + kk * 16 + cA));
            }
        }
        bf16* kh = sK + (p & 1) * KBUF;
        bf16* kl = kh + 128 * QST;
        bf16* vh = kl + 128 * QST;
        bf16* vl = vh + 32 * VST;

        // ---- S = Q K^T (16 q rows x 128 keys per warp) ----
        float sacc[16][4];
        #pragma unroll
        for (int t = 0; t < 16; t++) { sacc[t][0] = 0; sacc[t][1] = 0; sacc[t][2] = 0; sacc[t][3] = 0; }
        #pragma unroll
        for (int nt2 = 0; nt2 < 8; nt2++) {
            #pragma unroll
            for (int kk = 0; kk < 2; kk++) {
                uint32_t bh4[4], bl4[4];
                ldm4(bh4, smem_u32(kh + (nt2 * 16 + rB) * QST + kk * 16 + cB));
                ldm4(bl4, smem_u32(kl + (nt2 * 16 + rB) * QST + kk * 16 + cB));
                #pragma unroll
                for (int hf = 0; hf < 2; hf++) {
                    mma16816(sacc[2 * nt2 + hf], qfh[kk], &bh4[2 * hf]);
                    mma16816(sacc[2 * nt2 + hf], qfh[kk], &bl4[2 * hf]);
                    mma16816(sacc[2 * nt2 + hf], qfl[kk], &bh4[2 * hf]);
                }
            }
        }
        // ---- online softmax ----
        float cm0 = -1e30f, cm1 = -1e30f;
        #pragma unroll
        for (int t = 0; t < 16; t++) {
            sacc[t][0] *= scale; sacc[t][1] *= scale;
            sacc[t][2] *= scale; sacc[t][3] *= scale;
            cm0 = fmaxf(cm0, fmaxf(sacc[t][0], sacc[t][1]));
            cm1 = fmaxf(cm1, fmaxf(sacc[t][2], sacc[t][3]));
        }
        cm0 = fmaxf(cm0, __shfl_xor_sync(0xffffffffu, cm0, 1));
        cm0 = fmaxf(cm0, __shfl_xor_sync(0xffffffffu, cm0, 2));
        cm1 = fmaxf(cm1, __shfl_xor_sync(0xffffffffu, cm1, 1));
        cm1 = fmaxf(cm1, __shfl_xor_sync(0xffffffffu, cm1, 2));
        float mn0 = fmaxf(m0, cm0), mn1 = fmaxf(m1, cm1);
        float c0 = __expf(m0 - mn0), c1 = __expf(m1 - mn1);
        m0 = mn0; m1 = mn1;
        float rs0 = 0.0f, rs1 = 0.0f;
        #pragma unroll
        for (int t = 0; t < 16; t++) {
            sacc[t][0] = __expf(sacc[t][0] - mn0);
            sacc[t][1] = __expf(sacc[t][1] - mn0);
            sacc[t][2] = __expf(sacc[t][2] - mn1);
            sacc[t][3] = __expf(sacc[t][3] - mn1);
            rs0 += sacc[t][0] + sacc[t][1];
            rs1 += sacc[t][2] + sacc[t][3];
        }
        l0 = l0 * c0 + rs0;
        l1 = l1 * c1 + rs1;
        #pragma unroll
        for (int n = 0; n < 4; n++) {
            oacc[n][0] *= c0; oacc[n][1] *= c0;
            oacc[n][2] *= c1; oacc[n][3] *= c1;
        }
        // ---- O += P V ----
        #pragma unroll
        for (int kt = 0; kt < 8; kt++) {
            uint32_t pah4[4], pal4[4];
            pah4[0] = pk2(sacc[2 * kt][0],     sacc[2 * kt][1],     pal4[0]);
            pah4[1] = pk2(sacc[2 * kt][2],     sacc[2 * kt][3],     pal4[1]);
            pah4[2] = pk2(sacc[2 * kt + 1][0], sacc[2 * kt + 1][1], pal4[2]);
            pah4[3] = pk2(sacc[2 * kt + 1][2], sacc[2 * kt + 1][3], pal4[3]);
            #pragma unroll
            for (int np = 0; np < 2; np++) {
                uint32_t vb_h[4], vb_l[4];
                ldm4(vb_h, smem_u32(vh + (np * 16 + rB) * VST + kt * 16 + cB));
                ldm4(vb_l, smem_u32(vl + (np * 16 + rB) * VST + kt * 16 + cB));
                #pragma unroll
                for (int hf = 0; hf < 2; hf++) {
                    mma16816(oacc[2 * np + hf], pah4, &vb_h[2 * hf]);
                    mma16816(oacc[2 * np + hf], pah4, &vb_l[2 * hf]);
                    mma16816(oacc[2 * np + hf], pal4, &vb_h[2 * hf]);
                }
            }
        }
        __syncthreads();
    }
    // ---- epilogue: O / l, write bf16 hi/lo ----
    l0 += __shfl_xor_sync(0xffffffffu, l0, 1);
    l0 += __shfl_xor_sync(0xffffffffu, l0, 2);
    l1 += __shfl_xor_sync(0xffffffffu, l1, 1);
    l1 += __shfl_xor_sync(0xffffffffu, l1, 2);
    float i0 = 1.0f / l0, i1 = 1.0f / l1;
    size_t obase = (size_t)(b * 1024 + q0) * 256 + h * 32;
    #pragma unroll
    for (int n = 0; n < 4; n++) {
        int row = wid * 16 + grp;
        int col = n * 8 + q4 * 2;
        uint32_t lo0, lo1;
        uint32_t h0 = pk2(oacc[n][0] * i0, oacc[n][1] * i0, lo0);
        uint32_t h1 = pk2(oacc[n][2] * i1, oacc[n][3] * i1, lo1);
        *(uint32_t*)&Oh[obase + (size_t)row * 256 + col]       = h0;
        *(uint32_t*)&Ol[obase + (size_t)row * 256 + col]       = lo0;
        *(uint32_t*)&Oh[obase + (size_t)(row + 8) * 256 + col] = h1;
        *(uint32_t*)&Ol[obase + (size_t)(row + 8) * 256 + col] = lo1;
    }
}

// ------------------------- GAT pieces -------------------------
__global__ void fillz(float* p, int n) {
    int i = blockIdx.x * 256 + threadIdx.x;
    if (i < n) p[i] = 0.0f;
}

__global__ void att_prep(const float* __restrict__ hbuf,
                         const float* __restrict__ atts, const float* __restrict__ attd)
{
    int t = blockIdx.x * 256 + threadIdx.x;
    if (t >= Nn * Hh) return;
    int n = t >> 3, hd = t & 7;
    const float* hp = hbuf + (size_t)n * Dd + hd * Cc;
    const float* pa = atts + hd * Cc;
    const float* pb = attd + hd * Cc;
    float s1 = 0.0f, s2 = 0.0f;
    #pragma unroll
    for (int c = 0; c < Cc; c++) {
        float hv = hp[c];
        s1 += hv * pa[c];
        s2 += hv * pb[c];
    }
    g_as[t] = s1;
    g_ad[t] = s2;
}

__global__ void edge_pass1(const int* __restrict__ ei, int E, int Etot)
{
    int t = blockIdx.x * 256 + threadIdx.x;
    if (t >= Etot * Hh) return;
    int e = t >> 3, hd = t & 7;
    int s, d;
    if (e < E) { s = ei[e]; d = ei[E + e]; } else { s = d = e - E; }
    float v = g_as[s * Hh + hd] + g_ad[d * Hh + hd];
    v = v > 0.0f ? v : 0.2f * v;
    g_e[t] = v;
    atomicMax(&g_menc[d * Hh + hd], fenc(v));
}

__global__ void edge_pass2(const int* __restrict__ ei, int E, int Etot)
{
    int t = blockIdx.x * 256 + threadIdx.x;
    if (t >= Etot * Hh) return;
    int e = t >> 3, hd = t & 7;
    int d;
    if (e < E) { d = ei[E + e]; } else { d = e - E; }
    float m = fdec(g_menc[d * Hh + hd]);
    float p = __expf(g_e[t] - m);
    g_e[t] = p;
    atomicAdd(&g_ssum[d * Hh + hd], p);
}

__global__ void edge_pass3(const int* __restrict__ ei, int E, int Etot,
                           const float* __restrict__ hbuf, float* __restrict__ obuf)
{
    int gt = blockIdx.x * 256 + threadIdx.x;
    int e = gt >> 5, lane = gt & 31;
    if (e >= Etot) return;
    int s, d;
    if (e < E) { s = ei[e]; d = ei[E + e]; } else { s = d = e - E; }
    #pragma unroll
    for (int k = 0; k < Hh; k++) {
        float alpha = g_e[e * Hh + k] / g_ssum[d * Hh + k];
        float hv = hbuf[(size_t)s * Dd + k * Cc + lane];
        atomicAdd(&obuf[(size_t)d * Dd + k * Cc + lane], hv * alpha);
    }
}

__global__ void bias_relu(float* __restrict__ buf, const float* __restrict__ bias,
                          bf16* __restrict__ oh, bf16* __restrict__ ol)
{
    int t = blockIdx.x * 256 + threadIdx.x;
    if (t >= Nn * Dd) return;
    float v = buf[t] + bias[t & (Dd - 1)];
    v = fmaxf(v, 0.0f);
    buf[t] = v;
    bf16 h = __float2bfloat16(v);
    oh[t] = h;
    ol[t] = __float2bfloat16(v - __bfloat162float(h));
}

// ------------------------- residual + layernorm (emits fp32 + bf16 hi/lo) -------------------------
__global__ void ln_res(const float* __restrict__ xin, const float* __restrict__ add,
                       float* __restrict__ xout, const float* __restrict__ w,
                       const float* __restrict__ b,
                       bf16* __restrict__ oh, bf16* __restrict__ ol)
{
    int row = blockIdx.x * 8 + (threadIdx.x >> 5);
    int lane = threadIdx.x & 31;
    const float* xr = xin + (size_t)row * Dd;
    const float* ar = add + (size_t)row * Dd;
    float v[8];
    float s = 0.0f;
    #pragma unroll
    for (int j = 0; j < 8; j++) {
        int d = lane + j * 32;
        v[j] = xr[d] + ar[d];
        s += v[j];
    }
    s = warpSum(s);
    float mean = s * (1.0f / 256.0f);
    float var = 0.0f;
    #pragma unroll
    for (int j = 0; j < 8; j++) {
        float dv = v[j] - mean;
        var += dv * dv;
    }
    var = warpSum(var) * (1.0f / 256.0f);
    float inv = rsqrtf(var + 1e-5f);
    float* orow = xout + (size_t)row * Dd;
    #pragma unroll
    for (int j = 0; j < 8; j++) {
        int d = lane + j * 32;
        float o = (v[j] - mean) * inv * w[d] + b[d];
        orow[d] = o;
        bf16 h = __float2bfloat16(o);
        oh[(size_t)row * Dd + d] = h;
        ol[(size_t)row * Dd + d] = __float2bfloat16(o - __bfloat162float(h));
    }
}

// ------------------------- prediction head -------------------------
__global__ void pred_kernel(const float* __restrict__ xin, const float* __restrict__ pw,
                            const float* __restrict__ pb, float* __restrict__ out)
{
    int gw = (blockIdx.x * 256 + threadIdx.x) >> 5;
    int lane = threadIdx.x & 31;
    if (gw >= Nn) return;
    const float* xr = xin + (size_t)gw * Dd;
    float a0 = 0.0f, a1 = 0.0f, a2 = 0.0f;
    #pragma unroll
    for (int j = 0; j < 8; j++) {
        int d = lane + j * 32;
        float xv = xr[d];
        a0 += xv * pw[d];
        a1 += xv * pw[Dd + d];
        a2 += xv * pw[2 * Dd + d];
    }
    a0 = warpSum(a0);
    a1 = warpSum(a1);
    a2 = warpSum(a2);
    if (lane == 0) {
        out[gw * 3 + 0] = a0 + pb[0];
        out[gw * 3 + 1] = a1 + pb[1];
        out[gw * 3 + 2] = a2 + pb[2];
    }
}

// ------------------------- host orchestration -------------------------
#define SMEM_G (4 * 128 * 40 * 2 * 2)                       // 81920 B
#define SMEM_F ((2 * 128 * 40 + 2 * (2 * 128 * 40 + 2 * 32 * 136)) * 2)  // 96256 B

extern "C" void kernel_launch(void* const* d_in, const int* in_sizes, int n_in,
                              void* d_out, int out_size)
{
    const float* x      = (const float*)d_in[0];
    const int*   ei     = (const int*)d_in[1];
    const float* W0     = (const float*)d_in[3];
    const float* W12    = (const float*)d_in[4];
    const float* att_s  = (const float*)d_in[5];
    const float* att_d  = (const float*)d_in[6];
    const float* gbias  = (const float*)d_in[7];
    const float* qkv_w  = (const float*)d_in[8];
    const float* qkv_b  = (const float*)d_in[9];
    const float* out_w  = (const float*)d_in[10];
    const float* out_b  = (const float*)d_in[11];
    const float* ln1w   = (const float*)d_in[12];
    const float* ln1b   = (const float*)d_in[13];
    const float* ln2w   = (const float*)d_in[14];
    const float* ln2b   = (const float*)d_in[15];
    const float* ff1w   = (const float*)d_in[16];
    const float* ff1b   = (const float*)d_in[17];
    const float* ff2w   = (const float*)d_in[18];
    const float* ff2b   = (const float*)d_in[19];
    const float* predw  = (const float*)d_in[20];
    const float* predb  = (const float*)d_in[21];
    float* out = (float*)d_out;

    int E = in_sizes[1] / 2;
    int Etot = E + Nn;

    cudaFuncSetAttribute((const void*)hgemm<0>, cudaFuncAttributeMaxDynamicSharedMemorySize, SMEM_G);
    cudaFuncSetAttribute((const void*)hgemm<1>, cudaFuncAttributeMaxDynamicSharedMemorySize, SMEM_G);
    cudaFuncSetAttribute((const void*)flash_attn, cudaFuncAttributeMaxDynamicSharedMemorySize, SMEM_F);

    float *ph, *px, *py, *pssum;
    unsigned* pm;
    bf16 *pah, *pal, *pxh, *pxl, *pwh, *pwl, *pqh, *pql, *pvth, *pvtl;
    cudaGetSymbolAddress((void**)&ph,    g_h);
    cudaGetSymbolAddress((void**)&px,    g_x);
    cudaGetSymbolAddress((void**)&py,    g_y);
    cudaGetSymbolAddress((void**)&pm,    g_menc);
    cudaGetSymbolAddress((void**)&pssum, g_ssum);
    cudaGetSymbolAddress((void**)&pah,   g_ah);
    cudaGetSymbolAddress((void**)&pal,   g_al);
    cudaGetSymbolAddress((void**)&pxh,   g_xh);
    cudaGetSymbolAddress((void**)&pxl,   g_xl);
    cudaGetSymbolAddress((void**)&pwh,   g_wh);
    cudaGetSymbolAddress((void**)&pwl,   g_wl);
    cudaGetSymbolAddress((void**)&pqh,   g_qh);
    cudaGetSymbolAddress((void**)&pql,   g_ql);
    cudaGetSymbolAddress((void**)&pvth,  g_vth);
    cudaGetSymbolAddress((void**)&pvtl,  g_vtl);

    // ---------------- GAT layers ----------------
    // layer 0 input: raw x (K=64) -> cvt; later layers: bias_relu emits hi/lo
    cvt_hilo<<<(Nn * 64 / 4 + 255) / 256, 256>>>(x, pxh, pxl, Nn * 64 / 4);
    int curK = 64;
    float* aggr_targets[3] = {px, py, px};
    for (int l = 0; l < 3; l++) {
        const float* W = (l == 0) ? W0 : (W12 + (size_t)(l - 1) * Dd * Dd);
        float* aggr = aggr_targets[l];
        cvt_hilo<<<(Dd * curK / 4 + 255) / 256, 256>>>(W, pwh, pwl, Dd * curK / 4);
        hgemm<0><<<dim3(Dd / 128, Nn / 128), 256, SMEM_G>>>(
            pxh, pxl, curK, pwh, pwl, curK, nullptr, ph, nullptr, nullptr, Dd, curK, 0);
        att_prep<<<(Nn * Hh + 255) / 256, 256>>>(ph, att_s + l * Dd, att_d + l * Dd);
        fillz<<<(Nn * Hh + 255) / 256, 256>>>((float*)pm, Nn * Hh);
        fillz<<<(Nn * Hh + 255) / 256, 256>>>(pssum, Nn * Hh);
        fillz<<<(Nn * Dd + 255) / 256, 256>>>(aggr, Nn * Dd);
        edge_pass1<<<(Etot * Hh + 255) / 256, 256>>>(ei, E, Etot);
        edge_pass2<<<(Etot * Hh + 255) / 256, 256>>>(ei, E, Etot);
        edge_pass3<<<(Etot * 32 + 255) / 256, 256>>>(ei, E, Etot, ph, aggr);
        bias_relu<<<(Nn * Dd + 255) / 256, 256>>>(aggr, gbias + l * Dd, pxh, pxl);
        curK = Dd;
    }
    // fp32 features in g_x (aggr_targets[2]); hi/lo in pxh/pxl

    // ---------------- transformer layers ----------------
    const float scale = 0.17677669529663687f;  // 1/sqrt(32)
    for (int i = 0; i < 2; i++) {
        // QKV projection -> bf16 hi/lo directly
        cvt_hilo<<<(768 * Dd / 4 + 255) / 256, 256>>>(qkv_w + (size_t)i * 768 * Dd, pwh, pwl, 768 * Dd / 4);
        hgemm<1><<<dim3(768 / 128, Nn / 128), 256, SMEM_G>>>(
            pxh, pxl, Dd, pwh, pwl, Dd, qkv_b + i * 768, nullptr, pqh, pql, 768, Dd, 0);
        // V transpose gather + fused flash attention -> pah/pal (bf16 hi/lo)
        cvt_vt<<<(64 * 32 * 1024) / 256, 256>>>(pqh, pql, pvth, pvtl);
        flash_attn<<<dim3(8, 64), 256, SMEM_F>>>(pqh, pql, pvth, pvtl, pah, pal, scale);
        // out projection (A = attention output hi/lo)
        cvt_hilo<<<(Dd * Dd / 4 + 255) / 256, 256>>>(out_w + (size_t)i * Dd * Dd, pwh, pwl, Dd * Dd / 4);
        hgemm<0><<<dim3(Dd / 128, Nn / 128), 256, SMEM_G>>>(
            pah, pal, Dd, pwh, pwl, Dd, out_b + i * Dd, ph, nullptr, nullptr, Dd, Dd, 0);
        ln_res<<<Nn / 8, 256>>>(px, ph, px, ln1w + i * Dd, ln1b + i * Dd, pxh, pxl);
        // FFN: FF1 -> bf16 hi/lo (relu), FF2 -> fp32
        cvt_hilo<<<(DFF * Dd / 4 + 255) / 256, 256>>>(ff1w + (size_t)i * DFF * Dd, pwh, pwl, DFF * Dd / 4);
        hgemm<1><<<dim3(DFF / 128, Nn / 128), 256, SMEM_G>>>(
            pxh, pxl, Dd, pwh, pwl, Dd, ff1b + i * DFF, nullptr, pah, pal, DFF, Dd, 1);
        cvt_hilo<<<(Dd * DFF / 4 + 255) / 256, 256>>>(ff2w + (size_t)i * Dd * DFF, pwh, pwl, Dd * DFF / 4);
        hgemm<0><<<dim3(Dd / 128, Nn / 128), 256, SMEM_G>>>(
            pah, pal, DFF, pwh, pwl, DFF, ff2b + i * Dd, ph, nullptr, nullptr, Dd, DFF, 0);
        ln_res<<<Nn / 8, 256>>>(px, ph, px, ln2w + i * Dd, ln2b + i * Dd, pxh, pxl);
    }

    // ---------------- prediction head ----------------
    pred_kernel<<<(Nn * 32 + 255) / 256, 256>>>(px, predw, predb, out);
}

// round 5
// speedup vs baseline: 2.6171x; 1.1620x over previous
#include <cuda_runtime.h>
#include <cuda_bf16.h>
#include <math.h>
#include <stdint.h>

using bf16 = __nv_bfloat16;

#define Nn   8192
#define Bb   8
#define Ll   1024
#define Hh   8
#define Cc   32
#define Dd   256
#define DFF  2048
#define Emax 262144
#define ETOTmax (Emax + Nn)

// ------------------------- scratch (static device globals) -------------------------
__device__ float    g_h   [Nn * Dd];
__device__ float    g_x   [Nn * Dd];
__device__ float    g_as  [Nn * Hh];
__device__ float    g_ad  [Nn * Hh];
__device__ int      g_cnt [Nn];
__device__ int      g_rowptr[Nn + 1];
__device__ int      g_wpos[Nn];
__device__ int      g_col [ETOTmax];

__device__ bf16 g_ah[Nn * DFF];               // A hi (max 8192x2048)
__device__ bf16 g_al[Nn * DFF];               // A lo
__device__ bf16 g_xh[Nn * Dd];                // residual stream hi
__device__ bf16 g_xl[Nn * Dd];
__device__ bf16 g_wh[DFF * Dd];               // W hi (max 2048x256)
__device__ bf16 g_wl[DFF * Dd];
__device__ bf16 g_qh[Nn * 3 * Dd];            // qkv hi
__device__ bf16 g_ql[Nn * 3 * Dd];
__device__ bf16 g_vth[64 * 32 * 1024];        // V transposed hi: [z][d][k]
__device__ bf16 g_vtl[64 * 32 * 1024];

// ------------------------- helpers -------------------------
__device__ __forceinline__ uint32_t smem_u32(const void* p) {
    uint32_t a;
    asm("{ .reg .u64 t; cvta.to.shared.u64 t, %1; cvt.u32.u64 %0, t; }" : "=r"(a) : "l"(p));
    return a;
}
__device__ __forceinline__ void cp16(uint32_t s, const void* g) {
    asm volatile("cp.async.cg.shared.global [%0], [%1], 16;" :: "r"(s), "l"(g));
}
__device__ __forceinline__ void cp_commit() {
    asm volatile("cp.async.commit_group;" ::: "memory");
}
__device__ __forceinline__ void cp_wait0() {
    asm volatile("cp.async.wait_group 0;" ::: "memory");
}
__device__ __forceinline__ void cp_wait1() {
    asm volatile("cp.async.wait_group 1;" ::: "memory");
}
__device__ __forceinline__ void ldm4(uint32_t* r, uint32_t addr) {
    asm volatile("ldmatrix.sync.aligned.m8n8.x4.shared.b16 {%0,%1,%2,%3}, [%4];"
        : "=r"(r[0]), "=r"(r[1]), "=r"(r[2]), "=r"(r[3]) : "r"(addr));
}
__device__ __forceinline__ void mma16816(float* d, const uint32_t* a, const uint32_t* b) {
    asm volatile(
        "mma.sync.aligned.m16n8k16.row.col.f32.bf16.bf16.f32 "
        "{%0,%1,%2,%3}, {%4,%5,%6,%7}, {%8,%9}, {%0,%1,%2,%3};"
        : "+f"(d[0]), "+f"(d[1]), "+f"(d[2]), "+f"(d[3])
        : "r"(a[0]), "r"(a[1]), "r"(a[2]), "r"(a[3]), "r"(b[0]), "r"(b[1]));
}
__device__ __forceinline__ float warpSum(float v) {
    #pragma unroll
    for (int o = 16; o > 0; o >>= 1) v += __shfl_xor_sync(0xffffffffu, v, o);
    return v;
}
// pack two fp32 into bf16x2 hi reg, residual into lo reg
__device__ __forceinline__ uint32_t pk2(float a, float b, uint32_t& lo) {
    bf16 ha = __float2bfloat16(a), hb = __float2bfloat16(b);
    bf16 la = __float2bfloat16(a - __bfloat162float(ha));
    bf16 lb = __float2bfloat16(b - __bfloat162float(hb));
    lo = ((uint32_t)__bfloat16_as_ushort(lb) << 16) | __bfloat16_as_ushort(la);
    return ((uint32_t)__bfloat16_as_ushort(hb) << 16) | __bfloat16_as_ushort(ha);
}

// ------------------------- fp32 -> bf16 hi/lo conversion -------------------------
__global__ void cvt_hilo(const float* __restrict__ in, bf16* __restrict__ hi,
                         bf16* __restrict__ lo, int n4)
{
    int i = blockIdx.x * 256 + threadIdx.x;
    if (i >= n4) return;
    float4 x = ((const float4*)in)[i];
    float xs[4] = {x.x, x.y, x.z, x.w};
    bf16 h[4], l[4];
    #pragma unroll
    for (int j = 0; j < 4; j++) {
        h[j] = __float2bfloat16(xs[j]);
        l[j] = __float2bfloat16(xs[j] - __bfloat162float(h[j]));
    }
    ((__nv_bfloat162*)hi)[2 * i]     = __nv_bfloat162(h[0], h[1]);
    ((__nv_bfloat162*)hi)[2 * i + 1] = __nv_bfloat162(h[2], h[3]);
    ((__nv_bfloat162*)lo)[2 * i]     = __nv_bfloat162(l[0], l[1]);
    ((__nv_bfloat162*)lo)[2 * i + 1] = __nv_bfloat162(l[2], l[3]);
}

// V^T gather (hi/lo already split):  vt[z][d][k] = qkv_hl[b*1024+k][512 + h*32 + d]
__global__ void cvt_vt(const bf16* __restrict__ qh, const bf16* __restrict__ ql,
                       bf16* __restrict__ vth, bf16* __restrict__ vtl)
{
    int i = blockIdx.x * 256 + threadIdx.x;           // 64*32*1024 = 2M
    int k = i & 1023, d = (i >> 10) & 31, z = i >> 15;
    int b = z >> 3, h = z & 7;
    size_t src = (size_t)(b * 1024 + k) * 768 + 512 + h * 32 + d;
    vth[i] = qh[src];
    vtl[i] = ql[src];
}

// ------------------------- CSR build (once; edges constant across layers) -------------------------
__global__ void csr_init() {
    int i = blockIdx.x * 256 + threadIdx.x;
    if (i < Nn) g_cnt[i] = 1;                 // self loop
}
__global__ void csr_count(const int* __restrict__ ei, int E) {
    int i = blockIdx.x * 256 + threadIdx.x;
    if (i < E) atomicAdd(&g_cnt[ei[E + i]], 1);
}
__global__ void csr_scan() {                  // single block, 1024 threads
    __shared__ int sdata[1024];
    int tid = threadIdx.x;
    int base = tid * 8;
    int loc[8];
    int s = 0;
    #pragma unroll
    for (int j = 0; j < 8; j++) { loc[j] = g_cnt[base + j]; s += loc[j]; }
    sdata[tid] = s;
    __syncthreads();
    for (int off = 1; off < 1024; off <<= 1) {
        int v = (tid >= off) ? sdata[tid - off] : 0;
        __syncthreads();
        sdata[tid] += v;
        __syncthreads();
    }
    int run = sdata[tid] - s;                 // exclusive prefix
    #pragma unroll
    for (int j = 0; j < 8; j++) {
        g_rowptr[base + j] = run;
        g_wpos[base + j] = run;
        run += loc[j];
    }
    if (tid == 1023) g_rowptr[Nn] = run;
}
__global__ void csr_fill(const int* __restrict__ ei, int E, int Etot) {
    int i = blockIdx.x * 256 + threadIdx.x;
    if (i >= Etot) return;
    int s, d;
    if (i < E) { s = ei[i]; d = ei[E + i]; } else { s = d = i - E; }
    int pos = atomicAdd(&g_wpos[d], 1);
    g_col[pos] = s;
}

// ------------------------- HMMA split-bf16 GEMM -------------------------
// C[M,N] = A[M,K] @ W[N,K]^T (+bias)(+relu). grid (N/128, M/128), 256 thr.
// OUT=0: fp32 C.  OUT=1: bf16 hi/lo (Ch, Cl).
template<int OUT>
__global__ void __launch_bounds__(256, 1)
hgemm(const bf16* __restrict__ aH, const bf16* __restrict__ aL, int lda,
      const bf16* __restrict__ bH, const bf16* __restrict__ bL, int ldb,
      const float* __restrict__ bias, float* __restrict__ C,
      bf16* __restrict__ Ch, bf16* __restrict__ Cl, int ldc,
      int K, int relu)
{
    constexpr int WM = 64, WN = 32, MT = 4, NT8 = 4;
    constexpr int SST = 40;
    constexpr int ATILE = 128 * SST;
    constexpr int BTILE = 128 * SST;
    constexpr int STAGE = 2 * ATILE + 2 * BTILE;

    extern __shared__ bf16 sm[];

    int tid = threadIdx.x;
    int wid = tid >> 5, lane = tid & 31;
    int wm = wid % 2, wn = wid / 2;
    int m0 = blockIdx.y * 128;
    int n0 = blockIdx.x * 128;

    float acc[MT][NT8][4] = {};
    int P = K >> 5;

    auto load_panel = [&](int p, int s) {
        bf16* Ah = sm + s * STAGE;
        bf16* Al = Ah + ATILE;
        bf16* Bh = Al + ATILE;
        bf16* Bl = Bh + BTILE;
        int k0 = p * 32;
        #pragma unroll 2
        for (int idx = tid; idx < 512; idx += 256) {
            int r = idx >> 2, c = idx & 3;
            size_t g = (size_t)(m0 + r) * lda + k0 + c * 8;
            cp16(smem_u32(Ah + r * SST + c * 8), aH + g);
            cp16(smem_u32(Al + r * SST + c * 8), aL + g);
        }
        #pragma unroll 2
        for (int idx = tid; idx < 512; idx += 256) {
            int r = idx >> 2, c = idx & 3;
            size_t g = (size_t)(n0 + r) * ldb + k0 + c * 8;
            cp16(smem_u32(Bh + r * SST + c * 8), bH + g);
            cp16(smem_u32(Bl + r * SST + c * 8), bL + g);
        }
        cp_commit();
    };

    int t8 = lane >> 3;
    int rA = (t8 & 1) * 8 + (lane & 7), cA = (t8 >> 1) * 8;
    int rB = (t8 >> 1) * 8 + (lane & 7), cB = (t8 & 1) * 8;

    auto compute = [&](int s) {
        bf16* Ah = sm + s * STAGE;
        bf16* Al = Ah + ATILE;
        bf16* Bh = Al + ATILE;
        bf16* Bl = Bh + BTILE;
        #pragma unroll
        for (int kk = 0; kk < 2; kk++) {
            int k16 = kk * 16;
            uint32_t ah[MT][4], al[MT][4], bh[NT8][2], bl[NT8][2];
            #pragma unroll
            for (int mt = 0; mt < MT; mt++) {
                int row = wm * WM + mt * 16 + rA;
                ldm4(ah[mt], smem_u32(Ah + row * SST + k16 + cA));
                ldm4(al[mt], smem_u32(Al + row * SST + k16 + cA));
            }
            #pragma unroll
            for (int nt2 = 0; nt2 < NT8 / 2; nt2++) {
                int row = wn * WN + nt2 * 16 + rB;
                uint32_t r4[4];
                ldm4(r4, smem_u32(Bh + row * SST + k16 + cB));
                bh[2 * nt2][0] = r4[0]; bh[2 * nt2][1] = r4[1];
                bh[2 * nt2 + 1][0] = r4[2]; bh[2 * nt2 + 1][1] = r4[3];
                ldm4(r4, smem_u32(Bl + row * SST + k16 + cB));
                bl[2 * nt2][0] = r4[0]; bl[2 * nt2][1] = r4[1];
                bl[2 * nt2 + 1][0] = r4[2]; bl[2 * nt2 + 1][1] = r4[3];
            }
            #pragma unroll
            for (int mt = 0; mt < MT; mt++) {
                #pragma unroll
                for (int nt = 0; nt < NT8; nt++) {
                    mma16816(acc[mt][nt], ah[mt], bh[nt]);
                    mma16816(acc[mt][nt], ah[mt], bl[nt]);
                    mma16816(acc[mt][nt], al[mt], bh[nt]);
                }
            }
        }
    };

    load_panel(0, 0);
    for (int p = 0; p < P; p++) {
        if (p + 1 < P) {
            load_panel(p + 1, (p + 1) & 1);
            cp_wait1();
        } else {
            cp_wait0();
        }
        __syncthreads();
        compute(p & 1);
        __syncthreads();
    }

    int grp = lane >> 2, q4 = lane & 3;
    #pragma unroll
    for (int mt = 0; mt < MT; mt++) {
        #pragma unroll
        for (int nt = 0; nt < NT8; nt++) {
            int row = m0 + wm * WM + mt * 16 + grp;
            int col = n0 + wn * WN + nt * 8 + q4 * 2;
            float* a4 = acc[mt][nt];
            float b0 = 0.0f, b1 = 0.0f;
            if (bias) { b0 = bias[col]; b1 = bias[col + 1]; }
            float v0 = a4[0] + b0, v1 = a4[1] + b1;
            float v2 = a4[2] + b0, v3 = a4[3] + b1;
            if (relu) {
                v0 = fmaxf(v0, 0.0f); v1 = fmaxf(v1, 0.0f);
                v2 = fmaxf(v2, 0.0f); v3 = fmaxf(v3, 0.0f);
            }
            if (OUT == 0) {
                *(float2*)&C[(size_t)row * ldc + col]       = make_float2(v0, v1);
                *(float2*)&C[(size_t)(row + 8) * ldc + col] = make_float2(v2, v3);
            } else {
                uint32_t lo0, lo1;
                uint32_t h0 = pk2(v0, v1, lo0);
                uint32_t h1 = pk2(v2, v3, lo1);
                *(uint32_t*)&Ch[(size_t)row * ldc + col]       = h0;
                *(uint32_t*)&Cl[(size_t)row * ldc + col]       = lo0;
                *(uint32_t*)&Ch[(size_t)(row + 8) * ldc + col] = h1;
                *(uint32_t*)&Cl[(size_t)(row + 8) * ldc + col] = lo1;
            }
        }
    }
}

// ------------------------- fused flash attention -------------------------
__global__ void __launch_bounds__(256, 1)
flash_attn(const bf16* __restrict__ qkh, const bf16* __restrict__ qkl,
           const bf16* __restrict__ vth, const bf16* __restrict__ vtl,
           bf16* __restrict__ Oh, bf16* __restrict__ Ol, float scale)
{
    constexpr int QST = 40, VST = 136;
    constexpr int KBUF = 2 * 128 * QST + 2 * 32 * VST;  // elems
    extern __shared__ bf16 fsm[];
    bf16* sQh = fsm;
    bf16* sQl = sQh + 128 * QST;
    bf16* sK  = sQl + 128 * QST;

    int tid = threadIdx.x, wid = tid >> 5, lane = tid & 31;
    int z = blockIdx.y, b = z >> 3, h = z & 7;
    int q0 = blockIdx.x * 128;

    const bf16* Qh = qkh + (size_t)b * 1024 * 768 + h * 32;
    const bf16* Ql = qkl + (size_t)b * 1024 * 768 + h * 32;
    const bf16* Kh = Qh + 256;
    const bf16* Kl = Ql + 256;
    const bf16* Vh = vth + (size_t)z * 32 * 1024;
    const bf16* Vl = vtl + (size_t)z * 32 * 1024;

    for (int idx = tid; idx < 512; idx += 256) {
        int r = idx >> 2, c = idx & 3;
        cp16(smem_u32(sQh + r * QST + c * 8), Qh + (size_t)(q0 + r) * 768 + c * 8);
        cp16(smem_u32(sQl + r * QST + c * 8), Ql + (size_t)(q0 + r) * 768 + c * 8);
    }
    auto load_chunk = [&](int p, int s) {
        bf16* kh = sK + s * KBUF;
        bf16* kl = kh + 128 * QST;
        bf16* vh = kl + 128 * QST;
        bf16* vl = vh + 32 * VST;
        int k0 = p * 128;
        #pragma unroll 2
        for (int idx = tid; idx < 512; idx += 256) {
            int r = idx >> 2, c = idx & 3;
            cp16(smem_u32(kh + r * QST + c * 8), Kh + (size_t)(k0 + r) * 768 + c * 8);
            cp16(smem_u32(kl + r * QST + c * 8), Kl + (size_t)(k0 + r) * 768 + c * 8);
        }
        #pragma unroll 2
        for (int idx = tid; idx < 512; idx += 256) {
            int r = idx >> 4, c = idx & 15;
            cp16(smem_u32(vh + r * VST + c * 8), Vh + (size_t)r * 1024 + k0 + c * 8);
            cp16(smem_u32(vl + r * VST + c * 8), Vl + (size_t)r * 1024 + k0 + c * 8);
        }
        cp_commit();
    };

    int t8 = lane >> 3;
    int rA = (t8 & 1) * 8 + (lane & 7), cA = (t8 >> 1) * 8;
    int rB = (t8 >> 1) * 8 + (lane & 7), cB = (t8 & 1) * 8;
    int grp = lane >> 2, q4 = lane & 3;

    float oacc[4][4] = {};
    float m0 = -1e30f, m1 = -1e30f, l0 = 0.0f, l1 = 0.0f;
    uint32_t qfh[2][4], qfl[2][4];

    load_chunk(0, 0);
    for (int p = 0; p < 8; p++) {
        if (p < 7) { load_chunk(p + 1, (p + 1) & 1); cp_wait1(); }
        else cp_wait0();
        __syncthreads();
        if (p == 0) {
            #pragma unroll
            for (int kk = 0; kk < 2; kk++) {
                ldm4(qfh[kk], smem_u32(sQh + (wid * 16 + rA) * QST + kk * 16 + cA));
                ldm4(qfl[kk], smem_u32(sQl + (wid * 16 + rA) * QST + kk * 16 + cA));
            }
        }
        bf16* kh = sK + (p & 1) * KBUF;
        bf16* kl = kh + 128 * QST;
        bf16* vh = kl + 128 * QST;
        bf16* vl = vh + 32 * VST;

        float sacc[16][4];
        #pragma unroll
        for (int t = 0; t < 16; t++) { sacc[t][0] = 0; sacc[t][1] = 0; sacc[t][2] = 0; sacc[t][3] = 0; }
        #pragma unroll
        for (int nt2 = 0; nt2 < 8; nt2++) {
            #pragma unroll
            for (int kk = 0; kk < 2; kk++) {
                uint32_t bh4[4], bl4[4];
                ldm4(bh4, smem_u32(kh + (nt2 * 16 + rB) * QST + kk * 16 + cB));
                ldm4(bl4, smem_u32(kl + (nt2 * 16 + rB) * QST + kk * 16 + cB));
                #pragma unroll
                for (int hf = 0; hf < 2; hf++) {
                    mma16816(sacc[2 * nt2 + hf], qfh[kk], &bh4[2 * hf]);
                    mma16816(sacc[2 * nt2 + hf], qfh[kk], &bl4[2 * hf]);
                    mma16816(sacc[2 * nt2 + hf], qfl[kk], &bh4[2 * hf]);
                }
            }
        }
        float cm0 = -1e30f, cm1 = -1e30f;
        #pragma unroll
        for (int t = 0; t < 16; t++) {
            sacc[t][0] *= scale; sacc[t][1] *= scale;
            sacc[t][2] *= scale; sacc[t][3] *= scale;
            cm0 = fmaxf(cm0, fmaxf(sacc[t][0], sacc[t][1]));
            cm1 = fmaxf(cm1, fmaxf(sacc[t][2], sacc[t][3]));
        }
        cm0 = fmaxf(cm0, __shfl_xor_sync(0xffffffffu, cm0, 1));
        cm0 = fmaxf(cm0, __shfl_xor_sync(0xffffffffu, cm0, 2));
        cm1 = fmaxf(cm1, __shfl_xor_sync(0xffffffffu, cm1, 1));
        cm1 = fmaxf(cm1, __shfl_xor_sync(0xffffffffu, cm1, 2));
        float mn0 = fmaxf(m0, cm0), mn1 = fmaxf(m1, cm1);
        float c0 = __expf(m0 - mn0), c1 = __expf(m1 - mn1);
        m0 = mn0; m1 = mn1;
        float rs0 = 0.0f, rs1 = 0.0f;
        #pragma unroll
        for (int t = 0; t < 16; t++) {
            sacc[t][0] = __expf(sacc[t][0] - mn0);
            sacc[t][1] = __expf(sacc[t][1] - mn0);
            sacc[t][2] = __expf(sacc[t][2] - mn1);
            sacc[t][3] = __expf(sacc[t][3] - mn1);
            rs0 += sacc[t][0] + sacc[t][1];
            rs1 += sacc[t][2] + sacc[t][3];
        }
        l0 = l0 * c0 + rs0;
        l1 = l1 * c1 + rs1;
        #pragma unroll
        for (int n = 0; n < 4; n++) {
            oacc[n][0] *= c0; oacc[n][1] *= c0;
            oacc[n][2] *= c1; oacc[n][3] *= c1;
        }
        #pragma unroll
        for (int kt = 0; kt < 8; kt++) {
            uint32_t pah4[4], pal4[4];
            pah4[0] = pk2(sacc[2 * kt][0],     sacc[2 * kt][1],     pal4[0]);
            pah4[1] = pk2(sacc[2 * kt][2],     sacc[2 * kt][3],     pal4[1]);
            pah4[2] = pk2(sacc[2 * kt + 1][0], sacc[2 * kt + 1][1], pal4[2]);
            pah4[3] = pk2(sacc[2 * kt + 1][2], sacc[2 * kt + 1][3], pal4[3]);
            #pragma unroll
            for (int np = 0; np < 2; np++) {
                uint32_t vb_h[4], vb_l[4];
                ldm4(vb_h, smem_u32(vh + (np * 16 + rB) * VST + kt * 16 + cB));
                ldm4(vb_l, smem_u32(vl + (np * 16 + rB) * VST + kt * 16 + cB));
                #pragma unroll
                for (int hf = 0; hf < 2; hf++) {
                    mma16816(oacc[2 * np + hf], pah4, &vb_h[2 * hf]);
                    mma16816(oacc[2 * np + hf], pah4, &vb_l[2 * hf]);
                    mma16816(oacc[2 * np + hf], pal4, &vb_h[2 * hf]);
                }
            }
        }
        __syncthreads();
    }
    l0 += __shfl_xor_sync(0xffffffffu, l0, 1);
    l0 += __shfl_xor_sync(0xffffffffu, l0, 2);
    l1 += __shfl_xor_sync(0xffffffffu, l1, 1);
    l1 += __shfl_xor_sync(0xffffffffu, l1, 2);
    float i0 = 1.0f / l0, i1 = 1.0f / l1;
    size_t obase = (size_t)(b * 1024 + q0) * 256 + h * 32;
    #pragma unroll
    for (int n = 0; n < 4; n++) {
        int row = wid * 16 + grp;
        int col = n * 8 + q4 * 2;
        uint32_t lo0, lo1;
        uint32_t h0 = pk2(oacc[n][0] * i0, oacc[n][1] * i0, lo0);
        uint32_t h1 = pk2(oacc[n][2] * i1, oacc[n][3] * i1, lo1);
        *(uint32_t*)&Oh[obase + (size_t)row * 256 + col]       = h0;
        *(uint32_t*)&Ol[obase + (size_t)row * 256 + col]       = lo0;
        *(uint32_t*)&Oh[obase + (size_t)(row + 8) * 256 + col] = h1;
        *(uint32_t*)&Ol[obase + (size_t)(row + 8) * 256 + col] = lo1;
    }
}

// ------------------------- GAT pieces -------------------------
__global__ void att_prep(const float* __restrict__ hbuf,
                         const float* __restrict__ atts, const float* __restrict__ attd)
{
    int t = blockIdx.x * 256 + threadIdx.x;
    if (t >= Nn * Hh) return;
    int n = t >> 3, hd = t & 7;
    const float* hp = hbuf + (size_t)n * Dd + hd * Cc;
    const float* pa = atts + hd * Cc;
    const float* pb = attd + hd * Cc;
    float s1 = 0.0f, s2 = 0.0f;
    #pragma unroll
    for (int c = 0; c < Cc; c++) {
        float hv = hp[c];
        s1 += hv * pa[c];
        s2 += hv * pb[c];
    }
    g_as[t] = s1;
    g_ad[t] = s2;
}

// fused per-dst GAT aggregation: softmax over incident edges + gather + bias + relu,
// emits fp32 and bf16 hi/lo.  One warp per dst node.  grid = Nn/8, 256 threads.
__global__ void __launch_bounds__(256)
gat_aggr(const float* __restrict__ hbuf, const float* __restrict__ bias,
         float* __restrict__ outF, bf16* __restrict__ outH, bf16* __restrict__ outL)
{
    int wid = threadIdx.x >> 5, lane = threadIdx.x & 31;
    int d = blockIdx.x * 8 + wid;
    int base = g_rowptr[d];
    int deg  = g_rowptr[d + 1] - base;

    // ---- phase A/B: per-head max and exp-sum (head = lane&7, slot = lane>>3) ----
    int hd = lane & 7;
    float adv = g_ad[d * 8 + hd];
    float m = -1e30f;
    for (int i = lane >> 3; i < deg; i += 4) {
        int s = g_col[base + i];
        float v = g_as[s * 8 + hd] + adv;
        v = v > 0.0f ? v : 0.2f * v;
        m = fmaxf(m, v);
    }
    m = fmaxf(m, __shfl_xor_sync(0xffffffffu, m, 8));
    m = fmaxf(m, __shfl_xor_sync(0xffffffffu, m, 16));
    float sum = 0.0f;
    for (int i = lane >> 3; i < deg; i += 4) {
        int s = g_col[base + i];
        float v = g_as[s * 8 + hd] + adv;
        v = v > 0.0f ? v : 0.2f * v;
        sum += __expf(v - m);
    }
    sum += __shfl_xor_sync(0xffffffffu, sum, 8);
    sum += __shfl_xor_sync(0xffffffffu, sum, 16);

    // ---- phase C: aggregate; lane covers cols [lane*8, lane*8+8), head = lane>>2 ----
    int hd2 = lane >> 2;
    float m2  = __shfl_sync(0xffffffffu, m, hd2);
    float is2 = 1.0f / __shfl_sync(0xffffffffu, sum, hd2);
    float adv2 = g_ad[d * 8 + hd2];
    float acc[8] = {};
    for (int i = 0; i < deg; i++) {
        int s = g_col[base + i];
        float v = g_as[s * 8 + hd2] + adv2;
        v = v > 0.0f ? v : 0.2f * v;
        float alpha = __expf(v - m2) * is2;
        const float4* hp = (const float4*)(hbuf + (size_t)s * Dd + lane * 8);
        float4 a = hp[0], b2 = hp[1];
        acc[0] += alpha * a.x;  acc[1] += alpha * a.y;
        acc[2] += alpha * a.z;  acc[3] += alpha * a.w;
        acc[4] += alpha * b2.x; acc[5] += alpha * b2.y;
        acc[6] += alpha * b2.z; acc[7] += alpha * b2.w;
    }
    size_t rb = (size_t)d * Dd + lane * 8;
    #pragma unroll
    for (int j = 0; j < 8; j += 2) {
        float v0 = fmaxf(acc[j]     + bias[lane * 8 + j],     0.0f);
        float v1 = fmaxf(acc[j + 1] + bias[lane * 8 + j + 1], 0.0f);
        *(float2*)&outF[rb + j] = make_float2(v0, v1);
        uint32_t lo;
        uint32_t hi = pk2(v0, v1, lo);
        *(uint32_t*)&outH[rb + j] = hi;
        *(uint32_t*)&outL[rb + j] = lo;
    }
}

// ------------------------- residual + layernorm (emits fp32 + bf16 hi/lo) -------------------------
__global__ void ln_res(const float* __restrict__ xin, const float* __restrict__ add,
                       float* __restrict__ xout, const float* __restrict__ w,
                       const float* __restrict__ b,
                       bf16* __restrict__ oh, bf16* __restrict__ ol)
{
    int row = blockIdx.x * 8 + (threadIdx.x >> 5);
    int lane = threadIdx.x & 31;
    const float* xr = xin + (size_t)row * Dd;
    const float* ar = add + (size_t)row * Dd;
    float v[8];
    float s = 0.0f;
    #pragma unroll
    for (int j = 0; j < 8; j++) {
        int d = lane + j * 32;
        v[j] = xr[d] + ar[d];
        s += v[j];
    }
    s = warpSum(s);
    float mean = s * (1.0f / 256.0f);
    float var = 0.0f;
    #pragma unroll
    for (int j = 0; j < 8; j++) {
        float dv = v[j] - mean;
        var += dv * dv;
    }
    var = warpSum(var) * (1.0f / 256.0f);
    float inv = rsqrtf(var + 1e-5f);
    float* orow = xout + (size_t)row * Dd;
    #pragma unroll
    for (int j = 0; j < 8; j++) {
        int d = lane + j * 32;
        float o = (v[j] - mean) * inv * w[d] + b[d];
        orow[d] = o;
        bf16 h = __float2bfloat16(o);
        oh[(size_t)row * Dd + d] = h;
        ol[(size_t)row * Dd + d] = __float2bfloat16(o - __bfloat162float(h));
    }
}

// ------------------------- prediction head -------------------------
__global__ void pred_kernel(const float* __restrict__ xin, const float* __restrict__ pw,
                            const float* __restrict__ pb, float* __restrict__ out)
{
    int gw = (blockIdx.x * 256 + threadIdx.x) >> 5;
    int lane = threadIdx.x & 31;
    if (gw >= Nn) return;
    const float* xr = xin + (size_t)gw * Dd;
    float a0 = 0.0f, a1 = 0.0f, a2 = 0.0f;
    #pragma unroll
    for (int j = 0; j < 8; j++) {
        int d = lane + j * 32;
        float xv = xr[d];
        a0 += xv * pw[d];
        a1 += xv * pw[Dd + d];
        a2 += xv * pw[2 * Dd + d];
    }
    a0 = warpSum(a0);
    a1 = warpSum(a1);
    a2 = warpSum(a2);
    if (lane == 0) {
        out[gw * 3 + 0] = a0 + pb[0];
        out[gw * 3 + 1] = a1 + pb[1];
        out[gw * 3 + 2] = a2 + pb[2];
    }
}

// ------------------------- host orchestration -------------------------
#define SMEM_G (4 * 128 * 40 * 2 * 2)                       // 81920 B
#define SMEM_F ((2 * 128 * 40 + 2 * (2 * 128 * 40 + 2 * 32 * 136)) * 2)  // 96256 B

extern "C" void kernel_launch(void* const* d_in, const int* in_sizes, int n_in,
                              void* d_out, int out_size)
{
    const float* x      = (const float*)d_in[0];
    const int*   ei     = (const int*)d_in[1];
    const float* W0     = (const float*)d_in[3];
    const float* W12    = (const float*)d_in[4];
    const float* att_s  = (const float*)d_in[5];
    const float* att_d  = (const float*)d_in[6];
    const float* gbias  = (const float*)d_in[7];
    const float* qkv_w  = (const float*)d_in[8];
    const float* qkv_b  = (const float*)d_in[9];
    const float* out_w  = (const float*)d_in[10];
    const float* out_b  = (const float*)d_in[11];
    const float* ln1w   = (const float*)d_in[12];
    const float* ln1b   = (const float*)d_in[13];
    const float* ln2w   = (const float*)d_in[14];
    const float* ln2b   = (const float*)d_in[15];
    const float* ff1w   = (const float*)d_in[16];
    const float* ff1b   = (const float*)d_in[17];
    const float* ff2w   = (const float*)d_in[18];
    const float* ff2b   = (const float*)d_in[19];
    const float* predw  = (const float*)d_in[20];
    const float* predb  = (const float*)d_in[21];
    float* out = (float*)d_out;

    int E = in_sizes[1] / 2;
    int Etot = E + Nn;

    cudaFuncSetAttribute((const void*)hgemm<0>, cudaFuncAttributeMaxDynamicSharedMemorySize, SMEM_G);
    cudaFuncSetAttribute((const void*)hgemm<1>, cudaFuncAttributeMaxDynamicSharedMemorySize, SMEM_G);
    cudaFuncSetAttribute((const void*)flash_attn, cudaFuncAttributeMaxDynamicSharedMemorySize, SMEM_F);

    float *ph, *px;
    bf16 *pah, *pal, *pxh, *pxl, *pwh, *pwl, *pqh, *pql, *pvth, *pvtl;
    cudaGetSymbolAddress((void**)&ph,    g_h);
    cudaGetSymbolAddress((void**)&px,    g_x);
    cudaGetSymbolAddress((void**)&pah,   g_ah);
    cudaGetSymbolAddress((void**)&pal,   g_al);
    cudaGetSymbolAddress((void**)&pxh,   g_xh);
    cudaGetSymbolAddress((void**)&pxl,   g_xl);
    cudaGetSymbolAddress((void**)&pwh,   g_wh);
    cudaGetSymbolAddress((void**)&pwl,   g_wl);
    cudaGetSymbolAddress((void**)&pqh,   g_qh);
    cudaGetSymbolAddress((void**)&pql,   g_ql);
    cudaGetSymbolAddress((void**)&pvth,  g_vth);
    cudaGetSymbolAddress((void**)&pvtl,  g_vtl);

    // ---------------- CSR build (once) ----------------
    csr_init<<<Nn / 256, 256>>>();
    csr_count<<<(E + 255) / 256, 256>>>(ei, E);
    csr_scan<<<1, 1024>>>();
    csr_fill<<<(Etot + 255) / 256, 256>>>(ei, E, Etot);

    // ---------------- GAT layers ----------------
    cvt_hilo<<<(Nn * 64 / 4 + 255) / 256, 256>>>(x, pxh, pxl, Nn * 64 / 4);
    int curK = 64;
    for (int l = 0; l < 3; l++) {
        const float* W = (l == 0) ? W0 : (W12 + (size_t)(l - 1) * Dd * Dd);
        cvt_hilo<<<(Dd * curK / 4 + 255) / 256, 256>>>(W, pwh, pwl, Dd * curK / 4);
        hgemm<0><<<dim3(Dd / 128, Nn / 128), 256, SMEM_G>>>(
            pxh, pxl, curK, pwh, pwl, curK, nullptr, ph, nullptr, nullptr, Dd, curK, 0);
        att_prep<<<(Nn * Hh + 255) / 256, 256>>>(ph, att_s + l * Dd, att_d + l * Dd);
        gat_aggr<<<Nn / 8, 256>>>(ph, gbias + l * Dd, px, pxh, pxl);
        curK = Dd;
    }
    // fp32 features in g_x; hi/lo in pxh/pxl

    // ---------------- transformer layers ----------------
    const float scale = 0.17677669529663687f;  // 1/sqrt(32)
    for (int i = 0; i < 2; i++) {
        cvt_hilo<<<(768 * Dd / 4 + 255) / 256, 256>>>(qkv_w + (size_t)i * 768 * Dd, pwh, pwl, 768 * Dd / 4);
        hgemm<1><<<dim3(768 / 128, Nn / 128), 256, SMEM_G>>>(
            pxh, pxl, Dd, pwh, pwl, Dd, qkv_b + i * 768, nullptr, pqh, pql, 768, Dd, 0);
        cvt_vt<<<(64 * 32 * 1024) / 256, 256>>>(pqh, pql, pvth, pvtl);
        flash_attn<<<dim3(8, 64), 256, SMEM_F>>>(pqh, pql, pvth, pvtl, pah, pal, scale);
        cvt_hilo<<<(Dd * Dd / 4 + 255) / 256, 256>>>(out_w + (size_t)i * Dd * Dd, pwh, pwl, Dd * Dd / 4);
        hgemm<0><<<dim3(Dd / 128, Nn / 128), 256, SMEM_G>>>(
            pah, pal, Dd, pwh, pwl, Dd, out_b + i * Dd, ph, nullptr, nullptr, Dd, Dd, 0);
        ln_res<<<Nn / 8, 256>>>(px, ph, px, ln1w + i * Dd, ln1b + i * Dd, pxh, pxl);
        cvt_hilo<<<(DFF * Dd / 4 + 255) / 256, 256>>>(ff1w + (size_t)i * DFF * Dd, pwh, pwl, DFF * Dd / 4);
        hgemm<1><<<dim3(DFF / 128, Nn / 128), 256, SMEM_G>>>(
            pxh, pxl, Dd, pwh, pwl, Dd, ff1b + i * DFF, nullptr, pah, pal, DFF, Dd, 1);
        cvt_hilo<<<(Dd * DFF / 4 + 255) / 256, 256>>>(ff2w + (size_t)i * Dd * DFF, pwh, pwl, Dd * DFF / 4);
        hgemm<0><<<dim3(Dd / 128, Nn / 128), 256, SMEM_G>>>(
            pah, pal, DFF, pwh, pwl, DFF, ff2b + i * Dd, ph, nullptr, nullptr, Dd, DFF, 0);
        ln_res<<<Nn / 8, 256>>>(px, ph, px, ln2w + i * Dd, ln2b + i * Dd, pxh, pxl);
    }

    // ---------------- prediction head ----------------
    pred_kernel<<<(Nn * 32 + 255) / 256, 256>>>(px, predw, predb, out);
}

// round 6
// speedup vs baseline: 2.7737x; 1.0599x over previous
#include <cuda_runtime.h>
#include <cuda_bf16.h>
#include <math.h>
#include <stdint.h>

using bf16 = __nv_bfloat16;

#define Nn   8192
#define Bb   8
#define Ll   1024
#define Hh   8
#define Cc   32
#define Dd   256
#define DFF  2048
#define Emax 262144
#define ETOTmax (Emax + Nn)

// ------------------------- scratch (static device globals) -------------------------
__device__ float    g_h   [Nn * Dd];
__device__ float    g_x   [Nn * Dd];
__device__ float    g_as  [Nn * Hh];
__device__ float    g_ad  [Nn * Hh];
__device__ int      g_cnt [Nn];
__device__ int      g_rowptr[Nn + 1];
__device__ int      g_wpos[Nn];
__device__ int      g_col [ETOTmax];

__device__ bf16 g_ah[Nn * DFF];               // A hi (max 8192x2048)
__device__ bf16 g_al[Nn * DFF];               // A lo
__device__ bf16 g_xh[Nn * Dd];                // residual stream hi
__device__ bf16 g_xl[Nn * Dd];
__device__ bf16 g_wh[DFF * Dd];               // W hi (max 2048x256)
__device__ bf16 g_wl[DFF * Dd];
__device__ bf16 g_qh[Nn * 3 * Dd];            // qkv hi
__device__ bf16 g_ql[Nn * 3 * Dd];
__device__ bf16 g_vth[64 * 32 * 1024];        // V transposed hi: [z][d][k]
__device__ bf16 g_vtl[64 * 32 * 1024];

// ------------------------- helpers -------------------------
__device__ __forceinline__ uint32_t smem_u32(const void* p) {
    uint32_t a;
    asm("{ .reg .u64 t; cvta.to.shared.u64 t, %1; cvt.u32.u64 %0, t; }" : "=r"(a) : "l"(p));
    return a;
}
__device__ __forceinline__ void cp16(uint32_t s, const void* g) {
    asm volatile("cp.async.cg.shared.global [%0], [%1], 16;" :: "r"(s), "l"(g));
}
__device__ __forceinline__ void cp_commit() {
    asm volatile("cp.async.commit_group;" ::: "memory");
}
__device__ __forceinline__ void cp_wait0() {
    asm volatile("cp.async.wait_group 0;" ::: "memory");
}
__device__ __forceinline__ void cp_wait1() {
    asm volatile("cp.async.wait_group 1;" ::: "memory");
}
__device__ __forceinline__ void ldm4(uint32_t* r, uint32_t addr) {
    asm volatile("ldmatrix.sync.aligned.m8n8.x4.shared.b16 {%0,%1,%2,%3}, [%4];"
        : "=r"(r[0]), "=r"(r[1]), "=r"(r[2]), "=r"(r[3]) : "r"(addr));
}
__device__ __forceinline__ void mma16816(float* d, const uint32_t* a, const uint32_t* b) {
    asm volatile(
        "mma.sync.aligned.m16n8k16.row.col.f32.bf16.bf16.f32 "
        "{%0,%1,%2,%3}, {%4,%5,%6,%7}, {%8,%9}, {%0,%1,%2,%3};"
        : "+f"(d[0]), "+f"(d[1]), "+f"(d[2]), "+f"(d[3])
        : "r"(a[0]), "r"(a[1]), "r"(a[2]), "r"(a[3]), "r"(b[0]), "r"(b[1]));
}
__device__ __forceinline__ float warpSum(float v) {
    #pragma unroll
    for (int o = 16; o > 0; o >>= 1) v += __shfl_xor_sync(0xffffffffu, v, o);
    return v;
}
__device__ __forceinline__ float ex2(float x) {
    float y;
    asm("ex2.approx.f32 %0, %1;" : "=f"(y) : "f"(x));
    return y;
}
// fast pack: two fp32 -> bf16x2 hi reg + residual bf16x2 lo reg (6 instrs)
__device__ __forceinline__ uint32_t pk2(float a, float b, uint32_t& lo) {
    __nv_bfloat162 hh = __floats2bfloat162_rn(a, b);     // x=a(lo half), y=b(hi half)
    uint32_t h = *(uint32_t*)&hh;
    float ha = __uint_as_float(h << 16);
    float hb = __uint_as_float(h & 0xffff0000u);
    __nv_bfloat162 ll = __floats2bfloat162_rn(a - ha, b - hb);
    lo = *(uint32_t*)&ll;
    return h;
}

// ------------------------- fp32 -> bf16 hi/lo conversion -------------------------
__global__ void cvt_hilo(const float* __restrict__ in, bf16* __restrict__ hi,
                         bf16* __restrict__ lo, int n4)
{
    int i = blockIdx.x * 256 + threadIdx.x;
    if (i >= n4) return;
    float4 x = ((const float4*)in)[i];
    uint32_t l0, l1;
    uint32_t h0 = pk2(x.x, x.y, l0);
    uint32_t h1 = pk2(x.z, x.w, l1);
    ((uint32_t*)hi)[2 * i]     = h0;
    ((uint32_t*)hi)[2 * i + 1] = h1;
    ((uint32_t*)lo)[2 * i]     = l0;
    ((uint32_t*)lo)[2 * i + 1] = l1;
}

// V^T gather:  vt[z][d][k] = qkv_hl[b*1024+k][512 + h*32 + d]
__global__ void cvt_vt(const bf16* __restrict__ qh, const bf16* __restrict__ ql,
                       bf16* __restrict__ vth, bf16* __restrict__ vtl)
{
    int i = blockIdx.x * 256 + threadIdx.x;           // 64*32*1024 = 2M
    int k = i & 1023, d = (i >> 10) & 31, z = i >> 15;
    int b = z >> 3, h = z & 7;
    size_t src = (size_t)(b * 1024 + k) * 768 + 512 + h * 32 + d;
    vth[i] = qh[src];
    vtl[i] = ql[src];
}

// ------------------------- CSR build (once) -------------------------
__global__ void csr_init() {
    int i = blockIdx.x * 256 + threadIdx.x;
    if (i < Nn) g_cnt[i] = 1;                 // self loop
}
__global__ void csr_count(const int* __restrict__ ei, int E) {
    int i = blockIdx.x * 256 + threadIdx.x;
    if (i < E) atomicAdd(&g_cnt[ei[E + i]], 1);
}
__global__ void csr_scan() {                  // single block, 1024 threads
    __shared__ int sdata[1024];
    int tid = threadIdx.x;
    int base = tid * 8;
    int loc[8];
    int s = 0;
    #pragma unroll
    for (int j = 0; j < 8; j++) { loc[j] = g_cnt[base + j]; s += loc[j]; }
    sdata[tid] = s;
    __syncthreads();
    for (int off = 1; off < 1024; off <<= 1) {
        int v = (tid >= off) ? sdata[tid - off] : 0;
        __syncthreads();
        sdata[tid] += v;
        __syncthreads();
    }
    int run = sdata[tid] - s;
    #pragma unroll
    for (int j = 0; j < 8; j++) {
        g_rowptr[base + j] = run;
        g_wpos[base + j] = run;
        run += loc[j];
    }
    if (tid == 1023) g_rowptr[Nn] = run;
}
__global__ void csr_fill(const int* __restrict__ ei, int E, int Etot) {
    int i = blockIdx.x * 256 + threadIdx.x;
    if (i >= Etot) return;
    int s, d;
    if (i < E) { s = ei[i]; d = ei[E + i]; } else { s = d = i - E; }
    int pos = atomicAdd(&g_wpos[d], 1);
    g_col[pos] = s;
}

// ------------------------- HMMA split-bf16 GEMM -------------------------
template<int OUT>
__global__ void __launch_bounds__(256, 1)
hgemm(const bf16* __restrict__ aH, const bf16* __restrict__ aL, int lda,
      const bf16* __restrict__ bH, const bf16* __restrict__ bL, int ldb,
      const float* __restrict__ bias, float* __restrict__ C,
      bf16* __restrict__ Ch, bf16* __restrict__ Cl, int ldc,
      int K, int relu)
{
    constexpr int WM = 64, WN = 32, MT = 4, NT8 = 4;
    constexpr int SST = 40;
    constexpr int ATILE = 128 * SST;
    constexpr int BTILE = 128 * SST;
    constexpr int STAGE = 2 * ATILE + 2 * BTILE;

    extern __shared__ bf16 sm[];

    int tid = threadIdx.x;
    int wid = tid >> 5, lane = tid & 31;
    int wm = wid % 2, wn = wid / 2;
    int m0 = blockIdx.y * 128;
    int n0 = blockIdx.x * 128;

    float acc[MT][NT8][4] = {};
    int P = K >> 5;

    auto load_panel = [&](int p, int s) {
        bf16* Ah = sm + s * STAGE;
        bf16* Al = Ah + ATILE;
        bf16* Bh = Al + ATILE;
        bf16* Bl = Bh + BTILE;
        int k0 = p * 32;
        #pragma unroll 2
        for (int idx = tid; idx < 512; idx += 256) {
            int r = idx >> 2, c = idx & 3;
            size_t g = (size_t)(m0 + r) * lda + k0 + c * 8;
            cp16(smem_u32(Ah + r * SST + c * 8), aH + g);
            cp16(smem_u32(Al + r * SST + c * 8), aL + g);
        }
        #pragma unroll 2
        for (int idx = tid; idx < 512; idx += 256) {
            int r = idx >> 2, c = idx & 3;
            size_t g = (size_t)(n0 + r) * ldb + k0 + c * 8;
            cp16(smem_u32(Bh + r * SST + c * 8), bH + g);
            cp16(smem_u32(Bl + r * SST + c * 8), bL + g);
        }
        cp_commit();
    };

    int t8 = lane >> 3;
    int rA = (t8 & 1) * 8 + (lane & 7), cA = (t8 >> 1) * 8;
    int rB = (t8 >> 1) * 8 + (lane & 7), cB = (t8 & 1) * 8;

    auto compute = [&](int s) {
        bf16* Ah = sm + s * STAGE;
        bf16* Al = Ah + ATILE;
        bf16* Bh = Al + ATILE;
        bf16* Bl = Bh + BTILE;
        #pragma unroll
        for (int kk = 0; kk < 2; kk++) {
            int k16 = kk * 16;
            uint32_t ah[MT][4], al[MT][4], bh[NT8][2], bl[NT8][2];
            #pragma unroll
            for (int mt = 0; mt < MT; mt++) {
                int row = wm * WM + mt * 16 + rA;
                ldm4(ah[mt], smem_u32(Ah + row * SST + k16 + cA));
                ldm4(al[mt], smem_u32(Al + row * SST + k16 + cA));
            }
            #pragma unroll
            for (int nt2 = 0; nt2 < NT8 / 2; nt2++) {
                int row = wn * WN + nt2 * 16 + rB;
                uint32_t r4[4];
                ldm4(r4, smem_u32(Bh + row * SST + k16 + cB));
                bh[2 * nt2][0] = r4[0]; bh[2 * nt2][1] = r4[1];
                bh[2 * nt2 + 1][0] = r4[2]; bh[2 * nt2 + 1][1] = r4[3];
                ldm4(r4, smem_u32(Bl + row * SST + k16 + cB));
                bl[2 * nt2][0] = r4[0]; bl[2 * nt2][1] = r4[1];
                bl[2 * nt2 + 1][0] = r4[2]; bl[2 * nt2 + 1][1] = r4[3];
            }
            #pragma unroll
            for (int mt = 0; mt < MT; mt++) {
                #pragma unroll
                for (int nt = 0; nt < NT8; nt++) {
                    mma16816(acc[mt][nt], ah[mt], bh[nt]);
                    mma16816(acc[mt][nt], ah[mt], bl[nt]);
                    mma16816(acc[mt][nt], al[mt], bh[nt]);
                }
            }
        }
    };

    load_panel(0, 0);
    for (int p = 0; p < P; p++) {
        if (p + 1 < P) {
            load_panel(p + 1, (p + 1) & 1);
            cp_wait1();
        } else {
            cp_wait0();
        }
        __syncthreads();
        compute(p & 1);
        __syncthreads();
    }

    int grp = lane >> 2, q4 = lane & 3;
    #pragma unroll
    for (int mt = 0; mt < MT; mt++) {
        #pragma unroll
        for (int nt = 0; nt < NT8; nt++) {
            int row = m0 + wm * WM + mt * 16 + grp;
            int col = n0 + wn * WN + nt * 8 + q4 * 2;
            float* a4 = acc[mt][nt];
            float b0 = 0.0f, b1 = 0.0f;
            if (bias) { b0 = bias[col]; b1 = bias[col + 1]; }
            float v0 = a4[0] + b0, v1 = a4[1] + b1;
            float v2 = a4[2] + b0, v3 = a4[3] + b1;
            if (relu) {
                v0 = fmaxf(v0, 0.0f); v1 = fmaxf(v1, 0.0f);
                v2 = fmaxf(v2, 0.0f); v3 = fmaxf(v3, 0.0f);
            }
            if (OUT == 0) {
                *(float2*)&C[(size_t)row * ldc + col]       = make_float2(v0, v1);
                *(float2*)&C[(size_t)(row + 8) * ldc + col] = make_float2(v2, v3);
            } else {
                uint32_t lo0, lo1;
                uint32_t h0 = pk2(v0, v1, lo0);
                uint32_t h1 = pk2(v2, v3, lo1);
                *(uint32_t*)&Ch[(size_t)row * ldc + col]       = h0;
                *(uint32_t*)&Cl[(size_t)row * ldc + col]       = lo0;
                *(uint32_t*)&Ch[(size_t)(row + 8) * ldc + col] = h1;
                *(uint32_t*)&Cl[(size_t)(row + 8) * ldc + col] = lo1;
            }
        }
    }
}

// ------------------------- fused flash attention -------------------------
__global__ void __launch_bounds__(256, 1)
flash_attn(const bf16* __restrict__ qkh, const bf16* __restrict__ qkl,
           const bf16* __restrict__ vth, const bf16* __restrict__ vtl,
           bf16* __restrict__ Oh, bf16* __restrict__ Ol, float scale)
{
    constexpr int QST = 40, VST = 136;
    constexpr int KBUF = 2 * 128 * QST + 2 * 32 * VST;
    extern __shared__ bf16 fsm[];
    bf16* sQh = fsm;
    bf16* sQl = sQh + 128 * QST;
    bf16* sK  = sQl + 128 * QST;

    const float SC = scale * 1.4426950408889634f;   // fold log2e: work in log2 domain

    int tid = threadIdx.x, wid = tid >> 5, lane = tid & 31;
    int z = blockIdx.y, b = z >> 3, h = z & 7;
    int q0 = blockIdx.x * 128;

    const bf16* Qh = qkh + (size_t)b * 1024 * 768 + h * 32;
    const bf16* Ql = qkl + (size_t)b * 1024 * 768 + h * 32;
    const bf16* Kh = Qh + 256;
    const bf16* Kl = Ql + 256;
    const bf16* Vh = vth + (size_t)z * 32 * 1024;
    const bf16* Vl = vtl + (size_t)z * 32 * 1024;

    for (int idx = tid; idx < 512; idx += 256) {
        int r = idx >> 2, c = idx & 3;
        cp16(smem_u32(sQh + r * QST + c * 8), Qh + (size_t)(q0 + r) * 768 + c * 8);
        cp16(smem_u32(sQl + r * QST + c * 8), Ql + (size_t)(q0 + r) * 768 + c * 8);
    }
    auto load_chunk = [&](int p, int s) {
        bf16* kh = sK + s * KBUF;
        bf16* kl = kh + 128 * QST;
        bf16* vh = kl + 128 * QST;
        bf16* vl = vh + 32 * VST;
        int k0 = p * 128;
        #pragma unroll 2
        for (int idx = tid; idx < 512; idx += 256) {
            int r = idx >> 2, c = idx & 3;
            cp16(smem_u32(kh + r * QST + c * 8), Kh + (size_t)(k0 + r) * 768 + c * 8);
            cp16(smem_u32(kl + r * QST + c * 8), Kl + (size_t)(k0 + r) * 768 + c * 8);
        }
        #pragma unroll 2
        for (int idx = tid; idx < 512; idx += 256) {
            int r = idx >> 4, c = idx & 15;
            cp16(smem_u32(vh + r * VST + c * 8), Vh + (size_t)r * 1024 + k0 + c * 8);
            cp16(smem_u32(vl + r * VST + c * 8), Vl + (size_t)r * 1024 + k0 + c * 8);
        }
        cp_commit();
    };

    int t8 = lane >> 3;
    int rA = (t8 & 1) * 8 + (lane & 7), cA = (t8 >> 1) * 8;
    int rB = (t8 >> 1) * 8 + (lane & 7), cB = (t8 & 1) * 8;
    int grp = lane >> 2, q4 = lane & 3;

    float oacc[4][4] = {};
    float m0 = -1e30f, m1 = -1e30f, l0 = 0.0f, l1 = 0.0f;
    uint32_t qfh[2][4], qfl[2][4];

    load_chunk(0, 0);
    for (int p = 0; p < 8; p++) {
        if (p < 7) { load_chunk(p + 1, (p + 1) & 1); cp_wait1(); }
        else cp_wait0();
        __syncthreads();
        if (p == 0) {
            #pragma unroll
            for (int kk = 0; kk < 2; kk++) {
                ldm4(qfh[kk], smem_u32(sQh + (wid * 16 + rA) * QST + kk * 16 + cA));
                ldm4(qfl[kk], smem_u32(sQl + (wid * 16 + rA) * QST + kk * 16 + cA));
            }
        }
        bf16* kh = sK + (p & 1) * KBUF;
        bf16* kl = kh + 128 * QST;
        bf16* vh = kl + 128 * QST;
        bf16* vl = vh + 32 * VST;

        float sacc[16][4];
        #pragma unroll
        for (int t = 0; t < 16; t++) { sacc[t][0] = 0; sacc[t][1] = 0; sacc[t][2] = 0; sacc[t][3] = 0; }
        #pragma unroll
        for (int nt2 = 0; nt2 < 8; nt2++) {
            #pragma unroll
            for (int kk = 0; kk < 2; kk++) {
                uint32_t bh4[4], bl4[4];
                ldm4(bh4, smem_u32(kh + (nt2 * 16 + rB) * QST + kk * 16 + cB));
                ldm4(bl4, smem_u32(kl + (nt2 * 16 + rB) * QST + kk * 16 + cB));
                #pragma unroll
                for (int hf = 0; hf < 2; hf++) {
                    mma16816(sacc[2 * nt2 + hf], qfh[kk], &bh4[2 * hf]);
                    mma16816(sacc[2 * nt2 + hf], qfh[kk], &bl4[2 * hf]);
                    mma16816(sacc[2 * nt2 + hf], qfl[kk], &bh4[2 * hf]);
                }
            }
        }
        // ---- online softmax (log2 domain) ----
        float cm0 = -1e30f, cm1 = -1e30f;
        #pragma unroll
        for (int t = 0; t < 16; t++) {
            sacc[t][0] *= SC; sacc[t][1] *= SC;
            sacc[t][2] *= SC; sacc[t][3] *= SC;
            cm0 = fmaxf(cm0, fmaxf(sacc[t][0], sacc[t][1]));
            cm1 = fmaxf(cm1, fmaxf(sacc[t][2], sacc[t][3]));
        }
        cm0 = fmaxf(cm0, __shfl_xor_sync(0xffffffffu, cm0, 1));
        cm0 = fmaxf(cm0, __shfl_xor_sync(0xffffffffu, cm0, 2));
        cm1 = fmaxf(cm1, __shfl_xor_sync(0xffffffffu, cm1, 1));
        cm1 = fmaxf(cm1, __shfl_xor_sync(0xffffffffu, cm1, 2));
        float mn0 = fmaxf(m0, cm0), mn1 = fmaxf(m1, cm1);
        float c0 = ex2(m0 - mn0), c1 = ex2(m1 - mn1);
        m0 = mn0; m1 = mn1;
        float rs0 = 0.0f, rs1 = 0.0f;
        #pragma unroll
        for (int t = 0; t < 16; t++) {
            sacc[t][0] = ex2(sacc[t][0] - mn0);
            sacc[t][1] = ex2(sacc[t][1] - mn0);
            sacc[t][2] = ex2(sacc[t][2] - mn1);
            sacc[t][3] = ex2(sacc[t][3] - mn1);
            rs0 += sacc[t][0] + sacc[t][1];
            rs1 += sacc[t][2] + sacc[t][3];
        }
        l0 = l0 * c0 + rs0;
        l1 = l1 * c1 + rs1;
        #pragma unroll
        for (int n = 0; n < 4; n++) {
            oacc[n][0] *= c0; oacc[n][1] *= c0;
            oacc[n][2] *= c1; oacc[n][3] *= c1;
        }
        #pragma unroll
        for (int kt = 0; kt < 8; kt++) {
            uint32_t pah4[4], pal4[4];
            pah4[0] = pk2(sacc[2 * kt][0],     sacc[2 * kt][1],     pal4[0]);
            pah4[1] = pk2(sacc[2 * kt][2],     sacc[2 * kt][3],     pal4[1]);
            pah4[2] = pk2(sacc[2 * kt + 1][0], sacc[2 * kt + 1][1], pal4[2]);
            pah4[3] = pk2(sacc[2 * kt + 1][2], sacc[2 * kt + 1][3], pal4[3]);
            #pragma unroll
            for (int np = 0; np < 2; np++) {
                uint32_t vb_h[4], vb_l[4];
                ldm4(vb_h, smem_u32(vh + (np * 16 + rB) * VST + kt * 16 + cB));
                ldm4(vb_l, smem_u32(vl + (np * 16 + rB) * VST + kt * 16 + cB));
                #pragma unroll
                for (int hf = 0; hf < 2; hf++) {
                    mma16816(oacc[2 * np + hf], pah4, &vb_h[2 * hf]);
                    mma16816(oacc[2 * np + hf], pah4, &vb_l[2 * hf]);
                    mma16816(oacc[2 * np + hf], pal4, &vb_h[2 * hf]);
                }
            }
        }
        __syncthreads();
    }
    l0 += __shfl_xor_sync(0xffffffffu, l0, 1);
    l0 += __shfl_xor_sync(0xffffffffu, l0, 2);
    l1 += __shfl_xor_sync(0xffffffffu, l1, 1);
    l1 += __shfl_xor_sync(0xffffffffu, l1, 2);
    float i0 = 1.0f / l0, i1 = 1.0f / l1;
    size_t obase = (size_t)(b * 1024 + q0) * 256 + h * 32;
    #pragma unroll
    for (int n = 0; n < 4; n++) {
        int row = wid * 16 + grp;
        int col = n * 8 + q4 * 2;
        uint32_t lo0, lo1;
        uint32_t h0 = pk2(oacc[n][0] * i0, oacc[n][1] * i0, lo0);
        uint32_t h1 = pk2(oacc[n][2] * i1, oacc[n][3] * i1, lo1);
        *(uint32_t*)&Oh[obase + (size_t)row * 256 + col]       = h0;
        *(uint32_t*)&Ol[obase + (size_t)row * 256 + col]       = lo0;
        *(uint32_t*)&Oh[obase + (size_t)(row + 8) * 256 + col] = h1;
        *(uint32_t*)&Ol[obase + (size_t)(row + 8) * 256 + col] = lo1;
    }
}

// ------------------------- GAT pieces -------------------------
// warp per node: lane covers cols [lane*8, lane*8+8), head = lane>>2, quad-reduce
__global__ void att_prep(const float* __restrict__ hbuf,
                         const float* __restrict__ atts, const float* __restrict__ attd)
{
    int n = blockIdx.x * 8 + (threadIdx.x >> 5);
    int lane = threadIdx.x & 31;
    const float4* hp = (const float4*)(hbuf + (size_t)n * Dd + lane * 8);
    float4 a = hp[0], b = hp[1];
    const float4* pa = (const float4*)(atts + lane * 8);
    const float4* pb = (const float4*)(attd + lane * 8);
    float4 wa0 = pa[0], wa1 = pa[1];
    float4 wb0 = pb[0], wb1 = pb[1];
    float s1 = a.x * wa0.x + a.y * wa0.y + a.z * wa0.z + a.w * wa0.w
             + b.x * wa1.x + b.y * wa1.y + b.z * wa1.z + b.w * wa1.w;
    float s2 = a.x * wb0.x + a.y * wb0.y + a.z * wb0.z + a.w * wb0.w
             + b.x * wb1.x + b.y * wb1.y + b.z * wb1.z + b.w * wb1.w;
    s1 += __shfl_xor_sync(0xffffffffu, s1, 1);
    s1 += __shfl_xor_sync(0xffffffffu, s1, 2);
    s2 += __shfl_xor_sync(0xffffffffu, s2, 1);
    s2 += __shfl_xor_sync(0xffffffffu, s2, 2);
    if ((lane & 3) == 0) {
        g_as[n * 8 + (lane >> 2)] = s1;
        g_ad[n * 8 + (lane >> 2)] = s2;
    }
}

// fused per-dst GAT aggregation; alpha cache in smem; one warp per dst node.
#define DEGCAP 96
__global__ void __launch_bounds__(256)
gat_aggr(const float* __restrict__ hbuf, const float* __restrict__ bias,
         float* __restrict__ outF, bf16* __restrict__ outH, bf16* __restrict__ outL)
{
    __shared__ float salpha[8][DEGCAP][8];
    int wid = threadIdx.x >> 5, lane = threadIdx.x & 31;
    int d = blockIdx.x * 8 + wid;
    int base = g_rowptr[d];
    int deg  = g_rowptr[d + 1] - base;

    // ---- phase A: per-head max (head = lane&7, slot = lane>>3) ----
    int hd = lane & 7;
    float adv = g_ad[d * 8 + hd];
    float m = -1e30f;
    for (int i = lane >> 3; i < deg; i += 4) {
        int s = g_col[base + i];
        float v = g_as[s * 8 + hd] + adv;
        v = v > 0.0f ? v : 0.2f * v;
        m = fmaxf(m, v);
    }
    m = fmaxf(m, __shfl_xor_sync(0xffffffffu, m, 8));
    m = fmaxf(m, __shfl_xor_sync(0xffffffffu, m, 16));
    // ---- phase B: exp-sum, cache p into smem ----
    float sum = 0.0f;
    for (int i = lane >> 3; i < deg; i += 4) {
        int s = g_col[base + i];
        float v = g_as[s * 8 + hd] + adv;
        v = v > 0.0f ? v : 0.2f * v;
        float p = __expf(v - m);
        if (i < DEGCAP) salpha[wid][i][hd] = p;
        sum += p;
    }
    sum += __shfl_xor_sync(0xffffffffu, sum, 8);
    sum += __shfl_xor_sync(0xffffffffu, sum, 16);
    __syncwarp();

    // ---- phase C: gather; lane covers cols [lane*8, +8), head = lane>>2 ----
    int hd2 = lane >> 2;
    float m2  = __shfl_sync(0xffffffffu, m, hd2);
    float is2 = 1.0f / __shfl_sync(0xffffffffu, sum, hd2);
    float adv2 = g_ad[d * 8 + hd2];
    float acc[8] = {};

    auto getp = [&](int i, int s) -> float {
        if (i < DEGCAP) return salpha[wid][i][hd2];
        float v = g_as[s * 8 + hd2] + adv2;
        v = v > 0.0f ? v : 0.2f * v;
        return __expf(v - m2);
    };
    int i = 0;
    for (; i + 2 <= deg; i += 2) {
        int s0 = g_col[base + i], s1 = g_col[base + i + 1];
        float al0 = getp(i, s0) * is2;
        float al1 = getp(i + 1, s1) * is2;
        const float4* h0 = (const float4*)(hbuf + (size_t)s0 * Dd + lane * 8);
        const float4* h1 = (const float4*)(hbuf + (size_t)s1 * Dd + lane * 8);
        float4 a0 = h0[0], b0 = h0[1];
        float4 a1 = h1[0], b1 = h1[1];
        acc[0] += al0 * a0.x + al1 * a1.x;  acc[1] += al0 * a0.y + al1 * a1.y;
        acc[2] += al0 * a0.z + al1 * a1.z;  acc[3] += al0 * a0.w + al1 * a1.w;
        acc[4] += al0 * b0.x + al1 * b1.x;  acc[5] += al0 * b0.y + al1 * b1.y;
        acc[6] += al0 * b0.z + al1 * b1.z;  acc[7] += al0 * b0.w + al1 * b1.w;
    }
    if (i < deg) {
        int s0 = g_col[base + i];
        float al0 = getp(i, s0) * is2;
        const float4* h0 = (const float4*)(hbuf + (size_t)s0 * Dd + lane * 8);
        float4 a0 = h0[0], b0 = h0[1];
        acc[0] += al0 * a0.x;  acc[1] += al0 * a0.y;
        acc[2] += al0 * a0.z;  acc[3] += al0 * a0.w;
        acc[4] += al0 * b0.x;  acc[5] += al0 * b0.y;
        acc[6] += al0 * b0.z;  acc[7] += al0 * b0.w;
    }
    size_t rb = (size_t)d * Dd + lane * 8;
    #pragma unroll
    for (int j = 0; j < 8; j += 2) {
        float v0 = fmaxf(acc[j]     + bias[lane * 8 + j],     0.0f);
        float v1 = fmaxf(acc[j + 1] + bias[lane * 8 + j + 1], 0.0f);
        *(float2*)&outF[rb + j] = make_float2(v0, v1);
        uint32_t lo;
        uint32_t hi = pk2(v0, v1, lo);
        *(uint32_t*)&outH[rb + j] = hi;
        *(uint32_t*)&outL[rb + j] = lo;
    }
}

// ------------------------- residual + layernorm -------------------------
__global__ void ln_res(const float* __restrict__ xin, const float* __restrict__ add,
                       float* __restrict__ xout, const float* __restrict__ w,
                       const float* __restrict__ b,
                       bf16* __restrict__ oh, bf16* __restrict__ ol)
{
    int row = blockIdx.x * 8 + (threadIdx.x >> 5);
    int lane = threadIdx.x & 31;
    const float* xr = xin + (size_t)row * Dd;
    const float* ar = add + (size_t)row * Dd;
    float v[8];
    float s = 0.0f;
    #pragma unroll
    for (int j = 0; j < 8; j++) {
        int d = lane + j * 32;
        v[j] = xr[d] + ar[d];
        s += v[j];
    }
    s = warpSum(s);
    float mean = s * (1.0f / 256.0f);
    float var = 0.0f;
    #pragma unroll
    for (int j = 0; j < 8; j++) {
        float dv = v[j] - mean;
        var += dv * dv;
    }
    var = warpSum(var) * (1.0f / 256.0f);
    float inv = rsqrtf(var + 1e-5f);
    float* orow = xout + (size_t)row * Dd;
    #pragma unroll
    for (int j = 0; j < 8; j++) {
        int d = lane + j * 32;
        float o = (v[j] - mean) * inv * w[d] + b[d];
        orow[d] = o;
        bf16 h = __float2bfloat16(o);
        oh[(size_t)row * Dd + d] = h;
        ol[(size_t)row * Dd + d] = __float2bfloat16(o - __bfloat162float(h));
    }
}

// ------------------------- prediction head -------------------------
__global__ void pred_kernel(const float* __restrict__ xin, const float* __restrict__ pw,
                            const float* __restrict__ pb, float* __restrict__ out)
{
    int gw = (blockIdx.x * 256 + threadIdx.x) >> 5;
    int lane = threadIdx.x & 31;
    if (gw >= Nn) return;
    const float* xr = xin + (size_t)gw * Dd;
    float a0 = 0.0f, a1 = 0.0f, a2 = 0.0f;
    #pragma unroll
    for (int j = 0; j < 8; j++) {
        int d = lane + j * 32;
        float xv = xr[d];
        a0 += xv * pw[d];
        a1 += xv * pw[Dd + d];
        a2 += xv * pw[2 * Dd + d];
    }
    a0 = warpSum(a0);
    a1 = warpSum(a1);
    a2 = warpSum(a2);
    if (lane == 0) {
        out[gw * 3 + 0] = a0 + pb[0];
        out[gw * 3 + 1] = a1 + pb[1];
        out[gw * 3 + 2] = a2 + pb[2];
    }
}

// ------------------------- host orchestration -------------------------
#define SMEM_G (4 * 128 * 40 * 2 * 2)
#define SMEM_F ((2 * 128 * 40 + 2 * (2 * 128 * 40 + 2 * 32 * 136)) * 2)

extern "C" void kernel_launch(void* const* d_in, const int* in_sizes, int n_in,
                              void* d_out, int out_size)
{
    const float* x      = (const float*)d_in[0];
    const int*   ei     = (const int*)d_in[1];
    const float* W0     = (const float*)d_in[3];
    const float* W12    = (const float*)d_in[4];
    const float* att_s  = (const float*)d_in[5];
    const float* att_d  = (const float*)d_in[6];
    const float* gbias  = (const float*)d_in[7];
    const float* qkv_w  = (const float*)d_in[8];
    const float* qkv_b  = (const float*)d_in[9];
    const float* out_w  = (const float*)d_in[10];
    const float* out_b  = (const float*)d_in[11];
    const float* ln1w   = (const float*)d_in[12];
    const float* ln1b   = (const float*)d_in[13];
    const float* ln2w   = (const float*)d_in[14];
    const float* ln2b   = (const float*)d_in[15];
    const float* ff1w   = (const float*)d_in[16];
    const float* ff1b   = (const float*)d_in[17];
    const float* ff2w   = (const float*)d_in[18];
    const float* ff2b   = (const float*)d_in[19];
    const float* predw  = (const float*)d_in[20];
    const float* predb  = (const float*)d_in[21];
    float* out = (float*)d_out;

    int E = in_sizes[1] / 2;
    int Etot = E + Nn;

    cudaFuncSetAttribute((const void*)hgemm<0>, cudaFuncAttributeMaxDynamicSharedMemorySize, SMEM_G);
    cudaFuncSetAttribute((const void*)hgemm<1>, cudaFuncAttributeMaxDynamicSharedMemorySize, SMEM_G);
    cudaFuncSetAttribute((const void*)flash_attn, cudaFuncAttributeMaxDynamicSharedMemorySize, SMEM_F);

    float *ph, *px;
    bf16 *pah, *pal, *pxh, *pxl, *pwh, *pwl, *pqh, *pql, *pvth, *pvtl;
    cudaGetSymbolAddress((void**)&ph,    g_h);
    cudaGetSymbolAddress((void**)&px,    g_x);
    cudaGetSymbolAddress((void**)&pah,   g_ah);
    cudaGetSymbolAddress((void**)&pal,   g_al);
    cudaGetSymbolAddress((void**)&pxh,   g_xh);
    cudaGetSymbolAddress((void**)&pxl,   g_xl);
    cudaGetSymbolAddress((void**)&pwh,   g_wh);
    cudaGetSymbolAddress((void**)&pwl,   g_wl);
    cudaGetSymbolAddress((void**)&pqh,   g_qh);
    cudaGetSymbolAddress((void**)&pql,   g_ql);
    cudaGetSymbolAddress((void**)&pvth,  g_vth);
    cudaGetSymbolAddress((void**)&pvtl,  g_vtl);

    // ---------------- CSR build (once) ----------------
    csr_init<<<Nn / 256, 256>>>();
    csr_count<<<(E + 255) / 256, 256>>>(ei, E);
    csr_scan<<<1, 1024>>>();
    csr_fill<<<(Etot + 255) / 256, 256>>>(ei, E, Etot);

    // ---------------- GAT layers ----------------
    cvt_hilo<<<(Nn * 64 / 4 + 255) / 256, 256>>>(x, pxh, pxl, Nn * 64 / 4);
    int curK = 64;
    for (int l = 0; l < 3; l++) {
        const float* W = (l == 0) ? W0 : (W12 + (size_t)(l - 1) * Dd * Dd);
        cvt_hilo<<<(Dd * curK / 4 + 255) / 256, 256>>>(W, pwh, pwl, Dd * curK / 4);
        hgemm<0><<<dim3(Dd / 128, Nn / 128), 256, SMEM_G>>>(
            pxh, pxl, curK, pwh, pwl, curK, nullptr, ph, nullptr, nullptr, Dd, curK, 0);
        att_prep<<<Nn / 8, 256>>>(ph, att_s + l * Dd, att_d + l * Dd);
        gat_aggr<<<Nn / 8, 256>>>(ph, gbias + l * Dd, px, pxh, pxl);
        curK = Dd;
    }

    // ---------------- transformer layers ----------------
    const float scale = 0.17677669529663687f;  // 1/sqrt(32)
    for (int i = 0; i < 2; i++) {
        cvt_hilo<<<(768 * Dd / 4 + 255) / 256, 256>>>(qkv_w + (size_t)i * 768 * Dd, pwh, pwl, 768 * Dd / 4);
        hgemm<1><<<dim3(768 / 128, Nn / 128), 256, SMEM_G>>>(
            pxh, pxl, Dd, pwh, pwl, Dd, qkv_b + i * 768, nullptr, pqh, pql, 768, Dd, 0);
        cvt_vt<<<(64 * 32 * 1024) / 256, 256>>>(pqh, pql, pvth, pvtl);
        flash_attn<<<dim3(8, 64), 256, SMEM_F>>>(pqh, pql, pvth, pvtl, pah, pal, scale);
        cvt_hilo<<<(Dd * Dd / 4 + 255) / 256, 256>>>(out_w + (size_t)i * Dd * Dd, pwh, pwl, Dd * Dd / 4);
        hgemm<0><<<dim3(Dd / 128, Nn / 128), 256, SMEM_G>>>(
            pah, pal, Dd, pwh, pwl, Dd, out_b + i * Dd, ph, nullptr, nullptr, Dd, Dd, 0);
        ln_res<<<Nn / 8, 256>>>(px, ph, px, ln1w + i * Dd, ln1b + i * Dd, pxh, pxl);
        cvt_hilo<<<(DFF * Dd / 4 + 255) / 256, 256>>>(ff1w + (size_t)i * DFF * Dd, pwh, pwl, DFF * Dd / 4);
        hgemm<1><<<dim3(DFF / 128, Nn / 128), 256, SMEM_G>>>(
            pxh, pxl, Dd, pwh, pwl, Dd, ff1b + i * DFF, nullptr, pah, pal, DFF, Dd, 1);
        cvt_hilo<<<(Dd * DFF / 4 + 255) / 256, 256>>>(ff2w + (size_t)i * Dd * DFF, pwh, pwl, Dd * DFF / 4);
        hgemm<0><<<dim3(Dd / 128, Nn / 128), 256, SMEM_G>>>(
            pah, pal, DFF, pwh, pwl, DFF, ff2b + i * Dd, ph, nullptr, nullptr, Dd, DFF, 0);
        ln_res<<<Nn / 8, 256>>>(px, ph, px, ln2w + i * Dd, ln2b + i * Dd, pxh, pxl);
    }

    // ---------------- prediction head ----------------
    pred_kernel<<<(Nn * 32 + 255) / 256, 256>>>(px, predw, predb, out);
}

// round 7
// speedup vs baseline: 2.9150x; 1.0509x over previous
#include <cuda_runtime.h>
#include <cuda_bf16.h>
#include <math.h>
#include <stdint.h>

using bf16 = __nv_bfloat16;

#define Nn   8192
#define Bb   8
#define Ll   1024
#define Hh   8
#define Cc   32
#define Dd   256
#define DFF  2048
#define Emax 262144
#define ETOTmax (Emax + Nn)
#define WTOT 2768896

// ------------------------- scratch (static device globals) -------------------------
__device__ float    g_h   [Nn * Dd];
__device__ float    g_x   [Nn * Dd];
__device__ float    g_as  [Nn * Hh];
__device__ float    g_ad  [Nn * Hh];
__device__ int      g_cnt [Nn];
__device__ int      g_rowptr[Nn + 1];
__device__ int      g_wpos[Nn];
__device__ int      g_col [ETOTmax];

__device__ bf16 g_ah[Nn * DFF];               // A hi (max 8192x2048)
__device__ bf16 g_al[Nn * DFF];               // A lo
__device__ bf16 g_xh[Nn * Dd];                // residual stream hi
__device__ bf16 g_xl[Nn * Dd];
__device__ bf16 g_wh[WTOT];                   // all weights hi
__device__ bf16 g_wl[WTOT];                   // all weights lo
__device__ bf16 g_qh[Nn * 3 * Dd];            // qkv hi
__device__ bf16 g_ql[Nn * 3 * Dd];

// weight arena offsets
#define WO_W0    0
#define WO_W1    16384
#define WO_W2    81920
#define WO_QKV0  147456
#define WO_QKV1  344064
#define WO_OUT0  540672
#define WO_OUT1  606208
#define WO_FF1_0 671744
#define WO_FF1_1 1196032
#define WO_FF2_0 1720320
#define WO_FF2_1 2244608

// ------------------------- helpers -------------------------
__device__ __forceinline__ uint32_t smem_u32(const void* p) {
    uint32_t a;
    asm("{ .reg .u64 t; cvta.to.shared.u64 t, %1; cvt.u32.u64 %0, t; }" : "=r"(a) : "l"(p));
    return a;
}
__device__ __forceinline__ void cp16(uint32_t s, const void* g) {
    asm volatile("cp.async.cg.shared.global [%0], [%1], 16;" :: "r"(s), "l"(g));
}
__device__ __forceinline__ void cp_commit() {
    asm volatile("cp.async.commit_group;" ::: "memory");
}
__device__ __forceinline__ void cp_wait0() {
    asm volatile("cp.async.wait_group 0;" ::: "memory");
}
__device__ __forceinline__ void cp_wait1() {
    asm volatile("cp.async.wait_group 1;" ::: "memory");
}
__device__ __forceinline__ void ldm4(uint32_t* r, uint32_t addr) {
    asm volatile("ldmatrix.sync.aligned.m8n8.x4.shared.b16 {%0,%1,%2,%3}, [%4];"
        : "=r"(r[0]), "=r"(r[1]), "=r"(r[2]), "=r"(r[3]) : "r"(addr));
}
__device__ __forceinline__ void ldm4t(uint32_t* r, uint32_t addr) {
    asm volatile("ldmatrix.sync.aligned.m8n8.x4.trans.shared.b16 {%0,%1,%2,%3}, [%4];"
        : "=r"(r[0]), "=r"(r[1]), "=r"(r[2]), "=r"(r[3]) : "r"(addr));
}
__device__ __forceinline__ void mma16816(float* d, const uint32_t* a, const uint32_t* b) {
    asm volatile(
        "mma.sync.aligned.m16n8k16.row.col.f32.bf16.bf16.f32 "
        "{%0,%1,%2,%3}, {%4,%5,%6,%7}, {%8,%9}, {%0,%1,%2,%3};"
        : "+f"(d[0]), "+f"(d[1]), "+f"(d[2]), "+f"(d[3])
        : "r"(a[0]), "r"(a[1]), "r"(a[2]), "r"(a[3]), "r"(b[0]), "r"(b[1]));
}
__device__ __forceinline__ float warpSum(float v) {
    #pragma unroll
    for (int o = 16; o > 0; o >>= 1) v += __shfl_xor_sync(0xffffffffu, v, o);
    return v;
}
__device__ __forceinline__ float ex2(float x) {
    float y;
    asm("ex2.approx.f32 %0, %1;" : "=f"(y) : "f"(x));
    return y;
}
// fast pack: two fp32 -> bf16x2 hi reg + residual bf16x2 lo reg
__device__ __forceinline__ uint32_t pk2(float a, float b, uint32_t& lo) {
    __nv_bfloat162 hh = __floats2bfloat162_rn(a, b);
    uint32_t h = *(uint32_t*)&hh;
    float ha = __uint_as_float(h << 16);
    float hb = __uint_as_float(h & 0xffff0000u);
    __nv_bfloat162 ll = __floats2bfloat162_rn(a - ha, b - hb);
    lo = *(uint32_t*)&ll;
    return h;
}

// ------------------------- conversions -------------------------
__global__ void cvt_hilo(const float* __restrict__ in, bf16* __restrict__ hi,
                         bf16* __restrict__ lo, int n4)
{
    int i = blockIdx.x * 256 + threadIdx.x;
    if (i >= n4) return;
    float4 x = ((const float4*)in)[i];
    uint32_t l0, l1;
    uint32_t h0 = pk2(x.x, x.y, l0);
    uint32_t h1 = pk2(x.z, x.w, l1);
    ((uint32_t*)hi)[2 * i]     = h0;
    ((uint32_t*)hi)[2 * i + 1] = h1;
    ((uint32_t*)lo)[2 * i]     = l0;
    ((uint32_t*)lo)[2 * i + 1] = l1;
}

// convert all weight matrices in one launch: grid (512, NSEG)
struct WSegs {
    const float* src[11];
    int off[11];
    int n4[11];
};
__global__ void cvt_weights(WSegs w)
{
    int s = blockIdx.y;
    int i = blockIdx.x * 256 + threadIdx.x;
    if (i >= w.n4[s]) return;
    float4 x = ((const float4*)w.src[s])[i];
    uint32_t l0, l1;
    uint32_t h0 = pk2(x.x, x.y, l0);
    uint32_t h1 = pk2(x.z, x.w, l1);
    uint32_t* dh = (uint32_t*)(g_wh + w.off[s]);
    uint32_t* dl = (uint32_t*)(g_wl + w.off[s]);
    dh[2 * i]     = h0;
    dh[2 * i + 1] = h1;
    dl[2 * i]     = l0;
    dl[2 * i + 1] = l1;
}

// ------------------------- CSR build (once) -------------------------
__global__ void csr_init() {
    int i = blockIdx.x * 256 + threadIdx.x;
    if (i < Nn) g_cnt[i] = 1;                 // self loop
}
__global__ void csr_count(const int* __restrict__ ei, int E) {
    int i = blockIdx.x * 256 + threadIdx.x;
    if (i < E) atomicAdd(&g_cnt[ei[E + i]], 1);
}
__global__ void csr_scan() {                  // single block, 1024 threads
    __shared__ int sdata[1024];
    int tid = threadIdx.x;
    int base = tid * 8;
    int loc[8];
    int s = 0;
    #pragma unroll
    for (int j = 0; j < 8; j++) { loc[j] = g_cnt[base + j]; s += loc[j]; }
    sdata[tid] = s;
    __syncthreads();
    for (int off = 1; off < 1024; off <<= 1) {
        int v = (tid >= off) ? sdata[tid - off] : 0;
        __syncthreads();
        sdata[tid] += v;
        __syncthreads();
    }
    int run = sdata[tid] - s;
    #pragma unroll
    for (int j = 0; j < 8; j++) {
        g_rowptr[base + j] = run;
        g_wpos[base + j] = run;
        run += loc[j];
    }
    if (tid == 1023) g_rowptr[Nn] = run;
}
__global__ void csr_fill(const int* __restrict__ ei, int E, int Etot) {
    int i = blockIdx.x * 256 + threadIdx.x;
    if (i >= Etot) return;
    int s, d;
    if (i < E) { s = ei[i]; d = ei[E + i]; } else { s = d = i - E; }
    int pos = atomicAdd(&g_wpos[d], 1);
    g_col[pos] = s;
}

// ------------------------- HMMA split-bf16 GEMM -------------------------
template<int OUT>
__global__ void __launch_bounds__(256, 1)
hgemm(const bf16* __restrict__ aH, const bf16* __restrict__ aL, int lda,
      const bf16* __restrict__ bH, const bf16* __restrict__ bL, int ldb,
      const float* __restrict__ bias, float* __restrict__ C,
      bf16* __restrict__ Ch, bf16* __restrict__ Cl, int ldc,
      int K, int relu)
{
    constexpr int WM = 64, WN = 32, MT = 4, NT8 = 4;
    constexpr int SST = 40;
    constexpr int ATILE = 128 * SST;
    constexpr int BTILE = 128 * SST;
    constexpr int STAGE = 2 * ATILE + 2 * BTILE;

    extern __shared__ bf16 sm[];

    int tid = threadIdx.x;
    int wid = tid >> 5, lane = tid & 31;
    int wm = wid % 2, wn = wid / 2;
    int m0 = blockIdx.y * 128;
    int n0 = blockIdx.x * 128;

    float acc[MT][NT8][4] = {};
    int P = K >> 5;

    auto load_panel = [&](int p, int s) {
        bf16* Ah = sm + s * STAGE;
        bf16* Al = Ah + ATILE;
        bf16* Bh = Al + ATILE;
        bf16* Bl = Bh + BTILE;
        int k0 = p * 32;
        #pragma unroll 2
        for (int idx = tid; idx < 512; idx += 256) {
            int r = idx >> 2, c = idx & 3;
            size_t g = (size_t)(m0 + r) * lda + k0 + c * 8;
            cp16(smem_u32(Ah + r * SST + c * 8), aH + g);
            cp16(smem_u32(Al + r * SST + c * 8), aL + g);
        }
        #pragma unroll 2
        for (int idx = tid; idx < 512; idx += 256) {
            int r = idx >> 2, c = idx & 3;
            size_t g = (size_t)(n0 + r) * ldb + k0 + c * 8;
            cp16(smem_u32(Bh + r * SST + c * 8), bH + g);
            cp16(smem_u32(Bl + r * SST + c * 8), bL + g);
        }
        cp_commit();
    };

    int t8 = lane >> 3;
    int rA = (t8 & 1) * 8 + (lane & 7), cA = (t8 >> 1) * 8;
    int rB = (t8 >> 1) * 8 + (lane & 7), cB = (t8 & 1) * 8;

    auto compute = [&](int s) {
        bf16* Ah = sm + s * STAGE;
        bf16* Al = Ah + ATILE;
        bf16* Bh = Al + ATILE;
        bf16* Bl = Bh + BTILE;
        #pragma unroll
        for (int kk = 0; kk < 2; kk++) {
            int k16 = kk * 16;
            uint32_t ah[MT][4], al[MT][4], bh[NT8][2], bl[NT8][2];
            #pragma unroll
            for (int mt = 0; mt < MT; mt++) {
                int row = wm * WM + mt * 16 + rA;
                ldm4(ah[mt], smem_u32(Ah + row * SST + k16 + cA));
                ldm4(al[mt], smem_u32(Al + row * SST + k16 + cA));
            }
            #pragma unroll
            for (int nt2 = 0; nt2 < NT8 / 2; nt2++) {
                int row = wn * WN + nt2 * 16 + rB;
                uint32_t r4[4];
                ldm4(r4, smem_u32(Bh + row * SST + k16 + cB));
                bh[2 * nt2][0] = r4[0]; bh[2 * nt2][1] = r4[1];
                bh[2 * nt2 + 1][0] = r4[2]; bh[2 * nt2 + 1][1] = r4[3];
                ldm4(r4, smem_u32(Bl + row * SST + k16 + cB));
                bl[2 * nt2][0] = r4[0]; bl[2 * nt2][1] = r4[1];
                bl[2 * nt2 + 1][0] = r4[2]; bl[2 * nt2 + 1][1] = r4[3];
            }
            #pragma unroll
            for (int mt = 0; mt < MT; mt++) {
                #pragma unroll
                for (int nt = 0; nt < NT8; nt++) {
                    mma16816(acc[mt][nt], ah[mt], bh[nt]);
                    mma16816(acc[mt][nt], ah[mt], bl[nt]);
                    mma16816(acc[mt][nt], al[mt], bh[nt]);
                }
            }
        }
    };

    load_panel(0, 0);
    for (int p = 0; p < P; p++) {
        if (p + 1 < P) {
            load_panel(p + 1, (p + 1) & 1);
            cp_wait1();
        } else {
            cp_wait0();
        }
        __syncthreads();
        compute(p & 1);
        __syncthreads();
    }

    int grp = lane >> 2, q4 = lane & 3;
    #pragma unroll
    for (int mt = 0; mt < MT; mt++) {
        #pragma unroll
        for (int nt = 0; nt < NT8; nt++) {
            int row = m0 + wm * WM + mt * 16 + grp;
            int col = n0 + wn * WN + nt * 8 + q4 * 2;
            float* a4 = acc[mt][nt];
            float b0 = 0.0f, b1 = 0.0f;
            if (bias) { b0 = bias[col]; b1 = bias[col + 1]; }
            float v0 = a4[0] + b0, v1 = a4[1] + b1;
            float v2 = a4[2] + b0, v3 = a4[3] + b1;
            if (relu) {
                v0 = fmaxf(v0, 0.0f); v1 = fmaxf(v1, 0.0f);
                v2 = fmaxf(v2, 0.0f); v3 = fmaxf(v3, 0.0f);
            }
            if (OUT == 0) {
                *(float2*)&C[(size_t)row * ldc + col]       = make_float2(v0, v1);
                *(float2*)&C[(size_t)(row + 8) * ldc + col] = make_float2(v2, v3);
            } else {
                uint32_t lo0, lo1;
                uint32_t h0 = pk2(v0, v1, lo0);
                uint32_t h1 = pk2(v2, v3, lo1);
                *(uint32_t*)&Ch[(size_t)row * ldc + col]       = h0;
                *(uint32_t*)&Cl[(size_t)row * ldc + col]       = lo0;
                *(uint32_t*)&Ch[(size_t)(row + 8) * ldc + col] = h1;
                *(uint32_t*)&Cl[(size_t)(row + 8) * ldc + col] = lo1;
            }
        }
    }
}

// ------------------------- fused flash attention (V direct, trans-ldmatrix) -------------------------
__global__ void __launch_bounds__(256, 1)
flash_attn(const bf16* __restrict__ qkh, const bf16* __restrict__ qkl,
           bf16* __restrict__ Oh, bf16* __restrict__ Ol, float scale)
{
    constexpr int QST = 40;
    constexpr int KBUF = 4 * 128 * QST;   // kh, kl, vh, vl each [128][40]
    extern __shared__ bf16 fsm[];
    bf16* sQh = fsm;
    bf16* sQl = sQh + 128 * QST;
    bf16* sK  = sQl + 128 * QST;

    const float SC = scale * 1.4426950408889634f;

    int tid = threadIdx.x, wid = tid >> 5, lane = tid & 31;
    int z = blockIdx.y, b = z >> 3, h = z & 7;
    int q0 = blockIdx.x * 128;

    const bf16* Qh = qkh + (size_t)b * 1024 * 768 + h * 32;
    const bf16* Ql = qkl + (size_t)b * 1024 * 768 + h * 32;
    const bf16* Kh = Qh + 256;
    const bf16* Kl = Ql + 256;
    const bf16* Vh = Qh + 512;
    const bf16* Vl = Ql + 512;

    for (int idx = tid; idx < 512; idx += 256) {
        int r = idx >> 2, c = idx & 3;
        cp16(smem_u32(sQh + r * QST + c * 8), Qh + (size_t)(q0 + r) * 768 + c * 8);
        cp16(smem_u32(sQl + r * QST + c * 8), Ql + (size_t)(q0 + r) * 768 + c * 8);
    }
    auto load_chunk = [&](int p, int s) {
        bf16* kh = sK + s * KBUF;
        bf16* kl = kh + 128 * QST;
        bf16* vh = kl + 128 * QST;
        bf16* vl = vh + 128 * QST;
        int k0 = p * 128;
        #pragma unroll 2
        for (int idx = tid; idx < 512; idx += 256) {
            int r = idx >> 2, c = idx & 3;
            size_t g = (size_t)(k0 + r) * 768 + c * 8;
            cp16(smem_u32(kh + r * QST + c * 8), Kh + g);
            cp16(smem_u32(kl + r * QST + c * 8), Kl + g);
        }
        #pragma unroll 2
        for (int idx = tid; idx < 512; idx += 256) {
            int r = idx >> 2, c = idx & 3;
            size_t g = (size_t)(k0 + r) * 768 + c * 8;
            cp16(smem_u32(vh + r * QST + c * 8), Vh + g);
            cp16(smem_u32(vl + r * QST + c * 8), Vl + g);
        }
        cp_commit();
    };

    int t8 = lane >> 3;
    int rA = (t8 & 1) * 8 + (lane & 7), cA = (t8 >> 1) * 8;
    int rB = (t8 >> 1) * 8 + (lane & 7), cB = (t8 & 1) * 8;
    int rV = (t8 & 1) * 8 + (lane & 7), cV = (t8 >> 1) * 8;   // trans-ldmatrix coords
    int grp = lane >> 2, q4 = lane & 3;

    float oacc[4][4] = {};
    float m0 = -1e30f, m1 = -1e30f, l0 = 0.0f, l1 = 0.0f;
    uint32_t qfh[2][4], qfl[2][4];

    load_chunk(0, 0);
    for (int p = 0; p < 8; p++) {
        if (p < 7) { load_chunk(p + 1, (p + 1) & 1); cp_wait1(); }
        else cp_wait0();
        __syncthreads();
        if (p == 0) {
            #pragma unroll
            for (int kk = 0; kk < 2; kk++) {
                ldm4(qfh[kk], smem_u32(sQh + (wid * 16 + rA) * QST + kk * 16 + cA));
                ldm4(qfl[kk], smem_u32(sQl + (wid * 16 + rA) * QST + kk * 16 + cA));
            }
        }
        bf16* kh = sK + (p & 1) * KBUF;
        bf16* kl = kh + 128 * QST;
        bf16* vh = kl + 128 * QST;
        bf16* vl = vh + 128 * QST;

        float sacc[16][4];
        #pragma unroll
        for (int t = 0; t < 16; t++) { sacc[t][0] = 0; sacc[t][1] = 0; sacc[t][2] = 0; sacc[t][3] = 0; }
        #pragma unroll
        for (int nt2 = 0; nt2 < 8; nt2++) {
            #pragma unroll
            for (int kk = 0; kk < 2; kk++) {
                uint32_t bh4[4], bl4[4];
                ldm4(bh4, smem_u32(kh + (nt2 * 16 + rB) * QST + kk * 16 + cB));
                ldm4(bl4, smem_u32(kl + (nt2 * 16 + rB) * QST + kk * 16 + cB));
                #pragma unroll
                for (int hf = 0; hf < 2; hf++) {
                    mma16816(sacc[2 * nt2 + hf], qfh[kk], &bh4[2 * hf]);
                    mma16816(sacc[2 * nt2 + hf], qfh[kk], &bl4[2 * hf]);
                    mma16816(sacc[2 * nt2 + hf], qfl[kk], &bh4[2 * hf]);
                }
            }
        }
        // ---- online softmax (log2 domain) ----
        float cm0 = -1e30f, cm1 = -1e30f;
        #pragma unroll
        for (int t = 0; t < 16; t++) {
            sacc[t][0] *= SC; sacc[t][1] *= SC;
            sacc[t][2] *= SC; sacc[t][3] *= SC;
            cm0 = fmaxf(cm0, fmaxf(sacc[t][0], sacc[t][1]));
            cm1 = fmaxf(cm1, fmaxf(sacc[t][2], sacc[t][3]));
        }
        cm0 = fmaxf(cm0, __shfl_xor_sync(0xffffffffu, cm0, 1));
        cm0 = fmaxf(cm0, __shfl_xor_sync(0xffffffffu, cm0, 2));
        cm1 = fmaxf(cm1, __shfl_xor_sync(0xffffffffu, cm1, 1));
        cm1 = fmaxf(cm1, __shfl_xor_sync(0xffffffffu, cm1, 2));
        float mn0 = fmaxf(m0, cm0), mn1 = fmaxf(m1, cm1);
        float c0 = ex2(m0 - mn0), c1 = ex2(m1 - mn1);
        m0 = mn0; m1 = mn1;
        float rs0 = 0.0f, rs1 = 0.0f;
        #pragma unroll
        for (int t = 0; t < 16; t++) {
            sacc[t][0] = ex2(sacc[t][0] - mn0);
            sacc[t][1] = ex2(sacc[t][1] - mn0);
            sacc[t][2] = ex2(sacc[t][2] - mn1);
            sacc[t][3] = ex2(sacc[t][3] - mn1);
            rs0 += sacc[t][0] + sacc[t][1];
            rs1 += sacc[t][2] + sacc[t][3];
        }
        l0 = l0 * c0 + rs0;
        l1 = l1 * c1 + rs1;
        #pragma unroll
        for (int n = 0; n < 4; n++) {
            oacc[n][0] *= c0; oacc[n][1] *= c0;
            oacc[n][2] *= c1; oacc[n][3] *= c1;
        }
        // ---- O += P V : B fragment from V[k][d] via trans ldmatrix ----
        #pragma unroll
        for (int kt = 0; kt < 8; kt++) {
            uint32_t pah4[4], pal4[4];
            pah4[0] = pk2(sacc[2 * kt][0],     sacc[2 * kt][1],     pal4[0]);
            pah4[1] = pk2(sacc[2 * kt][2],     sacc[2 * kt][3],     pal4[1]);
            pah4[2] = pk2(sacc[2 * kt + 1][0], sacc[2 * kt + 1][1], pal4[2]);
            pah4[3] = pk2(sacc[2 * kt + 1][2], sacc[2 * kt + 1][3], pal4[3]);
            #pragma unroll
            for (int np = 0; np < 2; np++) {
                uint32_t vb_h[4], vb_l[4];
                ldm4t(vb_h, smem_u32(vh + (kt * 16 + rV) * QST + np * 16 + cV));
                ldm4t(vb_l, smem_u32(vl + (kt * 16 + rV) * QST + np * 16 + cV));
                #pragma unroll
                for (int hf = 0; hf < 2; hf++) {
                    mma16816(oacc[2 * np + hf], pah4, &vb_h[2 * hf]);
                    mma16816(oacc[2 * np + hf], pah4, &vb_l[2 * hf]);
                    mma16816(oacc[2 * np + hf], pal4, &vb_h[2 * hf]);
                }
            }
        }
        __syncthreads();
    }
    l0 += __shfl_xor_sync(0xffffffffu, l0, 1);
    l0 += __shfl_xor_sync(0xffffffffu, l0, 2);
    l1 += __shfl_xor_sync(0xffffffffu, l1, 1);
    l1 += __shfl_xor_sync(0xffffffffu, l1, 2);
    float i0 = 1.0f / l0, i1 = 1.0f / l1;
    size_t obase = (size_t)(b * 1024 + q0) * 256 + h * 32;
    #pragma unroll
    for (int n = 0; n < 4; n++) {
        int row = wid * 16 + grp;
        int col = n * 8 + q4 * 2;
        uint32_t lo0, lo1;
        uint32_t h0 = pk2(oacc[n][0] * i0, oacc[n][1] * i0, lo0);
        uint32_t h1 = pk2(oacc[n][2] * i1, oacc[n][3] * i1, lo1);
        *(uint32_t*)&Oh[obase + (size_t)row * 256 + col]       = h0;
        *(uint32_t*)&Ol[obase + (size_t)row * 256 + col]       = lo0;
        *(uint32_t*)&Oh[obase + (size_t)(row + 8) * 256 + col] = h1;
        *(uint32_t*)&Ol[obase + (size_t)(row + 8) * 256 + col] = lo1;
    }
}

// ------------------------- GAT pieces -------------------------
__global__ void att_prep(const float* __restrict__ hbuf,
                         const float* __restrict__ atts, const float* __restrict__ attd)
{
    int n = blockIdx.x * 8 + (threadIdx.x >> 5);
    int lane = threadIdx.x & 31;
    const float4* hp = (const float4*)(hbuf + (size_t)n * Dd + lane * 8);
    float4 a = hp[0], b = hp[1];
    const float4* pa = (const float4*)(atts + lane * 8);
    const float4* pb = (const float4*)(attd + lane * 8);
    float4 wa0 = pa[0], wa1 = pa[1];
    float4 wb0 = pb[0], wb1 = pb[1];
    float s1 = a.x * wa0.x + a.y * wa0.y + a.z * wa0.z + a.w * wa0.w
             + b.x * wa1.x + b.y * wa1.y + b.z * wa1.z + b.w * wa1.w;
    float s2 = a.x * wb0.x + a.y * wb0.y + a.z * wb0.z + a.w * wb0.w
             + b.x * wb1.x + b.y * wb1.y + b.z * wb1.z + b.w * wb1.w;
    s1 += __shfl_xor_sync(0xffffffffu, s1, 1);
    s1 += __shfl_xor_sync(0xffffffffu, s1, 2);
    s2 += __shfl_xor_sync(0xffffffffu, s2, 1);
    s2 += __shfl_xor_sync(0xffffffffu, s2, 2);
    if ((lane & 3) == 0) {
        g_as[n * 8 + (lane >> 2)] = s1;
        g_ad[n * 8 + (lane >> 2)] = s2;
    }
}

#define DEGCAP 96
__global__ void __launch_bounds__(256)
gat_aggr(const float* __restrict__ hbuf, const float* __restrict__ bias,
         float* __restrict__ outF, bf16* __restrict__ outH, bf16* __restrict__ outL)
{
    __shared__ float salpha[8][DEGCAP][8];
    int wid = threadIdx.x >> 5, lane = threadIdx.x & 31;
    int d = blockIdx.x * 8 + wid;
    int base = g_rowptr[d];
    int deg  = g_rowptr[d + 1] - base;

    int hd = lane & 7;
    float adv = g_ad[d * 8 + hd];
    float m = -1e30f;
    for (int i = lane >> 3; i < deg; i += 4) {
        int s = g_col[base + i];
        float v = g_as[s * 8 + hd] + adv;
        v = v > 0.0f ? v : 0.2f * v;
        m = fmaxf(m, v);
    }
    m = fmaxf(m, __shfl_xor_sync(0xffffffffu, m, 8));
    m = fmaxf(m, __shfl_xor_sync(0xffffffffu, m, 16));
    float sum = 0.0f;
    for (int i = lane >> 3; i < deg; i += 4) {
        int s = g_col[base + i];
        float v = g_as[s * 8 + hd] + adv;
        v = v > 0.0f ? v : 0.2f * v;
        float p = __expf(v - m);
        if (i < DEGCAP) salpha[wid][i][hd] = p;
        sum += p;
    }
    sum += __shfl_xor_sync(0xffffffffu, sum, 8);
    sum += __shfl_xor_sync(0xffffffffu, sum, 16);
    __syncwarp();

    int hd2 = lane >> 2;
    float m2  = __shfl_sync(0xffffffffu, m, hd2);
    float is2 = 1.0f / __shfl_sync(0xffffffffu, sum, hd2);
    float adv2 = g_ad[d * 8 + hd2];
    float acc[8] = {};

    auto getp = [&](int i, int s) -> float {
        if (i < DEGCAP) return salpha[wid][i][hd2];
        float v = g_as[s * 8 + hd2] + adv2;
        v = v > 0.0f ? v : 0.2f * v;
        return __expf(v - m2);
    };
    int i = 0;
    for (; i + 2 <= deg; i += 2) {
        int s0 = g_col[base + i], s1 = g_col[base + i + 1];
        float al0 = getp(i, s0) * is2;
        float al1 = getp(i + 1, s1) * is2;
        const float4* h0 = (const float4*)(hbuf + (size_t)s0 * Dd + lane * 8);
        const float4* h1 = (const float4*)(hbuf + (size_t)s1 * Dd + lane * 8);
        float4 a0 = h0[0], b0 = h0[1];
        float4 a1 = h1[0], b1 = h1[1];
        acc[0] += al0 * a0.x + al1 * a1.x;  acc[1] += al0 * a0.y + al1 * a1.y;
        acc[2] += al0 * a0.z + al1 * a1.z;  acc[3] += al0 * a0.w + al1 * a1.w;
        acc[4] += al0 * b0.x + al1 * b1.x;  acc[5] += al0 * b0.y + al1 * b1.y;
        acc[6] += al0 * b0.z + al1 * b1.z;  acc[7] += al0 * b0.w + al1 * b1.w;
    }
    if (i < deg) {
        int s0 = g_col[base + i];
        float al0 = getp(i, s0) * is2;
        const float4* h0 = (const float4*)(hbuf + (size_t)s0 * Dd + lane * 8);
        float4 a0 = h0[0], b0 = h0[1];
        acc[0] += al0 * a0.x;  acc[1] += al0 * a0.y;
        acc[2] += al0 * a0.z;  acc[3] += al0 * a0.w;
        acc[4] += al0 * b0.x;  acc[5] += al0 * b0.y;
        acc[6] += al0 * b0.z;  acc[7] += al0 * b0.w;
    }
    size_t rb = (size_t)d * Dd + lane * 8;
    #pragma unroll
    for (int j = 0; j < 8; j += 2) {
        float v0 = fmaxf(acc[j]     + bias[lane * 8 + j],     0.0f);
        float v1 = fmaxf(acc[j + 1] + bias[lane * 8 + j + 1], 0.0f);
        *(float2*)&outF[rb + j] = make_float2(v0, v1);
        uint32_t lo;
        uint32_t hi = pk2(v0, v1, lo);
        *(uint32_t*)&outH[rb + j] = hi;
        *(uint32_t*)&outL[rb + j] = lo;
    }
}

// ------------------------- residual + layernorm -------------------------
__global__ void ln_res(const float* __restrict__ xin, const float* __restrict__ add,
                       float* __restrict__ xout, const float* __restrict__ w,
                       const float* __restrict__ b,
                       bf16* __restrict__ oh, bf16* __restrict__ ol)
{
    int row = blockIdx.x * 8 + (threadIdx.x >> 5);
    int lane = threadIdx.x & 31;
    const float* xr = xin + (size_t)row * Dd;
    const float* ar = add + (size_t)row * Dd;
    float v[8];
    float s = 0.0f;
    #pragma unroll
    for (int j = 0; j < 8; j++) {
        int d = lane + j * 32;
        v[j] = xr[d] + ar[d];
        s += v[j];
    }
    s = warpSum(s);
    float mean = s * (1.0f / 256.0f);
    float var = 0.0f;
    #pragma unroll
    for (int j = 0; j < 8; j++) {
        float dv = v[j] - mean;
        var += dv * dv;
    }
    var = warpSum(var) * (1.0f / 256.0f);
    float inv = rsqrtf(var + 1e-5f);
    float* orow = xout + (size_t)row * Dd;
    #pragma unroll
    for (int j = 0; j < 8; j++) {
        int d = lane + j * 32;
        float o = (v[j] - mean) * inv * w[d] + b[d];
        orow[d] = o;
        bf16 h = __float2bfloat16(o);
        oh[(size_t)row * Dd + d] = h;
        ol[(size_t)row * Dd + d] = __float2bfloat16(o - __bfloat162float(h));
    }
}

// ------------------------- prediction head -------------------------
__global__ void pred_kernel(const float* __restrict__ xin, const float* __restrict__ pw,
                            const float* __restrict__ pb, float* __restrict__ out)
{
    int gw = (blockIdx.x * 256 + threadIdx.x) >> 5;
    int lane = threadIdx.x & 31;
    if (gw >= Nn) return;
    const float* xr = xin + (size_t)gw * Dd;
    float a0 = 0.0f, a1 = 0.0f, a2 = 0.0f;
    #pragma unroll
    for (int j = 0; j < 8; j++) {
        int d = lane + j * 32;
        float xv = xr[d];
        a0 += xv * pw[d];
        a1 += xv * pw[Dd + d];
        a2 += xv * pw[2 * Dd + d];
    }
    a0 = warpSum(a0);
    a1 = warpSum(a1);
    a2 = warpSum(a2);
    if (lane == 0) {
        out[gw * 3 + 0] = a0 + pb[0];
        out[gw * 3 + 1] = a1 + pb[1];
        out[gw * 3 + 2] = a2 + pb[2];
    }
}

// ------------------------- host orchestration -------------------------
#define SMEM_G (4 * 128 * 40 * 2 * 2)
#define SMEM_F ((2 * 128 * 40 + 2 * 4 * 128 * 40) * 2)    // 102400 B

extern "C" void kernel_launch(void* const* d_in, const int* in_sizes, int n_in,
                              void* d_out, int out_size)
{
    const float* x      = (const float*)d_in[0];
    const int*   ei     = (const int*)d_in[1];
    const float* W0     = (const float*)d_in[3];
    const float* W12    = (const float*)d_in[4];
    const float* att_s  = (const float*)d_in[5];
    const float* att_d  = (const float*)d_in[6];
    const float* gbias  = (const float*)d_in[7];
    const float* qkv_w  = (const float*)d_in[8];
    const float* qkv_b  = (const float*)d_in[9];
    const float* out_w  = (const float*)d_in[10];
    const float* out_b  = (const float*)d_in[11];
    const float* ln1w   = (const float*)d_in[12];
    const float* ln1b   = (const float*)d_in[13];
    const float* ln2w   = (const float*)d_in[14];
    const float* ln2b   = (const float*)d_in[15];
    const float* ff1w   = (const float*)d_in[16];
    const float* ff1b   = (const float*)d_in[17];
    const float* ff2w   = (const float*)d_in[18];
    const float* ff2b   = (const float*)d_in[19];
    const float* predw  = (const float*)d_in[20];
    const float* predb  = (const float*)d_in[21];
    float* out = (float*)d_out;

    int E = in_sizes[1] / 2;
    int Etot = E + Nn;

    cudaFuncSetAttribute((const void*)hgemm<0>, cudaFuncAttributeMaxDynamicSharedMemorySize, SMEM_G);
    cudaFuncSetAttribute((const void*)hgemm<1>, cudaFuncAttributeMaxDynamicSharedMemorySize, SMEM_G);
    cudaFuncSetAttribute((const void*)flash_attn, cudaFuncAttributeMaxDynamicSharedMemorySize, SMEM_F);

    float *ph, *px;
    bf16 *pah, *pal, *pxh, *pxl, *pwh, *pwl, *pqh, *pql;
    cudaGetSymbolAddress((void**)&ph,    g_h);
    cudaGetSymbolAddress((void**)&px,    g_x);
    cudaGetSymbolAddress((void**)&pah,   g_ah);
    cudaGetSymbolAddress((void**)&pal,   g_al);
    cudaGetSymbolAddress((void**)&pxh,   g_xh);
    cudaGetSymbolAddress((void**)&pxl,   g_xl);
    cudaGetSymbolAddress((void**)&pwh,   g_wh);
    cudaGetSymbolAddress((void**)&pwl,   g_wl);
    cudaGetSymbolAddress((void**)&pqh,   g_qh);
    cudaGetSymbolAddress((void**)&pql,   g_ql);

    // ---------------- one-shot weight conversion (all 11 matrices) ----------------
    WSegs ws;
    ws.src[0]  = W0;                         ws.off[0]  = WO_W0;    ws.n4[0]  = 16384 / 4;
    ws.src[1]  = W12;                        ws.off[1]  = WO_W1;    ws.n4[1]  = 65536 / 4;
    ws.src[2]  = W12 + 65536;                ws.off[2]  = WO_W2;    ws.n4[2]  = 65536 / 4;
    ws.src[3]  = qkv_w;                      ws.off[3]  = WO_QKV0;  ws.n4[3]  = 196608 / 4;
    ws.src[4]  = qkv_w + 196608;             ws.off[4]  = WO_QKV1;  ws.n4[4]  = 196608 / 4;
    ws.src[5]  = out_w;                      ws.off[5]  = WO_OUT0;  ws.n4[5]  = 65536 / 4;
    ws.src[6]  = out_w + 65536;              ws.off[6]  = WO_OUT1;  ws.n4[6]  = 65536 / 4;
    ws.src[7]  = ff1w;                       ws.off[7]  = WO_FF1_0; ws.n4[7]  = 524288 / 4;
    ws.src[8]  = ff1w + 524288;              ws.off[8]  = WO_FF1_1; ws.n4[8]  = 524288 / 4;
    ws.src[9]  = ff2w;                       ws.off[9]  = WO_FF2_0; ws.n4[9]  = 524288 / 4;
    ws.src[10] = ff2w + 524288;              ws.off[10] = WO_FF2_1; ws.n4[10] = 524288 / 4;
    cvt_weights<<<dim3(512, 11), 256>>>(ws);

    // ---------------- CSR build (once) ----------------
    csr_init<<<Nn / 256, 256>>>();
    csr_count<<<(E + 255) / 256, 256>>>(ei, E);
    csr_scan<<<1, 1024>>>();
    csr_fill<<<(Etot + 255) / 256, 256>>>(ei, E, Etot);

    // ---------------- GAT layers ----------------
    cvt_hilo<<<(Nn * 64 / 4 + 255) / 256, 256>>>(x, pxh, pxl, Nn * 64 / 4);
    int curK = 64;
    const int woff[3] = {WO_W0, WO_W1, WO_W2};
    for (int l = 0; l < 3; l++) {
        hgemm<0><<<dim3(Dd / 128, Nn / 128), 256, SMEM_G>>>(
            pxh, pxl, curK, pwh + woff[l], pwl + woff[l], curK,
            nullptr, ph, nullptr, nullptr, Dd, curK, 0);
        att_prep<<<Nn / 8, 256>>>(ph, att_s + l * Dd, att_d + l * Dd);
        gat_aggr<<<Nn / 8, 256>>>(ph, gbias + l * Dd, px, pxh, pxl);
        curK = Dd;
    }

    // ---------------- transformer layers ----------------
    const float scale = 0.17677669529663687f;  // 1/sqrt(32)
    const int qoff[2] = {WO_QKV0, WO_QKV1};
    const int ooff[2] = {WO_OUT0, WO_OUT1};
    const int f1off[2] = {WO_FF1_0, WO_FF1_1};
    const int f2off[2] = {WO_FF2_0, WO_FF2_1};
    for (int i = 0; i < 2; i++) {
        hgemm<1><<<dim3(768 / 128, Nn / 128), 256, SMEM_G>>>(
            pxh, pxl, Dd, pwh + qoff[i], pwl + qoff[i], Dd,
            qkv_b + i * 768, nullptr, pqh, pql, 768, Dd, 0);
        flash_attn<<<dim3(8, 64), 256, SMEM_F>>>(pqh, pql, pah, pal, scale);
        hgemm<0><<<dim3(Dd / 128, Nn / 128), 256, SMEM_G>>>(
            pah, pal, Dd, pwh + ooff[i], pwl + ooff[i], Dd,
            out_b + i * Dd, ph, nullptr, nullptr, Dd, Dd, 0);
        ln_res<<<Nn / 8, 256>>>(px, ph, px, ln1w + i * Dd, ln1b + i * Dd, pxh, pxl);
        hgemm<1><<<dim3(DFF / 128, Nn / 128), 256, SMEM_G>>>(
            pxh, pxl, Dd, pwh + f1off[i], pwl + f1off[i], Dd,
            ff1b + i * DFF, nullptr, pah, pal, DFF, Dd, 1);
        hgemm<0><<<dim3(Dd / 128, Nn / 128), 256, SMEM_G>>>(
            pah, pal, DFF, pwh + f2off[i], pwl + f2off[i], DFF,
            ff2b + i * Dd, ph, nullptr, nullptr, Dd, DFF, 0);
        ln_res<<<Nn / 8, 256>>>(px, ph, px, ln2w + i * Dd, ln2b + i * Dd, pxh, pxl);
    }

    // ---------------- prediction head ----------------
    pred_kernel<<<(Nn * 32 + 255) / 256, 256>>>(px, predw, predb, out);
}

// round 8
// speedup vs baseline: 2.9424x; 1.0094x over previous
#include <cuda_runtime.h>
#include <cuda_bf16.h>
#include <math.h>
#include <stdint.h>

using bf16 = __nv_bfloat16;

#define Nn   8192
#define Bb   8
#define Ll   1024
#define Hh   8
#define Cc   32
#define Dd   256
#define DFF  2048
#define Emax 262144
#define ETOTmax (Emax + Nn)
#define WTOT 2768896

// ------------------------- scratch (static device globals) -------------------------
__device__ float    g_h   [Nn * Dd];
__device__ float    g_x   [Nn * Dd];
__device__ float    g_as  [Nn * Hh];
__device__ float    g_ad  [Nn * Hh];
__device__ int      g_cnt [Nn];
__device__ int      g_rowptr[Nn + 1];
__device__ int      g_wpos[Nn];
__device__ int      g_col [ETOTmax];

__device__ bf16 g_ah[Nn * DFF];               // A hi (max 8192x2048)
__device__ bf16 g_al[Nn * DFF];               // A lo
__device__ bf16 g_xh[Nn * Dd];                // residual stream hi
__device__ bf16 g_xl[Nn * Dd];
__device__ bf16 g_wh[WTOT];                   // all weights hi
__device__ bf16 g_wl[WTOT];                   // all weights lo
__device__ bf16 g_qh[Nn * 3 * Dd];            // qkv hi
__device__ bf16 g_ql[Nn * 3 * Dd];

// weight arena offsets
#define WO_W0    0
#define WO_W1    16384
#define WO_W2    81920
#define WO_QKV0  147456
#define WO_QKV1  344064
#define WO_OUT0  540672
#define WO_OUT1  606208
#define WO_FF1_0 671744
#define WO_FF1_1 1196032
#define WO_FF2_0 1720320
#define WO_FF2_1 2244608

// ------------------------- helpers -------------------------
__device__ __forceinline__ uint32_t smem_u32(const void* p) {
    uint32_t a;
    asm("{ .reg .u64 t; cvta.to.shared.u64 t, %1; cvt.u32.u64 %0, t; }" : "=r"(a) : "l"(p));
    return a;
}
__device__ __forceinline__ void cp16(uint32_t s, const void* g) {
    asm volatile("cp.async.cg.shared.global [%0], [%1], 16;" :: "r"(s), "l"(g));
}
__device__ __forceinline__ void cp_commit() {
    asm volatile("cp.async.commit_group;" ::: "memory");
}
__device__ __forceinline__ void cp_wait0() {
    asm volatile("cp.async.wait_group 0;" ::: "memory");
}
__device__ __forceinline__ void cp_wait1() {
    asm volatile("cp.async.wait_group 1;" ::: "memory");
}
__device__ __forceinline__ void ldm4(uint32_t* r, uint32_t addr) {
    asm volatile("ldmatrix.sync.aligned.m8n8.x4.shared.b16 {%0,%1,%2,%3}, [%4];"
        : "=r"(r[0]), "=r"(r[1]), "=r"(r[2]), "=r"(r[3]) : "r"(addr));
}
__device__ __forceinline__ void ldm4t(uint32_t* r, uint32_t addr) {
    asm volatile("ldmatrix.sync.aligned.m8n8.x4.trans.shared.b16 {%0,%1,%2,%3}, [%4];"
        : "=r"(r[0]), "=r"(r[1]), "=r"(r[2]), "=r"(r[3]) : "r"(addr));
}
__device__ __forceinline__ void mma16816(float* d, const uint32_t* a, const uint32_t* b) {
    asm volatile(
        "mma.sync.aligned.m16n8k16.row.col.f32.bf16.bf16.f32 "
        "{%0,%1,%2,%3}, {%4,%5,%6,%7}, {%8,%9}, {%0,%1,%2,%3};"
        : "+f"(d[0]), "+f"(d[1]), "+f"(d[2]), "+f"(d[3])
        : "r"(a[0]), "r"(a[1]), "r"(a[2]), "r"(a[3]), "r"(b[0]), "r"(b[1]));
}
__device__ __forceinline__ float warpSum(float v) {
    #pragma unroll
    for (int o = 16; o > 0; o >>= 1) v += __shfl_xor_sync(0xffffffffu, v, o);
    return v;
}
__device__ __forceinline__ float ex2(float x) {
    float y;
    asm("ex2.approx.f32 %0, %1;" : "=f"(y) : "f"(x));
    return y;
}
// fast pack: two fp32 -> bf16x2 hi reg + residual bf16x2 lo reg
__device__ __forceinline__ uint32_t pk2(float a, float b, uint32_t& lo) {
    __nv_bfloat162 hh = __floats2bfloat162_rn(a, b);
    uint32_t h = *(uint32_t*)&hh;
    float ha = __uint_as_float(h << 16);
    float hb = __uint_as_float(h & 0xffff0000u);
    __nv_bfloat162 ll = __floats2bfloat162_rn(a - ha, b - hb);
    lo = *(uint32_t*)&ll;
    return h;
}

// ------------------------- conversions -------------------------
__global__ void cvt_hilo(const float* __restrict__ in, bf16* __restrict__ hi,
                         bf16* __restrict__ lo, int n4)
{
    int i = blockIdx.x * 256 + threadIdx.x;
    if (i >= n4) return;
    float4 x = ((const float4*)in)[i];
    uint32_t l0, l1;
    uint32_t h0 = pk2(x.x, x.y, l0);
    uint32_t h1 = pk2(x.z, x.w, l1);
    ((uint32_t*)hi)[2 * i]     = h0;
    ((uint32_t*)hi)[2 * i + 1] = h1;
    ((uint32_t*)lo)[2 * i]     = l0;
    ((uint32_t*)lo)[2 * i + 1] = l1;
}

// convert all weight matrices in one launch: grid (512, NSEG)
struct WSegs {
    const float* src[11];
    int off[11];
    int n4[11];
};
__global__ void cvt_weights(WSegs w)
{
    int s = blockIdx.y;
    int i = blockIdx.x * 256 + threadIdx.x;
    if (i >= w.n4[s]) return;
    float4 x = ((const float4*)w.src[s])[i];
    uint32_t l0, l1;
    uint32_t h0 = pk2(x.x, x.y, l0);
    uint32_t h1 = pk2(x.z, x.w, l1);
    uint32_t* dh = (uint32_t*)(g_wh + w.off[s]);
    uint32_t* dl = (uint32_t*)(g_wl + w.off[s]);
    dh[2 * i]     = h0;
    dh[2 * i + 1] = h1;
    dl[2 * i]     = l0;
    dl[2 * i + 1] = l1;
}

// ------------------------- CSR build (once) -------------------------
__global__ void csr_init() {
    int i = blockIdx.x * 256 + threadIdx.x;
    if (i < Nn) g_cnt[i] = 1;                 // self loop
}
__global__ void csr_count(const int* __restrict__ ei, int E) {
    int i = blockIdx.x * 256 + threadIdx.x;
    if (i < E) atomicAdd(&g_cnt[ei[E + i]], 1);
}
__global__ void csr_scan() {                  // single block, 1024 threads
    __shared__ int sdata[1024];
    int tid = threadIdx.x;
    int base = tid * 8;
    int loc[8];
    int s = 0;
    #pragma unroll
    for (int j = 0; j < 8; j++) { loc[j] = g_cnt[base + j]; s += loc[j]; }
    sdata[tid] = s;
    __syncthreads();
    for (int off = 1; off < 1024; off <<= 1) {
        int v = (tid >= off) ? sdata[tid - off] : 0;
        __syncthreads();
        sdata[tid] += v;
        __syncthreads();
    }
    int run = sdata[tid] - s;
    #pragma unroll
    for (int j = 0; j < 8; j++) {
        g_rowptr[base + j] = run;
        g_wpos[base + j] = run;
        run += loc[j];
    }
    if (tid == 1023) g_rowptr[Nn] = run;
}
__global__ void csr_fill(const int* __restrict__ ei, int E, int Etot) {
    int i = blockIdx.x * 256 + threadIdx.x;
    if (i >= Etot) return;
    int s, d;
    if (i < E) { s = ei[i]; d = ei[E + i]; } else { s = d = i - E; }
    int pos = atomicAdd(&g_wpos[d], 1);
    g_col[pos] = s;
}

// ------------------------- HMMA split-bf16 GEMM (16 warps, 4x4 warp grid) -------------------------
template<int OUT>
__global__ void __launch_bounds__(512, 1)
hgemm(const bf16* __restrict__ aH, const bf16* __restrict__ aL, int lda,
      const bf16* __restrict__ bH, const bf16* __restrict__ bL, int ldb,
      const float* __restrict__ bias, float* __restrict__ C,
      bf16* __restrict__ Ch, bf16* __restrict__ Cl, int ldc,
      int K, int relu)
{
    constexpr int MT = 2, NT8 = 4;            // warp tile 32x32
    constexpr int SST = 40;
    constexpr int ATILE = 128 * SST;
    constexpr int BTILE = 128 * SST;
    constexpr int STAGE = 2 * ATILE + 2 * BTILE;

    extern __shared__ bf16 sm[];

    int tid = threadIdx.x;
    int wid = tid >> 5, lane = tid & 31;
    int wm = wid & 3, wn = wid >> 2;          // 4x4 warp grid
    int m0 = blockIdx.y * 128;
    int n0 = blockIdx.x * 128;

    float acc[MT][NT8][4] = {};
    int P = K >> 5;

    int lr = tid >> 2, lc = tid & 3;          // 512 threads: one 16B chunk each

    auto load_panel = [&](int p, int s) {
        bf16* Ah = sm + s * STAGE;
        bf16* Al = Ah + ATILE;
        bf16* Bh = Al + ATILE;
        bf16* Bl = Bh + BTILE;
        int k0 = p * 32;
        size_t ga = (size_t)(m0 + lr) * lda + k0 + lc * 8;
        cp16(smem_u32(Ah + lr * SST + lc * 8), aH + ga);
        cp16(smem_u32(Al + lr * SST + lc * 8), aL + ga);
        size_t gb = (size_t)(n0 + lr) * ldb + k0 + lc * 8;
        cp16(smem_u32(Bh + lr * SST + lc * 8), bH + gb);
        cp16(smem_u32(Bl + lr * SST + lc * 8), bL + gb);
        cp_commit();
    };

    int t8 = lane >> 3;
    int rA = (t8 & 1) * 8 + (lane & 7), cA = (t8 >> 1) * 8;
    int rB = (t8 >> 1) * 8 + (lane & 7), cB = (t8 & 1) * 8;

    auto compute = [&](int s) {
        bf16* Ah = sm + s * STAGE;
        bf16* Al = Ah + ATILE;
        bf16* Bh = Al + ATILE;
        bf16* Bl = Bh + BTILE;
        #pragma unroll
        for (int kk = 0; kk < 2; kk++) {
            int k16 = kk * 16;
            uint32_t ah[MT][4], al[MT][4], bh[NT8][2], bl[NT8][2];
            #pragma unroll
            for (int mt = 0; mt < MT; mt++) {
                int row = wm * 32 + mt * 16 + rA;
                ldm4(ah[mt], smem_u32(Ah + row * SST + k16 + cA));
                ldm4(al[mt], smem_u32(Al + row * SST + k16 + cA));
            }
            #pragma unroll
            for (int nt2 = 0; nt2 < NT8 / 2; nt2++) {
                int row = wn * 32 + nt2 * 16 + rB;
                uint32_t r4[4];
                ldm4(r4, smem_u32(Bh + row * SST + k16 + cB));
                bh[2 * nt2][0] = r4[0]; bh[2 * nt2][1] = r4[1];
                bh[2 * nt2 + 1][0] = r4[2]; bh[2 * nt2 + 1][1] = r4[3];
                ldm4(r4, smem_u32(Bl + row * SST + k16 + cB));
                bl[2 * nt2][0] = r4[0]; bl[2 * nt2][1] = r4[1];
                bl[2 * nt2 + 1][0] = r4[2]; bl[2 * nt2 + 1][1] = r4[3];
            }
            #pragma unroll
            for (int mt = 0; mt < MT; mt++) {
                #pragma unroll
                for (int nt = 0; nt < NT8; nt++) {
                    mma16816(acc[mt][nt], ah[mt], bh[nt]);
                    mma16816(acc[mt][nt], ah[mt], bl[nt]);
                    mma16816(acc[mt][nt], al[mt], bh[nt]);
                }
            }
        }
    };

    load_panel(0, 0);
    for (int p = 0; p < P; p++) {
        if (p + 1 < P) {
            load_panel(p + 1, (p + 1) & 1);
            cp_wait1();
        } else {
            cp_wait0();
        }
        __syncthreads();
        compute(p & 1);
        __syncthreads();
    }

    int grp = lane >> 2, q4 = lane & 3;
    #pragma unroll
    for (int mt = 0; mt < MT; mt++) {
        #pragma unroll
        for (int nt = 0; nt < NT8; nt++) {
            int row = m0 + wm * 32 + mt * 16 + grp;
            int col = n0 + wn * 32 + nt * 8 + q4 * 2;
            float* a4 = acc[mt][nt];
            float b0 = 0.0f, b1 = 0.0f;
            if (bias) { b0 = bias[col]; b1 = bias[col + 1]; }
            float v0 = a4[0] + b0, v1 = a4[1] + b1;
            float v2 = a4[2] + b0, v3 = a4[3] + b1;
            if (relu) {
                v0 = fmaxf(v0, 0.0f); v1 = fmaxf(v1, 0.0f);
                v2 = fmaxf(v2, 0.0f); v3 = fmaxf(v3, 0.0f);
            }
            if (OUT == 0) {
                *(float2*)&C[(size_t)row * ldc + col]       = make_float2(v0, v1);
                *(float2*)&C[(size_t)(row + 8) * ldc + col] = make_float2(v2, v3);
            } else {
                uint32_t lo0, lo1;
                uint32_t h0 = pk2(v0, v1, lo0);
                uint32_t h1 = pk2(v2, v3, lo1);
                *(uint32_t*)&Ch[(size_t)row * ldc + col]       = h0;
                *(uint32_t*)&Cl[(size_t)row * ldc + col]       = lo0;
                *(uint32_t*)&Ch[(size_t)(row + 8) * ldc + col] = h1;
                *(uint32_t*)&Cl[(size_t)(row + 8) * ldc + col] = lo1;
            }
        }
    }
}

// ------------------------- fused flash attention (V direct, trans-ldmatrix) -------------------------
__global__ void __launch_bounds__(256, 1)
flash_attn(const bf16* __restrict__ qkh, const bf16* __restrict__ qkl,
           bf16* __restrict__ Oh, bf16* __restrict__ Ol, float scale)
{
    constexpr int QST = 40;
    constexpr int KBUF = 4 * 128 * QST;   // kh, kl, vh, vl each [128][40]
    extern __shared__ bf16 fsm[];
    bf16* sQh = fsm;
    bf16* sQl = sQh + 128 * QST;
    bf16* sK  = sQl + 128 * QST;

    const float SC = scale * 1.4426950408889634f;

    int tid = threadIdx.x, wid = tid >> 5, lane = tid & 31;
    int z = blockIdx.y, b = z >> 3, h = z & 7;
    int q0 = blockIdx.x * 128;

    const bf16* Qh = qkh + (size_t)b * 1024 * 768 + h * 32;
    const bf16* Ql = qkl + (size_t)b * 1024 * 768 + h * 32;
    const bf16* Kh = Qh + 256;
    const bf16* Kl = Ql + 256;
    const bf16* Vh = Qh + 512;
    const bf16* Vl = Ql + 512;

    for (int idx = tid; idx < 512; idx += 256) {
        int r = idx >> 2, c = idx & 3;
        cp16(smem_u32(sQh + r * QST + c * 8), Qh + (size_t)(q0 + r) * 768 + c * 8);
        cp16(smem_u32(sQl + r * QST + c * 8), Ql + (size_t)(q0 + r) * 768 + c * 8);
    }
    auto load_chunk = [&](int p, int s) {
        bf16* kh = sK + s * KBUF;
        bf16* kl = kh + 128 * QST;
        bf16* vh = kl + 128 * QST;
        bf16* vl = vh + 128 * QST;
        int k0 = p * 128;
        #pragma unroll 2
        for (int idx = tid; idx < 512; idx += 256) {
            int r = idx >> 2, c = idx & 3;
            size_t g = (size_t)(k0 + r) * 768 + c * 8;
            cp16(smem_u32(kh + r * QST + c * 8), Kh + g);
            cp16(smem_u32(kl + r * QST + c * 8), Kl + g);
        }
        #pragma unroll 2
        for (int idx = tid; idx < 512; idx += 256) {
            int r = idx >> 2, c = idx & 3;
            size_t g = (size_t)(k0 + r) * 768 + c * 8;
            cp16(smem_u32(vh + r * QST + c * 8), Vh + g);
            cp16(smem_u32(vl + r * QST + c * 8), Vl + g);
        }
        cp_commit();
    };

    int t8 = lane >> 3;
    int rA = (t8 & 1) * 8 + (lane & 7), cA = (t8 >> 1) * 8;
    int rB = (t8 >> 1) * 8 + (lane & 7), cB = (t8 & 1) * 8;
    int rV = (t8 & 1) * 8 + (lane & 7), cV = (t8 >> 1) * 8;
    int grp = lane >> 2, q4 = lane & 3;

    float oacc[4][4] = {};
    float m0 = -1e30f, m1 = -1e30f, l0 = 0.0f, l1 = 0.0f;
    uint32_t qfh[2][4], qfl[2][4];

    load_chunk(0, 0);
    for (int p = 0; p < 8; p++) {
        if (p < 7) { load_chunk(p + 1, (p + 1) & 1); cp_wait1(); }
        else cp_wait0();
        __syncthreads();
        if (p == 0) {
            #pragma unroll
            for (int kk = 0; kk < 2; kk++) {
                ldm4(qfh[kk], smem_u32(sQh + (wid * 16 + rA) * QST + kk * 16 + cA));
                ldm4(qfl[kk], smem_u32(sQl + (wid * 16 + rA) * QST + kk * 16 + cA));
            }
        }
        bf16* kh = sK + (p & 1) * KBUF;
        bf16* kl = kh + 128 * QST;
        bf16* vh = kl + 128 * QST;
        bf16* vl = vh + 128 * QST;

        float sacc[16][4];
        #pragma unroll
        for (int t = 0; t < 16; t++) { sacc[t][0] = 0; sacc[t][1] = 0; sacc[t][2] = 0; sacc[t][3] = 0; }
        #pragma unroll
        for (int nt2 = 0; nt2 < 8; nt2++) {
            #pragma unroll
            for (int kk = 0; kk < 2; kk++) {
                uint32_t bh4[4], bl4[4];
                ldm4(bh4, smem_u32(kh + (nt2 * 16 + rB) * QST + kk * 16 + cB));
                ldm4(bl4, smem_u32(kl + (nt2 * 16 + rB) * QST + kk * 16 + cB));
                #pragma unroll
                for (int hf = 0; hf < 2; hf++) {
                    mma16816(sacc[2 * nt2 + hf], qfh[kk], &bh4[2 * hf]);
                    mma16816(sacc[2 * nt2 + hf], qfh[kk], &bl4[2 * hf]);
                    mma16816(sacc[2 * nt2 + hf], qfl[kk], &bh4[2 * hf]);
                }
            }
        }
        float cm0 = -1e30f, cm1 = -1e30f;
        #pragma unroll
        for (int t = 0; t < 16; t++) {
            sacc[t][0] *= SC; sacc[t][1] *= SC;
            sacc[t][2] *= SC; sacc[t][3] *= SC;
            cm0 = fmaxf(cm0, fmaxf(sacc[t][0], sacc[t][1]));
            cm1 = fmaxf(cm1, fmaxf(sacc[t][2], sacc[t][3]));
        }
        cm0 = fmaxf(cm0, __shfl_xor_sync(0xffffffffu, cm0, 1));
        cm0 = fmaxf(cm0, __shfl_xor_sync(0xffffffffu, cm0, 2));
        cm1 = fmaxf(cm1, __shfl_xor_sync(0xffffffffu, cm1, 1));
        cm1 = fmaxf(cm1, __shfl_xor_sync(0xffffffffu, cm1, 2));
        float mn0 = fmaxf(m0, cm0), mn1 = fmaxf(m1, cm1);
        float c0 = ex2(m0 - mn0), c1 = ex2(m1 - mn1);
        m0 = mn0; m1 = mn1;
        float rs0 = 0.0f, rs1 = 0.0f;
        #pragma unroll
        for (int t = 0; t < 16; t++) {
            sacc[t][0] = ex2(sacc[t][0] - mn0);
            sacc[t][1] = ex2(sacc[t][1] - mn0);
            sacc[t][2] = ex2(sacc[t][2] - mn1);
            sacc[t][3] = ex2(sacc[t][3] - mn1);
            rs0 += sacc[t][0] + sacc[t][1];
            rs1 += sacc[t][2] + sacc[t][3];
        }
        l0 = l0 * c0 + rs0;
        l1 = l1 * c1 + rs1;
        #pragma unroll
        for (int n = 0; n < 4; n++) {
            oacc[n][0] *= c0; oacc[n][1] *= c0;
            oacc[n][2] *= c1; oacc[n][3] *= c1;
        }
        #pragma unroll
        for (int kt = 0; kt < 8; kt++) {
            uint32_t pah4[4], pal4[4];
            pah4[0] = pk2(sacc[2 * kt][0],     sacc[2 * kt][1],     pal4[0]);
            pah4[1] = pk2(sacc[2 * kt][2],     sacc[2 * kt][3],     pal4[1]);
            pah4[2] = pk2(sacc[2 * kt + 1][0], sacc[2 * kt + 1][1], pal4[2]);
            pah4[3] = pk2(sacc[2 * kt + 1][2], sacc[2 * kt + 1][3], pal4[3]);
            #pragma unroll
            for (int np = 0; np < 2; np++) {
                uint32_t vb_h[4], vb_l[4];
                ldm4t(vb_h, smem_u32(vh + (kt * 16 + rV) * QST + np * 16 + cV));
                ldm4t(vb_l, smem_u32(vl + (kt * 16 + rV) * QST + np * 16 + cV));
                #pragma unroll
                for (int hf = 0; hf < 2; hf++) {
                    mma16816(oacc[2 * np + hf], pah4, &vb_h[2 * hf]);
                    mma16816(oacc[2 * np + hf], pah4, &vb_l[2 * hf]);
                    mma16816(oacc[2 * np + hf], pal4, &vb_h[2 * hf]);
                }
            }
        }
        __syncthreads();
    }
    l0 += __shfl_xor_sync(0xffffffffu, l0, 1);
    l0 += __shfl_xor_sync(0xffffffffu, l0, 2);
    l1 += __shfl_xor_sync(0xffffffffu, l1, 1);
    l1 += __shfl_xor_sync(0xffffffffu, l1, 2);
    float i0 = 1.0f / l0, i1 = 1.0f / l1;
    size_t obase = (size_t)(b * 1024 + q0) * 256 + h * 32;
    #pragma unroll
    for (int n = 0; n < 4; n++) {
        int row = wid * 16 + grp;
        int col = n * 8 + q4 * 2;
        uint32_t lo0, lo1;
        uint32_t h0 = pk2(oacc[n][0] * i0, oacc[n][1] * i0, lo0);
        uint32_t h1 = pk2(oacc[n][2] * i1, oacc[n][3] * i1, lo1);
        *(uint32_t*)&Oh[obase + (size_t)row * 256 + col]       = h0;
        *(uint32_t*)&Ol[obase + (size_t)row * 256 + col]       = lo0;
        *(uint32_t*)&Oh[obase + (size_t)(row + 8) * 256 + col] = h1;
        *(uint32_t*)&Ol[obase + (size_t)(row + 8) * 256 + col] = lo1;
    }
}

// ------------------------- GAT pieces -------------------------
__global__ void att_prep(const float* __restrict__ hbuf,
                         const float* __restrict__ atts, const float* __restrict__ attd)
{
    int n = blockIdx.x * 8 + (threadIdx.x >> 5);
    int lane = threadIdx.x & 31;
    const float4* hp = (const float4*)(hbuf + (size_t)n * Dd + lane * 8);
    float4 a = hp[0], b = hp[1];
    const float4* pa = (const float4*)(atts + lane * 8);
    const float4* pb = (const float4*)(attd + lane * 8);
    float4 wa0 = pa[0], wa1 = pa[1];
    float4 wb0 = pb[0], wb1 = pb[1];
    float s1 = a.x * wa0.x + a.y * wa0.y + a.z * wa0.z + a.w * wa0.w
             + b.x * wa1.x + b.y * wa1.y + b.z * wa1.z + b.w * wa1.w;
    float s2 = a.x * wb0.x + a.y * wb0.y + a.z * wb0.z + a.w * wb0.w
             + b.x * wb1.x + b.y * wb1.y + b.z * wb1.z + b.w * wb1.w;
    s1 += __shfl_xor_sync(0xffffffffu, s1, 1);
    s1 += __shfl_xor_sync(0xffffffffu, s1, 2);
    s2 += __shfl_xor_sync(0xffffffffu, s2, 1);
    s2 += __shfl_xor_sync(0xffffffffu, s2, 2);
    if ((lane & 3) == 0) {
        g_as[n * 8 + (lane >> 2)] = s1;
        g_ad[n * 8 + (lane >> 2)] = s2;
    }
}

#define DEGCAP 96
__global__ void __launch_bounds__(256)
gat_aggr(const float* __restrict__ hbuf, const float* __restrict__ bias,
         float* __restrict__ outF, bf16* __restrict__ outH, bf16* __restrict__ outL)
{
    __shared__ float salpha[8][DEGCAP][8];
    int wid = threadIdx.x >> 5, lane = threadIdx.x & 31;
    int d = blockIdx.x * 8 + wid;
    int base = g_rowptr[d];
    int deg  = g_rowptr[d + 1] - base;

    int hd = lane & 7;
    float adv = g_ad[d * 8 + hd];
    float m = -1e30f;
    for (int i = lane >> 3; i < deg; i += 4) {
        int s = g_col[base + i];
        float v = g_as[s * 8 + hd] + adv;
        v = v > 0.0f ? v : 0.2f * v;
        m = fmaxf(m, v);
    }
    m = fmaxf(m, __shfl_xor_sync(0xffffffffu, m, 8));
    m = fmaxf(m, __shfl_xor_sync(0xffffffffu, m, 16));
    float sum = 0.0f;
    for (int i = lane >> 3; i < deg; i += 4) {
        int s = g_col[base + i];
        float v = g_as[s * 8 + hd] + adv;
        v = v > 0.0f ? v : 0.2f * v;
        float p = __expf(v - m);
        if (i < DEGCAP) salpha[wid][i][hd] = p;
        sum += p;
    }
    sum += __shfl_xor_sync(0xffffffffu, sum, 8);
    sum += __shfl_xor_sync(0xffffffffu, sum, 16);
    __syncwarp();

    int hd2 = lane >> 2;
    float m2  = __shfl_sync(0xffffffffu, m, hd2);
    float is2 = 1.0f / __shfl_sync(0xffffffffu, sum, hd2);
    float adv2 = g_ad[d * 8 + hd2];
    float acc[8] = {};

    auto getp = [&](int i, int s) -> float {
        if (i < DEGCAP) return salpha[wid][i][hd2];
        float v = g_as[s * 8 + hd2] + adv2;
        v = v > 0.0f ? v : 0.2f * v;
        return __expf(v - m2);
    };
    int i = 0;
    for (; i + 2 <= deg; i += 2) {
        int s0 = g_col[base + i], s1 = g_col[base + i + 1];
        float al0 = getp(i, s0) * is2;
        float al1 = getp(i + 1, s1) * is2;
        const float4* h0 = (const float4*)(hbuf + (size_t)s0 * Dd + lane * 8);
        const float4* h1 = (const float4*)(hbuf + (size_t)s1 * Dd + lane * 8);
        float4 a0 = h0[0], b0 = h0[1];
        float4 a1 = h1[0], b1 = h1[1];
        acc[0] += al0 * a0.x + al1 * a1.x;  acc[1] += al0 * a0.y + al1 * a1.y;
        acc[2] += al0 * a0.z + al1 * a1.z;  acc[3] += al0 * a0.w + al1 * a1.w;
        acc[4] += al0 * b0.x + al1 * b1.x;  acc[5] += al0 * b0.y + al1 * b1.y;
        acc[6] += al0 * b0.z + al1 * b1.z;  acc[7] += al0 * b0.w + al1 * b1.w;
    }
    if (i < deg) {
        int s0 = g_col[base + i];
        float al0 = getp(i, s0) * is2;
        const float4* h0 = (const float4*)(hbuf + (size_t)s0 * Dd + lane * 8);
        float4 a0 = h0[0], b0 = h0[1];
        acc[0] += al0 * a0.x;  acc[1] += al0 * a0.y;
        acc[2] += al0 * a0.z;  acc[3] += al0 * a0.w;
        acc[4] += al0 * b0.x;  acc[5] += al0 * b0.y;
        acc[6] += al0 * b0.z;  acc[7] += al0 * b0.w;
    }
    size_t rb = (size_t)d * Dd + lane * 8;
    #pragma unroll
    for (int j = 0; j < 8; j += 2) {
        float v0 = fmaxf(acc[j]     + bias[lane * 8 + j],     0.0f);
        float v1 = fmaxf(acc[j + 1] + bias[lane * 8 + j + 1], 0.0f);
        *(float2*)&outF[rb + j] = make_float2(v0, v1);
        uint32_t lo;
        uint32_t hi = pk2(v0, v1, lo);
        *(uint32_t*)&outH[rb + j] = hi;
        *(uint32_t*)&outL[rb + j] = lo;
    }
}

// ------------------------- residual + layernorm -------------------------
__global__ void ln_res(const float* __restrict__ xin, const float* __restrict__ add,
                       float* __restrict__ xout, const float* __restrict__ w,
                       const float* __restrict__ b,
                       bf16* __restrict__ oh, bf16* __restrict__ ol)
{
    int row = blockIdx.x * 8 + (threadIdx.x >> 5);
    int lane = threadIdx.x & 31;
    const float* xr = xin + (size_t)row * Dd;
    const float* ar = add + (size_t)row * Dd;
    float v[8];
    float s = 0.0f;
    #pragma unroll
    for (int j = 0; j < 8; j++) {
        int d = lane + j * 32;
        v[j] = xr[d] + ar[d];
        s += v[j];
    }
    s = warpSum(s);
    float mean = s * (1.0f / 256.0f);
    float var = 0.0f;
    #pragma unroll
    for (int j = 0; j < 8; j++) {
        float dv = v[j] - mean;
        var += dv * dv;
    }
    var = warpSum(var) * (1.0f / 256.0f);
    float inv = rsqrtf(var + 1e-5f);
    float* orow = xout + (size_t)row * Dd;
    #pragma unroll
    for (int j = 0; j < 8; j++) {
        int d = lane + j * 32;
        float o = (v[j] - mean) * inv * w[d] + b[d];
        orow[d] = o;
        bf16 h = __float2bfloat16(o);
        oh[(size_t)row * Dd + d] = h;
        ol[(size_t)row * Dd + d] = __float2bfloat16(o - __bfloat162float(h));
    }
}

// ------------------------- prediction head -------------------------
__global__ void pred_kernel(const float* __restrict__ xin, const float* __restrict__ pw,
                            const float* __restrict__ pb, float* __restrict__ out)
{
    int gw = (blockIdx.x * 256 + threadIdx.x) >> 5;
    int lane = threadIdx.x & 31;
    if (gw >= Nn) return;
    const float* xr = xin + (size_t)gw * Dd;
    float a0 = 0.0f, a1 = 0.0f, a2 = 0.0f;
    #pragma unroll
    for (int j = 0; j < 8; j++) {
        int d = lane + j * 32;
        float xv = xr[d];
        a0 += xv * pw[d];
        a1 += xv * pw[Dd + d];
        a2 += xv * pw[2 * Dd + d];
    }
    a0 = warpSum(a0);
    a1 = warpSum(a1);
    a2 = warpSum(a2);
    if (lane == 0) {
        out[gw * 3 + 0] = a0 + pb[0];
        out[gw * 3 + 1] = a1 + pb[1];
        out[gw * 3 + 2] = a2 + pb[2];
    }
}

// ------------------------- host orchestration -------------------------
#define SMEM_G (4 * 128 * 40 * 2 * 2)
#define SMEM_F ((2 * 128 * 40 + 2 * 4 * 128 * 40) * 2)    // 102400 B

extern "C" void kernel_launch(void* const* d_in, const int* in_sizes, int n_in,
                              void* d_out, int out_size)
{
    const float* x      = (const float*)d_in[0];
    const int*   ei     = (const int*)d_in[1];
    const float* W0     = (const float*)d_in[3];
    const float* W12    = (const float*)d_in[4];
    const float* att_s  = (const float*)d_in[5];
    const float* att_d  = (const float*)d_in[6];
    const float* gbias  = (const float*)d_in[7];
    const float* qkv_w  = (const float*)d_in[8];
    const float* qkv_b  = (const float*)d_in[9];
    const float* out_w  = (const float*)d_in[10];
    const float* out_b  = (const float*)d_in[11];
    const float* ln1w   = (const float*)d_in[12];
    const float* ln1b   = (const float*)d_in[13];
    const float* ln2w   = (const float*)d_in[14];
    const float* ln2b   = (const float*)d_in[15];
    const float* ff1w   = (const float*)d_in[16];
    const float* ff1b   = (const float*)d_in[17];
    const float* ff2w   = (const float*)d_in[18];
    const float* ff2b   = (const float*)d_in[19];
    const float* predw  = (const float*)d_in[20];
    const float* predb  = (const float*)d_in[21];
    float* out = (float*)d_out;

    int E = in_sizes[1] / 2;
    int Etot = E + Nn;

    cudaFuncSetAttribute((const void*)hgemm<0>, cudaFuncAttributeMaxDynamicSharedMemorySize, SMEM_G);
    cudaFuncSetAttribute((const void*)hgemm<1>, cudaFuncAttributeMaxDynamicSharedMemorySize, SMEM_G);
    cudaFuncSetAttribute((const void*)flash_attn, cudaFuncAttributeMaxDynamicSharedMemorySize, SMEM_F);

    float *ph, *px;
    bf16 *pah, *pal, *pxh, *pxl, *pwh, *pwl, *pqh, *pql;
    cudaGetSymbolAddress((void**)&ph,    g_h);
    cudaGetSymbolAddress((void**)&px,    g_x);
    cudaGetSymbolAddress((void**)&pah,   g_ah);
    cudaGetSymbolAddress((void**)&pal,   g_al);
    cudaGetSymbolAddress((void**)&pxh,   g_xh);
    cudaGetSymbolAddress((void**)&pxl,   g_xl);
    cudaGetSymbolAddress((void**)&pwh,   g_wh);
    cudaGetSymbolAddress((void**)&pwl,   g_wl);
    cudaGetSymbolAddress((void**)&pqh,   g_qh);
    cudaGetSymbolAddress((void**)&pql,   g_ql);

    // ---------------- one-shot weight conversion (all 11 matrices) ----------------
    WSegs ws;
    ws.src[0]  = W0;                         ws.off[0]  = WO_W0;    ws.n4[0]  = 16384 / 4;
    ws.src[1]  = W12;                        ws.off[1]  = WO_W1;    ws.n4[1]  = 65536 / 4;
    ws.src[2]  = W12 + 65536;                ws.off[2]  = WO_W2;    ws.n4[2]  = 65536 / 4;
    ws.src[3]  = qkv_w;                      ws.off[3]  = WO_QKV0;  ws.n4[3]  = 196608 / 4;
    ws.src[4]  = qkv_w + 196608;             ws.off[4]  = WO_QKV1;  ws.n4[4]  = 196608 / 4;
    ws.src[5]  = out_w;                      ws.off[5]  = WO_OUT0;  ws.n4[5]  = 65536 / 4;
    ws.src[6]  = out_w + 65536;              ws.off[6]  = WO_OUT1;  ws.n4[6]  = 65536 / 4;
    ws.src[7]  = ff1w;                       ws.off[7]  = WO_FF1_0; ws.n4[7]  = 524288 / 4;
    ws.src[8]  = ff1w + 524288;              ws.off[8]  = WO_FF1_1; ws.n4[8]  = 524288 / 4;
    ws.src[9]  = ff2w;                       ws.off[9]  = WO_FF2_0; ws.n4[9]  = 524288 / 4;
    ws.src[10] = ff2w + 524288;              ws.off[10] = WO_FF2_1; ws.n4[10] = 524288 / 4;
    cvt_weights<<<dim3(512, 11), 256>>>(ws);

    // ---------------- CSR build (once) ----------------
    csr_init<<<Nn / 256, 256>>>();
    csr_count<<<(E + 255) / 256, 256>>>(ei, E);
    csr_scan<<<1, 1024>>>();
    csr_fill<<<(Etot + 255) / 256, 256>>>(ei, E, Etot);

    // ---------------- GAT layers ----------------
    cvt_hilo<<<(Nn * 64 / 4 + 255) / 256, 256>>>(x, pxh, pxl, Nn * 64 / 4);
    int curK = 64;
    const int woff[3] = {WO_W0, WO_W1, WO_W2};
    for (int l = 0; l < 3; l++) {
        hgemm<0><<<dim3(Dd / 128, Nn / 128), 512, SMEM_G>>>(
            pxh, pxl, curK, pwh + woff[l], pwl + woff[l], curK,
            nullptr, ph, nullptr, nullptr, Dd, curK, 0);
        att_prep<<<Nn / 8, 256>>>(ph, att_s + l * Dd, att_d + l * Dd);
        gat_aggr<<<Nn / 8, 256>>>(ph, gbias + l * Dd, px, pxh, pxl);
        curK = Dd;
    }

    // ---------------- transformer layers ----------------
    const float scale = 0.17677669529663687f;  // 1/sqrt(32)
    const int qoff[2] = {WO_QKV0, WO_QKV1};
    const int ooff[2] = {WO_OUT0, WO_OUT1};
    const int f1off[2] = {WO_FF1_0, WO_FF1_1};
    const int f2off[2] = {WO_FF2_0, WO_FF2_1};
    for (int i = 0; i < 2; i++) {
        hgemm<1><<<dim3(768 / 128, Nn / 128), 512, SMEM_G>>>(
            pxh, pxl, Dd, pwh + qoff[i], pwl + qoff[i], Dd,
            qkv_b + i * 768, nullptr, pqh, pql, 768, Dd, 0);
        flash_attn<<<dim3(8, 64), 256, SMEM_F>>>(pqh, pql, pah, pal, scale);
        hgemm<0><<<dim3(Dd / 128, Nn / 128), 512, SMEM_G>>>(
            pah, pal, Dd, pwh + ooff[i], pwl + ooff[i], Dd,
            out_b + i * Dd, ph, nullptr, nullptr, Dd, Dd, 0);
        ln_res<<<Nn / 8, 256>>>(px, ph, px, ln1w + i * Dd, ln1b + i * Dd, pxh, pxl);
        hgemm<1><<<dim3(DFF / 128, Nn / 128), 512, SMEM_G>>>(
            pxh, pxl, Dd, pwh + f1off[i], pwl + f1off[i], Dd,
            ff1b + i * DFF, nullptr, pah, pal, DFF, Dd, 1);
        hgemm<0><<<dim3(Dd / 128, Nn / 128), 512, SMEM_G>>>(
            pah, pal, DFF, pwh + f2off[i], pwl + f2off[i], DFF,
            ff2b + i * Dd, ph, nullptr, nullptr, Dd, DFF, 0);
        ln_res<<<Nn / 8, 256>>>(px, ph, px, ln2w + i * Dd, ln2b + i * Dd, pxh, pxl);
    }

    // ---------------- prediction head ----------------
    pred_kernel<<<(Nn * 32 + 255) / 256, 256>>>(px, predw, predb, out);
}